// round 2
// baseline (speedup 1.0000x reference)
#include <cuda_runtime.h>
#include <math.h>

#define DIMM  768
#define HEADS 12
#define DHEAD 64
#define INNER 768
#define MLPD  3072
#define BB    8
#define SEQ   1024
#define ROWS  (BB*SEQ)   /* 8192 */
#define DEPTH 6
#define SCALE 0.125f     /* 64^-0.5 */

// ---------------- scratch (device globals: no allocations allowed) ----------
__device__ __align__(16) float g_ln[ROWS*DIMM];
__device__ __align__(16) float g_qkv[(size_t)ROWS*3*INNER];
__device__ __align__(16) float g_scores[(size_t)BB*HEADS*SEQ*SEQ];
__device__ __align__(16) float g_obuf[ROWS*INNER];
__device__ __align__(16) float g_mlp[(size_t)ROWS*MLPD];
__device__ __align__(16) float g_wqkv[3*INNER*DIMM];
__device__ __align__(16) float g_wo[DIMM*INNER];
__device__ __align__(16) float g_w1[MLPD*DIMM];
__device__ __align__(16) float g_w2[DIMM*MLPD];
__device__ float g_scal[4];

// ---------------- ternary quantization -------------------------------------
__global__ void abs_sum_kernel(const float* __restrict__ w, float* out, int n) {
    float s = 0.f;
    for (int i = blockIdx.x*blockDim.x + threadIdx.x; i < n; i += gridDim.x*blockDim.x)
        s += fabsf(w[i]);
    #pragma unroll
    for (int o = 16; o; o >>= 1) s += __shfl_down_sync(0xffffffffu, s, o);
    __shared__ float sh[8];
    if ((threadIdx.x & 31) == 0) sh[threadIdx.x >> 5] = s;
    __syncthreads();
    if (threadIdx.x < 8) {
        float v = sh[threadIdx.x];
        #pragma unroll
        for (int o = 4; o; o >>= 1) v += __shfl_down_sync(0xffu, v, o);
        if (threadIdx.x == 0) atomicAdd(out, v);
    }
}

__global__ void quant_kernel(const float* __restrict__ w, float* __restrict__ q,
                             const float* __restrict__ sums, int idx, int n) {
    float s = sums[idx] / (float)n + 1e-8f;
    float inv = 1.0f / s;
    for (int i = blockIdx.x*blockDim.x + threadIdx.x; i < n; i += gridDim.x*blockDim.x) {
        float t = rintf(w[i] * inv);           // round half-to-even, matches jnp.round
        t = fminf(1.0f, fmaxf(-1.0f, t));
        q[i] = t * s;
    }
}

// ---------------- layernorm -------------------------------------------------
__device__ __forceinline__ float blockReduceSum(float v) {
    __shared__ float sh[33];
    __syncthreads();                           // protect sh across repeated calls
    int lane = threadIdx.x & 31, wid = threadIdx.x >> 5;
    #pragma unroll
    for (int o = 16; o; o >>= 1) v += __shfl_down_sync(0xffffffffu, v, o);
    if (!lane) sh[wid] = v;
    __syncthreads();
    if (threadIdx.x < 8) {
        float t = sh[threadIdx.x];
        #pragma unroll
        for (int o = 4; o; o >>= 1) t += __shfl_down_sync(0xffu, t, o);
        if (!threadIdx.x) sh[32] = t;
    }
    __syncthreads();
    return sh[32];
}

__global__ void __launch_bounds__(256) ln_kernel(const float* __restrict__ x,
                                                 float* __restrict__ y,
                                                 const float* __restrict__ g,
                                                 const float* __restrict__ b,
                                                 int width) {
    extern __shared__ float row[];
    const float* xr = x + (size_t)blockIdx.x * width;
    float s = 0.f;
    for (int i = threadIdx.x; i < width; i += blockDim.x) { float v = xr[i]; row[i] = v; s += v; }
    float m = blockReduceSum(s) / (float)width;
    float v2 = 0.f;
    for (int i = threadIdx.x; i < width; i += blockDim.x) { float d = row[i] - m; v2 += d*d; }
    float var = blockReduceSum(v2) / (float)width;
    float r = rsqrtf(var + 1e-5f);
    float* yr = y + (size_t)blockIdx.x * width;
    for (int i = threadIdx.x; i < width; i += blockDim.x)
        yr[i] = (row[i] - m) * r * g[i] + b[i];
}

// ---------------- SGEMM: C[M,N] = A[M,K] * W[N,K]^T (+bias) (+resid) --------
#define BM 128
#define BN 128
#define BK 8
__global__ void __launch_bounds__(256) gemm_nt(const float* __restrict__ A,
                                               const float* __restrict__ W,
                                               const float* __restrict__ bias,
                                               const float* __restrict__ resid,
                                               float* __restrict__ C,
                                               int M, int N, int K) {
    __shared__ __align__(16) float As[BK][BM];
    __shared__ __align__(16) float Ws[BK][BN];
    int bm = blockIdx.y * BM, bn = blockIdx.x * BN;
    int t = threadIdx.x;
    int tx = t & 15, ty = t >> 4;
    int lm = t >> 1;
    int lk = (t & 1) << 2;
    const float* Ap = A + (size_t)(bm + lm) * K + lk;
    const float* Wp = W + (size_t)(bn + lm) * K + lk;
    float acc[8][8] = {};
    for (int k0 = 0; k0 < K; k0 += BK) {
        float4 a4 = *(const float4*)(Ap + k0);
        float4 w4 = *(const float4*)(Wp + k0);
        As[lk+0][lm] = a4.x; As[lk+1][lm] = a4.y; As[lk+2][lm] = a4.z; As[lk+3][lm] = a4.w;
        Ws[lk+0][lm] = w4.x; Ws[lk+1][lm] = w4.y; Ws[lk+2][lm] = w4.z; Ws[lk+3][lm] = w4.w;
        __syncthreads();
        #pragma unroll
        for (int k = 0; k < BK; k++) {
            float4 ra0 = *(const float4*)&As[k][ty*8];
            float4 ra1 = *(const float4*)&As[k][ty*8+4];
            float4 rw0 = *(const float4*)&Ws[k][tx*8];
            float4 rw1 = *(const float4*)&Ws[k][tx*8+4];
            float ra[8] = {ra0.x, ra0.y, ra0.z, ra0.w, ra1.x, ra1.y, ra1.z, ra1.w};
            float rw[8] = {rw0.x, rw0.y, rw0.z, rw0.w, rw1.x, rw1.y, rw1.z, rw1.w};
            #pragma unroll
            for (int i = 0; i < 8; i++)
                #pragma unroll
                for (int j = 0; j < 8; j++)
                    acc[i][j] += ra[i] * rw[j];
        }
        __syncthreads();
    }
    #pragma unroll
    for (int i = 0; i < 8; i++) {
        int r = bm + ty*8 + i;
        #pragma unroll
        for (int j = 0; j < 8; j++) {
            int c = bn + tx*8 + j;
            float v = acc[i][j];
            if (bias)  v += bias[c];
            if (resid) v += resid[(size_t)r * N + c];
            C[(size_t)r * N + c] = v;
        }
    }
}

// ---------------- attention: S = Q K^T * scale ------------------------------
__global__ void __launch_bounds__(256) attn_scores(const float* __restrict__ qkv,
                                                   float* __restrict__ S) {
    int bh = blockIdx.z;
    int b = bh / HEADS, hh = bh % HEADS;
    const float* base = qkv + (size_t)b * SEQ * (3*INNER);
    const float* Q  = base + hh * DHEAD;
    const float* Kp = base + INNER + hh * DHEAD;
    int m0 = blockIdx.y * 64, n0 = blockIdx.x * 64;
    __shared__ float Qs[64][65];
    __shared__ float Ks[64][65];
    int t = threadIdx.x;
    #pragma unroll
    for (int it = 0; it < 4; it++) {
        int idx = it*256 + t;          // 0..1023 float4s
        int m = idx >> 4;
        int d = (idx & 15) << 2;
        float4 q4 = *(const float4*)(Q  + (size_t)(m0+m)*(3*INNER) + d);
        float4 k4 = *(const float4*)(Kp + (size_t)(n0+m)*(3*INNER) + d);
        Qs[d+0][m] = q4.x; Qs[d+1][m] = q4.y; Qs[d+2][m] = q4.z; Qs[d+3][m] = q4.w;
        Ks[d+0][m] = k4.x; Ks[d+1][m] = k4.y; Ks[d+2][m] = k4.z; Ks[d+3][m] = k4.w;
    }
    __syncthreads();
    int tx = t & 15, ty = t >> 4;
    float acc[4][4] = {};
    #pragma unroll
    for (int k = 0; k < 64; k++) {
        float ra[4], rk[4];
        #pragma unroll
        for (int i = 0; i < 4; i++) ra[i] = Qs[k][ty*4+i];
        #pragma unroll
        for (int j = 0; j < 4; j++) rk[j] = Ks[k][tx*4+j];
        #pragma unroll
        for (int i = 0; i < 4; i++)
            #pragma unroll
            for (int j = 0; j < 4; j++)
                acc[i][j] += ra[i] * rk[j];
    }
    float* Sout = S + ((size_t)bh << 20);
    #pragma unroll
    for (int i = 0; i < 4; i++)
        #pragma unroll
        for (int j = 0; j < 4; j++)
            Sout[(size_t)(m0+ty*4+i)*SEQ + n0+tx*4+j] = acc[i][j] * SCALE;
}

// ---------------- softmax over rows of S ------------------------------------
__global__ void __launch_bounds__(256) softmax_kernel(float* __restrict__ S) {
    __shared__ float row[SEQ];
    __shared__ float red[8];
    float* r = S + (size_t)blockIdx.x * SEQ;
    int t = threadIdx.x;
    float mx = -1e30f;
    for (int i = t; i < SEQ; i += 256) { float v = r[i]; row[i] = v; mx = fmaxf(mx, v); }
    #pragma unroll
    for (int o = 16; o; o >>= 1) mx = fmaxf(mx, __shfl_xor_sync(0xffffffffu, mx, o));
    if ((t & 31) == 0) red[t >> 5] = mx;
    __syncthreads();
    if (t < 8) {
        float v = red[t];
        #pragma unroll
        for (int o = 4; o; o >>= 1) v = fmaxf(v, __shfl_xor_sync(0xffu, v, o));
        if (!t) red[0] = v;
    }
    __syncthreads();
    mx = red[0];
    float s = 0.f;
    for (int i = t; i < SEQ; i += 256) { float e = __expf(row[i] - mx); row[i] = e; s += e; }
    __syncthreads();                    // all reads of red[0] done
    #pragma unroll
    for (int o = 16; o; o >>= 1) s += __shfl_xor_sync(0xffffffffu, s, o);
    if ((t & 31) == 0) red[t >> 5] = s;
    __syncthreads();
    if (t < 8) {
        float v = red[t];
        #pragma unroll
        for (int o = 4; o; o >>= 1) v += __shfl_xor_sync(0xffu, v, o);
        if (!t) red[0] = v;
    }
    __syncthreads();
    float inv = 1.0f / red[0];
    for (int i = t; i < SEQ; i += 256) r[i] = row[i] * inv;
}

// ---------------- attention: O = P V ----------------------------------------
__global__ void __launch_bounds__(256) attn_pv(const float* __restrict__ S,
                                               const float* __restrict__ qkv,
                                               float* __restrict__ O) {
    int bh = blockIdx.z;
    int b = bh / HEADS, hh = bh % HEADS;
    int n0 = blockIdx.y * 64;
    const float* Srow = S + ((size_t)bh << 20);
    const float* Vb = qkv + (size_t)b * SEQ * (3*INNER) + 2*INNER + hh * DHEAD;
    __shared__ float Ps[32][65];
    __shared__ __align__(16) float Vs[32][64];
    int t = threadIdx.x;
    int tx = t & 15, ty = t >> 4;
    float acc[4][4] = {};
    for (int k0 = 0; k0 < SEQ; k0 += 32) {
        #pragma unroll
        for (int it = 0; it < 2; it++) {
            int idx = it*256 + t;       // 0..511
            int n  = idx >> 3;
            int k4 = (idx & 7) << 2;
            float4 p4 = *(const float4*)(Srow + (size_t)(n0+n)*SEQ + k0 + k4);
            Ps[k4+0][n] = p4.x; Ps[k4+1][n] = p4.y; Ps[k4+2][n] = p4.z; Ps[k4+3][n] = p4.w;
            int kk = idx >> 4;          // 0..31
            int dd = (idx & 15) << 2;
            *(float4*)&Vs[kk][dd] = *(const float4*)(Vb + (size_t)(k0+kk)*(3*INNER) + dd);
        }
        __syncthreads();
        #pragma unroll
        for (int k = 0; k < 32; k++) {
            float rp[4], rv[4];
            #pragma unroll
            for (int i = 0; i < 4; i++) rp[i] = Ps[k][ty*4+i];
            #pragma unroll
            for (int j = 0; j < 4; j++) rv[j] = Vs[k][tx*4+j];
            #pragma unroll
            for (int i = 0; i < 4; i++)
                #pragma unroll
                for (int j = 0; j < 4; j++)
                    acc[i][j] += rp[i] * rv[j];
        }
        __syncthreads();
    }
    #pragma unroll
    for (int i = 0; i < 4; i++)
        #pragma unroll
        for (int j = 0; j < 4; j++)
            O[((size_t)b*SEQ + n0+ty*4+i)*INNER + hh*DHEAD + tx*4+j] = acc[i][j];
}

// ---------------- GELU (exact) ----------------------------------------------
__global__ void gelu_kernel(float* __restrict__ y, size_t n) {
    for (size_t i = blockIdx.x*(size_t)blockDim.x + threadIdx.x; i < n;
         i += (size_t)gridDim.x*blockDim.x) {
        float v = y[i];
        y[i] = v * 0.5f * (1.0f + erff(v * 0.70710678118654752f));
    }
}

// ---------------- host driver -----------------------------------------------
extern "C" void kernel_launch(void* const* d_in, const int* in_sizes, int n_in,
                              void* d_out, int out_size) {
    const float* x    = (const float*)d_in[0];
    const float* ln1g = (const float*)d_in[1];
    const float* ln1b = (const float*)d_in[2];
    const float* Wqkv = (const float*)d_in[3];
    const float* ln2g = (const float*)d_in[4];
    const float* ln2b = (const float*)d_in[5];
    const float* Wo   = (const float*)d_in[6];
    const float* bo   = (const float*)d_in[7];
    const float* f1g  = (const float*)d_in[8];
    const float* f1b  = (const float*)d_in[9];
    const float* W1   = (const float*)d_in[10];
    const float* b1   = (const float*)d_in[11];
    const float* f2g  = (const float*)d_in[12];
    const float* f2b  = (const float*)d_in[13];
    const float* W2   = (const float*)d_in[14];
    const float* b2   = (const float*)d_in[15];
    float* h = (float*)d_out;

    float *lnb, *qkv, *sc, *ob, *mlp, *wqkvq, *woq, *w1q, *w2q, *scal;
    cudaGetSymbolAddress((void**)&lnb,   g_ln);
    cudaGetSymbolAddress((void**)&qkv,   g_qkv);
    cudaGetSymbolAddress((void**)&sc,    g_scores);
    cudaGetSymbolAddress((void**)&ob,    g_obuf);
    cudaGetSymbolAddress((void**)&mlp,   g_mlp);
    cudaGetSymbolAddress((void**)&wqkvq, g_wqkv);
    cudaGetSymbolAddress((void**)&woq,   g_wo);
    cudaGetSymbolAddress((void**)&w1q,   g_w1);
    cudaGetSymbolAddress((void**)&w2q,   g_w2);
    cudaGetSymbolAddress((void**)&scal,  g_scal);

    cudaMemcpyAsync(h, x, sizeof(float)*(size_t)ROWS*DIMM, cudaMemcpyDeviceToDevice);

    for (int l = 0; l < DEPTH; l++) {
        const float* wqkv_l = Wqkv + (size_t)l * 3*INNER*DIMM;
        const float* wo_l   = Wo   + (size_t)l * DIMM*INNER;
        const float* w1_l   = W1   + (size_t)l * MLPD*DIMM;
        const float* w2_l   = W2   + (size_t)l * DIMM*MLPD;
        const float *uq = wqkv_l, *uo = wo_l, *u1 = w1_l, *u2 = w2_l;

        if (l < DEPTH - 1) {   // ternary layers
            cudaMemsetAsync(scal, 0, 4*sizeof(float));
            abs_sum_kernel<<<512,256>>>(wqkv_l, scal+0, 3*INNER*DIMM);
            abs_sum_kernel<<<512,256>>>(wo_l,   scal+1, DIMM*INNER);
            abs_sum_kernel<<<512,256>>>(w1_l,   scal+2, MLPD*DIMM);
            abs_sum_kernel<<<512,256>>>(w2_l,   scal+3, DIMM*MLPD);
            quant_kernel<<<512,256>>>(wqkv_l, wqkvq, scal, 0, 3*INNER*DIMM);
            quant_kernel<<<512,256>>>(wo_l,   woq,   scal, 1, DIMM*INNER);
            quant_kernel<<<512,256>>>(w1_l,   w1q,   scal, 2, MLPD*DIMM);
            quant_kernel<<<512,256>>>(w2_l,   w2q,   scal, 3, DIMM*MLPD);
            uq = wqkvq; uo = woq; u1 = w1q; u2 = w2q;
        }

        // attention block
        ln_kernel<<<ROWS,256,DIMM*4>>>(h, lnb, ln1g + l*DIMM, ln1b + l*DIMM, DIMM);
        gemm_nt<<<dim3(3*INNER/BN, ROWS/BM),256>>>(lnb, uq, nullptr, nullptr, qkv,
                                                   ROWS, 3*INNER, DIMM);
        attn_scores<<<dim3(16,16,BB*HEADS),256>>>(qkv, sc);
        softmax_kernel<<<BB*HEADS*SEQ,256>>>(sc);
        attn_pv<<<dim3(1,16,BB*HEADS),256>>>(sc, qkv, ob);
        ln_kernel<<<ROWS,256,INNER*4>>>(ob, ob, ln2g + l*INNER, ln2b + l*INNER, INNER);
        gemm_nt<<<dim3(DIMM/BN, ROWS/BM),256>>>(ob, uo, bo + l*DIMM, h, h,
                                                ROWS, DIMM, INNER);

        // MLP block
        ln_kernel<<<ROWS,256,DIMM*4>>>(h, lnb, f1g + l*DIMM, f1b + l*DIMM, DIMM);
        gemm_nt<<<dim3(MLPD/BN, ROWS/BM),256>>>(lnb, u1, b1 + l*MLPD, nullptr, mlp,
                                                ROWS, MLPD, DIMM);
        gelu_kernel<<<4096,256>>>(mlp, (size_t)ROWS*MLPD);
        ln_kernel<<<ROWS,256,MLPD*4>>>(mlp, mlp, f2g + l*MLPD, f2b + l*MLPD, MLPD);
        gemm_nt<<<dim3(DIMM/BN, ROWS/BM),256>>>(mlp, u2, b2 + l*DIMM, h, h,
                                                ROWS, DIMM, MLPD);
    }
}

// round 3
// speedup vs baseline: 1.2848x; 1.2848x over previous
#include <cuda_runtime.h>
#include <math.h>
#include <stdint.h>

#define DIMM  768
#define HEADS 12
#define DHEAD 64
#define INNER 768
#define MLPD  3072
#define BB    8
#define SEQ   1024
#define ROWS  (BB*SEQ)   /* 8192 */
#define DEPTH 6
#define SCALE 0.125f     /* 64^-0.5 */

// ---------------- scratch (device globals: no allocations allowed) ----------
__device__ __align__(16) float g_ln[ROWS*DIMM];
__device__ __align__(16) float g_qkv[(size_t)ROWS*3*INNER];
__device__ __align__(16) float g_scores[(size_t)BB*HEADS*SEQ*SEQ];
__device__ __align__(16) float g_obuf[ROWS*INNER];
__device__ __align__(16) float g_mlp[(size_t)ROWS*MLPD];
__device__ __align__(16) float g_wqkv[3*INNER*DIMM];
__device__ __align__(16) float g_wo[DIMM*INNER];
__device__ __align__(16) float g_w1[MLPD*DIMM];
__device__ __align__(16) float g_w2[DIMM*MLPD];
__device__ float g_scal[4];

// ---------------- ternary quantization -------------------------------------
__global__ void abs_sum_kernel(const float* __restrict__ w, float* out, int n) {
    float s = 0.f;
    for (int i = blockIdx.x*blockDim.x + threadIdx.x; i < n; i += gridDim.x*blockDim.x)
        s += fabsf(w[i]);
    #pragma unroll
    for (int o = 16; o; o >>= 1) s += __shfl_down_sync(0xffffffffu, s, o);
    __shared__ float sh[8];
    if ((threadIdx.x & 31) == 0) sh[threadIdx.x >> 5] = s;
    __syncthreads();
    if (threadIdx.x < 8) {
        float v = sh[threadIdx.x];
        #pragma unroll
        for (int o = 4; o; o >>= 1) v += __shfl_down_sync(0xffu, v, o);
        if (threadIdx.x == 0) atomicAdd(out, v);
    }
}

// emits TERNARY values {-1,0,+1} (scale applied in GEMM epilogue)
__global__ void quant_kernel(const float* __restrict__ w, float* __restrict__ q,
                             const float* __restrict__ sums, int idx, int n) {
    float s = sums[idx] / (float)n + 1e-8f;
    float inv = 1.0f / s;
    for (int i = blockIdx.x*blockDim.x + threadIdx.x; i < n; i += gridDim.x*blockDim.x) {
        float t = rintf(w[i] * inv);           // round half-to-even, matches jnp.round
        t = fminf(1.0f, fmaxf(-1.0f, t));
        q[i] = t;
    }
}

// ---------------- layernorm -------------------------------------------------
__device__ __forceinline__ float blockReduceSum(float v) {
    __shared__ float sh[33];
    __syncthreads();
    int lane = threadIdx.x & 31, wid = threadIdx.x >> 5;
    #pragma unroll
    for (int o = 16; o; o >>= 1) v += __shfl_down_sync(0xffffffffu, v, o);
    if (!lane) sh[wid] = v;
    __syncthreads();
    if (threadIdx.x < 8) {
        float t = sh[threadIdx.x];
        #pragma unroll
        for (int o = 4; o; o >>= 1) t += __shfl_down_sync(0xffu, t, o);
        if (!threadIdx.x) sh[32] = t;
    }
    __syncthreads();
    return sh[32];
}

__global__ void __launch_bounds__(256) ln_kernel(const float* __restrict__ x,
                                                 float* __restrict__ y,
                                                 const float* __restrict__ g,
                                                 const float* __restrict__ b,
                                                 int width) {
    extern __shared__ float row[];
    const float* xr = x + (size_t)blockIdx.x * width;
    float s = 0.f;
    for (int i = threadIdx.x; i < width; i += blockDim.x) { float v = xr[i]; row[i] = v; s += v; }
    float m = blockReduceSum(s) / (float)width;
    float v2 = 0.f;
    for (int i = threadIdx.x; i < width; i += blockDim.x) { float d = row[i] - m; v2 += d*d; }
    float var = blockReduceSum(v2) / (float)width;
    float r = rsqrtf(var + 1e-5f);
    float* yr = y + (size_t)blockIdx.x * width;
    for (int i = threadIdx.x; i < width; i += blockDim.x)
        yr[i] = (row[i] - m) * r * g[i] + b[i];
}

// ---------------- tf32 tensor-core GEMM: C = s*(A @ W^T) + bias + resid -----
// Split-precision: A = Ah + Al (tf32 each). CHAINS==2: weight assumed exact in
// tf32 (ternary). CHAINS==3: also split W (3xTF32, ~fp32 accuracy).
__device__ __forceinline__ void mma8(float c[4], const uint32_t a[4], const uint32_t b[2]) {
    asm volatile(
        "mma.sync.aligned.m16n8k8.row.col.f32.tf32.tf32.f32 "
        "{%0,%1,%2,%3}, {%4,%5,%6,%7}, {%8,%9}, {%0,%1,%2,%3};\n"
        : "+f"(c[0]), "+f"(c[1]), "+f"(c[2]), "+f"(c[3])
        : "r"(a[0]), "r"(a[1]), "r"(a[2]), "r"(a[3]), "r"(b[0]), "r"(b[1]));
}
__device__ __forceinline__ float to_tf32(float x) {
    float r; asm("cvt.rna.tf32.f32 %0, %1;" : "=f"(r) : "f"(x)); return r;
}

#define GPAD 20
template<int CHAINS>
__global__ void __launch_bounds__(256) gemm_tf32(
    const float* __restrict__ A, const float* __restrict__ W,
    const float* __restrict__ sumptr, float wcount,
    const float* __restrict__ bias, const float* __restrict__ resid,
    float* __restrict__ C, int M, int N, int K)
{
    __shared__ float Ah[128][GPAD], Al[128][GPAD], Wh[128][GPAD], Wl[128][GPAD];
    int t = threadIdx.x;
    int lane = t & 31, wid = t >> 5;
    int wm = wid >> 2, wn = wid & 3;       // 2x4 warp grid
    int bm = blockIdx.y * 128, bn = blockIdx.x * 128;
    float acc[4][4][4] = {};

    for (int k0 = 0; k0 < K; k0 += 16) {
        #pragma unroll
        for (int it = 0; it < 2; it++) {
            int idx = it*256 + t;          // 0..511 float4 slots
            int row = idx >> 2, kf = (idx & 3) << 2;
            float4 a4 = *(const float4*)(A + (size_t)(bm+row)*K + k0 + kf);
            float4 w4 = *(const float4*)(W + (size_t)(bn+row)*K + k0 + kf);
            float av[4] = {a4.x, a4.y, a4.z, a4.w};
            float wv[4] = {w4.x, w4.y, w4.z, w4.w};
            #pragma unroll
            for (int u = 0; u < 4; u++) {
                float hi = to_tf32(av[u]);
                Ah[row][kf+u] = hi;
                Al[row][kf+u] = to_tf32(av[u] - hi);
                float whi = to_tf32(wv[u]);
                Wh[row][kf+u] = whi;
                if (CHAINS == 3) Wl[row][kf+u] = to_tf32(wv[u] - whi);
            }
        }
        __syncthreads();

        #pragma unroll
        for (int kk = 0; kk < 16; kk += 8) {
            uint32_t bh[4][2], bl[4][2];
            #pragma unroll
            for (int j = 0; j < 4; j++) {
                int n0 = wn*32 + j*8 + (lane >> 2);
                int c0 = kk + (lane & 3);
                bh[j][0] = __float_as_uint(Wh[n0][c0]);
                bh[j][1] = __float_as_uint(Wh[n0][c0+4]);
                if (CHAINS == 3) {
                    bl[j][0] = __float_as_uint(Wl[n0][c0]);
                    bl[j][1] = __float_as_uint(Wl[n0][c0+4]);
                }
            }
            #pragma unroll
            for (int i = 0; i < 4; i++) {
                int r0 = wm*64 + i*16 + (lane >> 2);
                int c0 = kk + (lane & 3);
                uint32_t ah[4], al[4];
                ah[0] = __float_as_uint(Ah[r0  ][c0]);
                ah[1] = __float_as_uint(Ah[r0+8][c0]);
                ah[2] = __float_as_uint(Ah[r0  ][c0+4]);
                ah[3] = __float_as_uint(Ah[r0+8][c0+4]);
                al[0] = __float_as_uint(Al[r0  ][c0]);
                al[1] = __float_as_uint(Al[r0+8][c0]);
                al[2] = __float_as_uint(Al[r0  ][c0+4]);
                al[3] = __float_as_uint(Al[r0+8][c0+4]);
                #pragma unroll
                for (int j = 0; j < 4; j++) {
                    mma8(acc[i][j], ah, bh[j]);
                    mma8(acc[i][j], al, bh[j]);
                    if (CHAINS == 3) mma8(acc[i][j], ah, bl[j]);
                }
            }
        }
        __syncthreads();
    }

    float s = 1.0f;
    if (sumptr) s = sumptr[0] / wcount + 1e-8f;
    #pragma unroll
    for (int i = 0; i < 4; i++) {
        int r0 = bm + wm*64 + i*16 + (lane >> 2);
        #pragma unroll
        for (int j = 0; j < 4; j++) {
            int c0 = bn + wn*32 + j*8 + ((lane & 3) << 1);
            float v0 = acc[i][j][0]*s, v1 = acc[i][j][1]*s;
            float v2 = acc[i][j][2]*s, v3 = acc[i][j][3]*s;
            if (bias) { v0 += bias[c0]; v1 += bias[c0+1]; v2 += bias[c0]; v3 += bias[c0+1]; }
            if (resid) {
                v0 += resid[(size_t)r0*N + c0];     v1 += resid[(size_t)r0*N + c0+1];
                v2 += resid[(size_t)(r0+8)*N + c0]; v3 += resid[(size_t)(r0+8)*N + c0+1];
            }
            C[(size_t)r0*N + c0]       = v0; C[(size_t)r0*N + c0+1]     = v1;
            C[(size_t)(r0+8)*N + c0]   = v2; C[(size_t)(r0+8)*N + c0+1] = v3;
        }
    }
}

// ---------------- attention: S = Q K^T * scale ------------------------------
__global__ void __launch_bounds__(256) attn_scores(const float* __restrict__ qkv,
                                                   float* __restrict__ S) {
    int bh = blockIdx.z;
    int b = bh / HEADS, hh = bh % HEADS;
    const float* base = qkv + (size_t)b * SEQ * (3*INNER);
    const float* Q  = base + hh * DHEAD;
    const float* Kp = base + INNER + hh * DHEAD;
    int m0 = blockIdx.y * 64, n0 = blockIdx.x * 64;
    __shared__ float Qs[64][65];
    __shared__ float Ks[64][65];
    int t = threadIdx.x;
    #pragma unroll
    for (int it = 0; it < 4; it++) {
        int idx = it*256 + t;
        int m = idx >> 4;
        int d = (idx & 15) << 2;
        float4 q4 = *(const float4*)(Q  + (size_t)(m0+m)*(3*INNER) + d);
        float4 k4 = *(const float4*)(Kp + (size_t)(n0+m)*(3*INNER) + d);
        Qs[d+0][m] = q4.x; Qs[d+1][m] = q4.y; Qs[d+2][m] = q4.z; Qs[d+3][m] = q4.w;
        Ks[d+0][m] = k4.x; Ks[d+1][m] = k4.y; Ks[d+2][m] = k4.z; Ks[d+3][m] = k4.w;
    }
    __syncthreads();
    int tx = t & 15, ty = t >> 4;
    float acc[4][4] = {};
    #pragma unroll
    for (int k = 0; k < 64; k++) {
        float ra[4], rk[4];
        #pragma unroll
        for (int i = 0; i < 4; i++) ra[i] = Qs[k][ty*4+i];
        #pragma unroll
        for (int j = 0; j < 4; j++) rk[j] = Ks[k][tx*4+j];
        #pragma unroll
        for (int i = 0; i < 4; i++)
            #pragma unroll
            for (int j = 0; j < 4; j++)
                acc[i][j] += ra[i] * rk[j];
    }
    float* Sout = S + ((size_t)bh << 20);
    #pragma unroll
    for (int i = 0; i < 4; i++)
        #pragma unroll
        for (int j = 0; j < 4; j++)
            Sout[(size_t)(m0+ty*4+i)*SEQ + n0+tx*4+j] = acc[i][j] * SCALE;
}

// ---------------- softmax over rows of S ------------------------------------
__global__ void __launch_bounds__(256) softmax_kernel(float* __restrict__ S) {
    __shared__ float row[SEQ];
    __shared__ float red[8];
    float* r = S + (size_t)blockIdx.x * SEQ;
    int t = threadIdx.x;
    float mx = -1e30f;
    for (int i = t; i < SEQ; i += 256) { float v = r[i]; row[i] = v; mx = fmaxf(mx, v); }
    #pragma unroll
    for (int o = 16; o; o >>= 1) mx = fmaxf(mx, __shfl_xor_sync(0xffffffffu, mx, o));
    if ((t & 31) == 0) red[t >> 5] = mx;
    __syncthreads();
    if (t < 8) {
        float v = red[t];
        #pragma unroll
        for (int o = 4; o; o >>= 1) v = fmaxf(v, __shfl_xor_sync(0xffu, v, o));
        if (!t) red[0] = v;
    }
    __syncthreads();
    mx = red[0];
    float s = 0.f;
    for (int i = t; i < SEQ; i += 256) { float e = __expf(row[i] - mx); row[i] = e; s += e; }
    __syncthreads();
    #pragma unroll
    for (int o = 16; o; o >>= 1) s += __shfl_xor_sync(0xffffffffu, s, o);
    if ((t & 31) == 0) red[t >> 5] = s;
    __syncthreads();
    if (t < 8) {
        float v = red[t];
        #pragma unroll
        for (int o = 4; o; o >>= 1) v += __shfl_xor_sync(0xffu, v, o);
        if (!t) red[0] = v;
    }
    __syncthreads();
    float inv = 1.0f / red[0];
    for (int i = t; i < SEQ; i += 256) r[i] = row[i] * inv;
}

// ---------------- attention: O = P V ----------------------------------------
__global__ void __launch_bounds__(256) attn_pv(const float* __restrict__ S,
                                               const float* __restrict__ qkv,
                                               float* __restrict__ O) {
    int bh = blockIdx.z;
    int b = bh / HEADS, hh = bh % HEADS;
    int n0 = blockIdx.y * 64;
    const float* Srow = S + ((size_t)bh << 20);
    const float* Vb = qkv + (size_t)b * SEQ * (3*INNER) + 2*INNER + hh * DHEAD;
    __shared__ float Ps[32][65];
    __shared__ __align__(16) float Vs[32][64];
    int t = threadIdx.x;
    int tx = t & 15, ty = t >> 4;
    float acc[4][4] = {};
    for (int k0 = 0; k0 < SEQ; k0 += 32) {
        #pragma unroll
        for (int it = 0; it < 2; it++) {
            int idx = it*256 + t;
            int n  = idx >> 3;
            int k4 = (idx & 7) << 2;
            float4 p4 = *(const float4*)(Srow + (size_t)(n0+n)*SEQ + k0 + k4);
            Ps[k4+0][n] = p4.x; Ps[k4+1][n] = p4.y; Ps[k4+2][n] = p4.z; Ps[k4+3][n] = p4.w;
            int kk = idx >> 4;
            int dd = (idx & 15) << 2;
            *(float4*)&Vs[kk][dd] = *(const float4*)(Vb + (size_t)(k0+kk)*(3*INNER) + dd);
        }
        __syncthreads();
        #pragma unroll
        for (int k = 0; k < 32; k++) {
            float rp[4], rv[4];
            #pragma unroll
            for (int i = 0; i < 4; i++) rp[i] = Ps[k][ty*4+i];
            #pragma unroll
            for (int j = 0; j < 4; j++) rv[j] = Vs[k][tx*4+j];
            #pragma unroll
            for (int i = 0; i < 4; i++)
                #pragma unroll
                for (int j = 0; j < 4; j++)
                    acc[i][j] += rp[i] * rv[j];
        }
        __syncthreads();
    }
    #pragma unroll
    for (int i = 0; i < 4; i++)
        #pragma unroll
        for (int j = 0; j < 4; j++)
            O[((size_t)b*SEQ + n0+ty*4+i)*INNER + hh*DHEAD + tx*4+j] = acc[i][j];
}

// ---------------- GELU (exact) ----------------------------------------------
__global__ void gelu_kernel(float* __restrict__ y, size_t n) {
    for (size_t i = blockIdx.x*(size_t)blockDim.x + threadIdx.x; i < n;
         i += (size_t)gridDim.x*blockDim.x) {
        float v = y[i];
        y[i] = v * 0.5f * (1.0f + erff(v * 0.70710678118654752f));
    }
}

// ---------------- host driver -----------------------------------------------
extern "C" void kernel_launch(void* const* d_in, const int* in_sizes, int n_in,
                              void* d_out, int out_size) {
    const float* x    = (const float*)d_in[0];
    const float* ln1g = (const float*)d_in[1];
    const float* ln1b = (const float*)d_in[2];
    const float* Wqkv = (const float*)d_in[3];
    const float* ln2g = (const float*)d_in[4];
    const float* ln2b = (const float*)d_in[5];
    const float* Wo   = (const float*)d_in[6];
    const float* bo   = (const float*)d_in[7];
    const float* f1g  = (const float*)d_in[8];
    const float* f1b  = (const float*)d_in[9];
    const float* W1   = (const float*)d_in[10];
    const float* b1   = (const float*)d_in[11];
    const float* f2g  = (const float*)d_in[12];
    const float* f2b  = (const float*)d_in[13];
    const float* W2   = (const float*)d_in[14];
    const float* b2   = (const float*)d_in[15];
    float* h = (float*)d_out;

    float *lnb, *qkv, *sc, *ob, *mlp, *wqkvq, *woq, *w1q, *w2q, *scal;
    cudaGetSymbolAddress((void**)&lnb,   g_ln);
    cudaGetSymbolAddress((void**)&qkv,   g_qkv);
    cudaGetSymbolAddress((void**)&sc,    g_scores);
    cudaGetSymbolAddress((void**)&ob,    g_obuf);
    cudaGetSymbolAddress((void**)&mlp,   g_mlp);
    cudaGetSymbolAddress((void**)&wqkvq, g_wqkv);
    cudaGetSymbolAddress((void**)&woq,   g_wo);
    cudaGetSymbolAddress((void**)&w1q,   g_w1);
    cudaGetSymbolAddress((void**)&w2q,   g_w2);
    cudaGetSymbolAddress((void**)&scal,  g_scal);

    cudaMemcpyAsync(h, x, sizeof(float)*(size_t)ROWS*DIMM, cudaMemcpyDeviceToDevice);

    const int NQKV = 3*INNER;
    for (int l = 0; l < DEPTH; l++) {
        const float* wqkv_l = Wqkv + (size_t)l * NQKV*DIMM;
        const float* wo_l   = Wo   + (size_t)l * DIMM*INNER;
        const float* w1_l   = W1   + (size_t)l * MLPD*DIMM;
        const float* w2_l   = W2   + (size_t)l * DIMM*MLPD;
        bool tern = (l < DEPTH - 1);

        if (tern) {
            cudaMemsetAsync(scal, 0, 4*sizeof(float));
            abs_sum_kernel<<<512,256>>>(wqkv_l, scal+0, NQKV*DIMM);
            abs_sum_kernel<<<512,256>>>(wo_l,   scal+1, DIMM*INNER);
            abs_sum_kernel<<<512,256>>>(w1_l,   scal+2, MLPD*DIMM);
            abs_sum_kernel<<<512,256>>>(w2_l,   scal+3, DIMM*MLPD);
            quant_kernel<<<512,256>>>(wqkv_l, wqkvq, scal, 0, NQKV*DIMM);
            quant_kernel<<<512,256>>>(wo_l,   woq,   scal, 1, DIMM*INNER);
            quant_kernel<<<512,256>>>(w1_l,   w1q,   scal, 2, MLPD*DIMM);
            quant_kernel<<<512,256>>>(w2_l,   w2q,   scal, 3, DIMM*MLPD);
        }

        // attention block
        ln_kernel<<<ROWS,256,DIMM*4>>>(h, lnb, ln1g + l*DIMM, ln1b + l*DIMM, DIMM);
        if (tern)
            gemm_tf32<2><<<dim3(NQKV/128, ROWS/128),256>>>(lnb, wqkvq, scal+0,
                (float)(NQKV*DIMM), nullptr, nullptr, qkv, ROWS, NQKV, DIMM);
        else
            gemm_tf32<3><<<dim3(NQKV/128, ROWS/128),256>>>(lnb, wqkv_l, nullptr,
                1.0f, nullptr, nullptr, qkv, ROWS, NQKV, DIMM);
        attn_scores<<<dim3(16,16,BB*HEADS),256>>>(qkv, sc);
        softmax_kernel<<<BB*HEADS*SEQ,256>>>(sc);
        attn_pv<<<dim3(1,16,BB*HEADS),256>>>(sc, qkv, ob);
        ln_kernel<<<ROWS,256,INNER*4>>>(ob, ob, ln2g + l*INNER, ln2b + l*INNER, INNER);
        if (tern)
            gemm_tf32<2><<<dim3(DIMM/128, ROWS/128),256>>>(ob, woq, scal+1,
                (float)(DIMM*INNER), bo + l*DIMM, h, h, ROWS, DIMM, INNER);
        else
            gemm_tf32<3><<<dim3(DIMM/128, ROWS/128),256>>>(ob, wo_l, nullptr,
                1.0f, bo + l*DIMM, h, h, ROWS, DIMM, INNER);

        // MLP block
        ln_kernel<<<ROWS,256,DIMM*4>>>(h, lnb, f1g + l*DIMM, f1b + l*DIMM, DIMM);
        if (tern)
            gemm_tf32<2><<<dim3(MLPD/128, ROWS/128),256>>>(lnb, w1q, scal+2,
                (float)(MLPD*DIMM), b1 + l*MLPD, nullptr, mlp, ROWS, MLPD, DIMM);
        else
            gemm_tf32<3><<<dim3(MLPD/128, ROWS/128),256>>>(lnb, w1_l, nullptr,
                1.0f, b1 + l*MLPD, nullptr, mlp, ROWS, MLPD, DIMM);
        gelu_kernel<<<4096,256>>>(mlp, (size_t)ROWS*MLPD);
        ln_kernel<<<ROWS,256,MLPD*4>>>(mlp, mlp, f2g + l*MLPD, f2b + l*MLPD, MLPD);
        if (tern)
            gemm_tf32<2><<<dim3(DIMM/128, ROWS/128),256>>>(mlp, w2q, scal+3,
                (float)(DIMM*MLPD), b2 + l*DIMM, h, h, ROWS, DIMM, MLPD);
        else
            gemm_tf32<3><<<dim3(DIMM/128, ROWS/128),256>>>(mlp, w2_l, nullptr,
                1.0f, b2 + l*DIMM, h, h, ROWS, DIMM, MLPD);
    }
}

// round 4
// speedup vs baseline: 1.8044x; 1.4045x over previous
#include <cuda_runtime.h>
#include <math.h>
#include <stdint.h>

#define DIMM  768
#define HEADS 12
#define DHEAD 64
#define INNER 768
#define MLPD  3072
#define BB    8
#define SEQ   1024
#define ROWS  (BB*SEQ)   /* 8192 */
#define DEPTH 6
#define SCALE 0.125f     /* 64^-0.5 */

// ---------------- scratch (device globals: no allocations allowed) ----------
__device__ __align__(16) float g_ln[ROWS*DIMM];
__device__ __align__(16) float g_qkv[(size_t)ROWS*3*INNER];
__device__ __align__(16) float g_obuf[ROWS*INNER];
__device__ __align__(16) float g_mlp[(size_t)ROWS*MLPD];
__device__ __align__(16) float g_wqkv[3*INNER*DIMM];
__device__ __align__(16) float g_wo[DIMM*INNER];
__device__ __align__(16) float g_w1[MLPD*DIMM];
__device__ __align__(16) float g_w2[DIMM*MLPD];
__device__ float g_scal[4];

// ---------------- ternary quantization -------------------------------------
__global__ void abs_sum_kernel(const float* __restrict__ w, float* out, int n) {
    float s = 0.f;
    for (int i = blockIdx.x*blockDim.x + threadIdx.x; i < n; i += gridDim.x*blockDim.x)
        s += fabsf(w[i]);
    #pragma unroll
    for (int o = 16; o; o >>= 1) s += __shfl_down_sync(0xffffffffu, s, o);
    __shared__ float sh[8];
    if ((threadIdx.x & 31) == 0) sh[threadIdx.x >> 5] = s;
    __syncthreads();
    if (threadIdx.x < 8) {
        float v = sh[threadIdx.x];
        #pragma unroll
        for (int o = 4; o; o >>= 1) v += __shfl_down_sync(0xffu, v, o);
        if (threadIdx.x == 0) atomicAdd(out, v);
    }
}

// emits TERNARY values {-1,0,+1} (scale applied in GEMM epilogue)
__global__ void quant_kernel(const float* __restrict__ w, float* __restrict__ q,
                             const float* __restrict__ sums, int idx, int n) {
    float s = sums[idx] / (float)n + 1e-8f;
    float inv = 1.0f / s;
    for (int i = blockIdx.x*blockDim.x + threadIdx.x; i < n; i += gridDim.x*blockDim.x) {
        float t = rintf(w[i] * inv);
        t = fminf(1.0f, fmaxf(-1.0f, t));
        q[i] = t;
    }
}

// ---------------- layernorm -------------------------------------------------
__device__ __forceinline__ float blockReduceSum(float v) {
    __shared__ float sh[33];
    __syncthreads();
    int lane = threadIdx.x & 31, wid = threadIdx.x >> 5;
    #pragma unroll
    for (int o = 16; o; o >>= 1) v += __shfl_down_sync(0xffffffffu, v, o);
    if (!lane) sh[wid] = v;
    __syncthreads();
    if (threadIdx.x < 8) {
        float t = sh[threadIdx.x];
        #pragma unroll
        for (int o = 4; o; o >>= 1) t += __shfl_down_sync(0xffu, t, o);
        if (!threadIdx.x) sh[32] = t;
    }
    __syncthreads();
    return sh[32];
}

__global__ void __launch_bounds__(256) ln_kernel(const float* __restrict__ x,
                                                 float* __restrict__ y,
                                                 const float* __restrict__ g,
                                                 const float* __restrict__ b,
                                                 int width) {
    extern __shared__ float row[];
    const float* xr = x + (size_t)blockIdx.x * width;
    float s = 0.f;
    for (int i = threadIdx.x; i < width; i += blockDim.x) { float v = xr[i]; row[i] = v; s += v; }
    float m = blockReduceSum(s) / (float)width;
    float v2 = 0.f;
    for (int i = threadIdx.x; i < width; i += blockDim.x) { float d = row[i] - m; v2 += d*d; }
    float var = blockReduceSum(v2) / (float)width;
    float r = rsqrtf(var + 1e-5f);
    float* yr = y + (size_t)blockIdx.x * width;
    for (int i = threadIdx.x; i < width; i += blockDim.x)
        yr[i] = (row[i] - m) * r * g[i] + b[i];
}

// ---------------- tf32 tensor-core GEMM (double-buffered) -------------------
// C = s*(A @ W^T) + bias [+gelu] [+resid]
// CHAINS==2: W exact in tf32 (ternary), A split hi/lo.
// CHAINS==3: W also split (3xTF32, ~fp32 accuracy).
__device__ __forceinline__ void mma8(float c[4], const uint32_t a[4], const uint32_t b[2]) {
    asm volatile(
        "mma.sync.aligned.m16n8k8.row.col.f32.tf32.tf32.f32 "
        "{%0,%1,%2,%3}, {%4,%5,%6,%7}, {%8,%9}, {%0,%1,%2,%3};\n"
        : "+f"(c[0]), "+f"(c[1]), "+f"(c[2]), "+f"(c[3])
        : "r"(a[0]), "r"(a[1]), "r"(a[2]), "r"(a[3]), "r"(b[0]), "r"(b[1]));
}
__device__ __forceinline__ float to_tf32(float x) {
    float r; asm("cvt.rna.tf32.f32 %0, %1;" : "=f"(r) : "f"(x)); return r;
}

#define GPAD 20
#define GTILE (128*GPAD)
#define GSMEM2 (6*GTILE*4)   /* 61440 B */
#define GSMEM3 (8*GTILE*4)   /* 81920 B */

template<int CHAINS, int EPI>
__global__ void __launch_bounds__(256) gemm_tf32(
    const float* __restrict__ A, const float* __restrict__ W,
    const float* __restrict__ sumptr, float wcount,
    const float* __restrict__ bias, const float* __restrict__ resid,
    float* __restrict__ C, int M, int N, int K)
{
    extern __shared__ float sm[];
    float* AH = sm;
    float* AL = sm + 2*GTILE;
    float* WH = sm + 4*GTILE;
    float* WL = sm + 6*GTILE;   // valid only when CHAINS==3 (smem sized accordingly)
    int t = threadIdx.x;
    int lane = t & 31, wid = t >> 5;
    int wm = wid >> 2, wn = wid & 3;
    int bm = blockIdx.y * 128, bn = blockIdx.x * 128;
    float acc[4][4][4] = {};
    float4 pa[2], pw[2];

    // preload tile 0
    #pragma unroll
    for (int it = 0; it < 2; it++) {
        int idx = it*256 + t, row = idx >> 2, kf = (idx & 3) << 2;
        pa[it] = *(const float4*)(A + (size_t)(bm+row)*K + kf);
        pw[it] = *(const float4*)(W + (size_t)(bn+row)*K + kf);
    }
    #pragma unroll
    for (int it = 0; it < 2; it++) {
        int idx = it*256 + t, row = idx >> 2, kf = (idx & 3) << 2;
        float av[4] = {pa[it].x, pa[it].y, pa[it].z, pa[it].w};
        float wv[4] = {pw[it].x, pw[it].y, pw[it].z, pw[it].w};
        #pragma unroll
        for (int u = 0; u < 4; u++) {
            float hi = to_tf32(av[u]);
            AH[row*GPAD + kf+u] = hi;
            AL[row*GPAD + kf+u] = to_tf32(av[u] - hi);
            if (CHAINS == 3) {
                float whi = to_tf32(wv[u]);
                WH[row*GPAD + kf+u] = whi;
                WL[row*GPAD + kf+u] = to_tf32(wv[u] - whi);
            } else {
                WH[row*GPAD + kf+u] = wv[u];
            }
        }
    }
    __syncthreads();

    for (int k0 = 0; k0 < K; k0 += 16) {
        int st = (k0 >> 4) & 1;
        bool more = (k0 + 16 < K);
        if (more) {
            #pragma unroll
            for (int it = 0; it < 2; it++) {
                int idx = it*256 + t, row = idx >> 2, kf = (idx & 3) << 2;
                pa[it] = *(const float4*)(A + (size_t)(bm+row)*K + k0+16 + kf);
                pw[it] = *(const float4*)(W + (size_t)(bn+row)*K + k0+16 + kf);
            }
        }
        const float* AHs = AH + st*GTILE;
        const float* ALs = AL + st*GTILE;
        const float* WHs = WH + st*GTILE;
        const float* WLs = WL + st*GTILE;

        #pragma unroll
        for (int kk = 0; kk < 16; kk += 8) {
            uint32_t bh[4][2], bl[4][2];
            #pragma unroll
            for (int j = 0; j < 4; j++) {
                int n0 = wn*32 + j*8 + (lane >> 2);
                int c0 = kk + (lane & 3);
                bh[j][0] = __float_as_uint(WHs[n0*GPAD + c0]);
                bh[j][1] = __float_as_uint(WHs[n0*GPAD + c0+4]);
                if (CHAINS == 3) {
                    bl[j][0] = __float_as_uint(WLs[n0*GPAD + c0]);
                    bl[j][1] = __float_as_uint(WLs[n0*GPAD + c0+4]);
                }
            }
            #pragma unroll
            for (int i = 0; i < 4; i++) {
                int r0 = wm*64 + i*16 + (lane >> 2);
                int c0 = kk + (lane & 3);
                uint32_t ah[4], al[4];
                ah[0] = __float_as_uint(AHs[r0*GPAD + c0]);
                ah[1] = __float_as_uint(AHs[(r0+8)*GPAD + c0]);
                ah[2] = __float_as_uint(AHs[r0*GPAD + c0+4]);
                ah[3] = __float_as_uint(AHs[(r0+8)*GPAD + c0+4]);
                al[0] = __float_as_uint(ALs[r0*GPAD + c0]);
                al[1] = __float_as_uint(ALs[(r0+8)*GPAD + c0]);
                al[2] = __float_as_uint(ALs[r0*GPAD + c0+4]);
                al[3] = __float_as_uint(ALs[(r0+8)*GPAD + c0+4]);
                #pragma unroll
                for (int j = 0; j < 4; j++) {
                    mma8(acc[i][j], ah, bh[j]);
                    mma8(acc[i][j], al, bh[j]);
                    if (CHAINS == 3) mma8(acc[i][j], ah, bl[j]);
                }
            }
        }

        if (more) {
            int nx = st ^ 1;
            #pragma unroll
            for (int it = 0; it < 2; it++) {
                int idx = it*256 + t, row = idx >> 2, kf = (idx & 3) << 2;
                float av[4] = {pa[it].x, pa[it].y, pa[it].z, pa[it].w};
                float wv[4] = {pw[it].x, pw[it].y, pw[it].z, pw[it].w};
                #pragma unroll
                for (int u = 0; u < 4; u++) {
                    float hi = to_tf32(av[u]);
                    AH[nx*GTILE + row*GPAD + kf+u] = hi;
                    AL[nx*GTILE + row*GPAD + kf+u] = to_tf32(av[u] - hi);
                    if (CHAINS == 3) {
                        float whi = to_tf32(wv[u]);
                        WH[nx*GTILE + row*GPAD + kf+u] = whi;
                        WL[nx*GTILE + row*GPAD + kf+u] = to_tf32(wv[u] - whi);
                    } else {
                        WH[nx*GTILE + row*GPAD + kf+u] = wv[u];
                    }
                }
            }
        }
        __syncthreads();
    }

    float s = 1.0f;
    if (sumptr) s = sumptr[0] / wcount + 1e-8f;
    #pragma unroll
    for (int i = 0; i < 4; i++) {
        int r0 = bm + wm*64 + i*16 + (lane >> 2);
        #pragma unroll
        for (int j = 0; j < 4; j++) {
            int c0 = bn + wn*32 + j*8 + ((lane & 3) << 1);
            float v[4] = {acc[i][j][0]*s, acc[i][j][1]*s, acc[i][j][2]*s, acc[i][j][3]*s};
            if (bias) { v[0] += bias[c0]; v[1] += bias[c0+1]; v[2] += bias[c0]; v[3] += bias[c0+1]; }
            if (EPI == 1) {
                #pragma unroll
                for (int u = 0; u < 4; u++)
                    v[u] = v[u] * 0.5f * (1.0f + erff(v[u] * 0.70710678118654752f));
            }
            if (resid) {
                v[0] += resid[(size_t)r0*N + c0];     v[1] += resid[(size_t)r0*N + c0+1];
                v[2] += resid[(size_t)(r0+8)*N + c0]; v[3] += resid[(size_t)(r0+8)*N + c0+1];
            }
            C[(size_t)r0*N + c0]       = v[0]; C[(size_t)r0*N + c0+1]     = v[1];
            C[(size_t)(r0+8)*N + c0]   = v[2]; C[(size_t)(r0+8)*N + c0+1] = v[3];
        }
    }
}

// ---------------- fused flash attention (fp32) ------------------------------
// One block = one (b,h) x 64 query rows; streams K/V in 64-key chunks with
// online softmax. No materialized score tensor.
#define FLASH_SMEM ((3*64*65 + 64*68)*4)   /* 67328 B */

__global__ void __launch_bounds__(256) attn_flash(const float* __restrict__ qkv,
                                                  float* __restrict__ O) {
    extern __shared__ float fs[];
    float (*Qs)[65] = (float(*)[65])fs;
    float (*Ks)[65] = (float(*)[65])(fs + 64*65);
    float (*Ps)[65] = (float(*)[65])(fs + 2*64*65);
    float (*Vs)[68] = (float(*)[68])(fs + 3*64*65);

    int bh = blockIdx.y;
    int b = bh / HEADS, hh = bh % HEADS;
    int m0 = blockIdx.x * 64;
    const float* base = qkv + (size_t)b * SEQ * (3*INNER);
    const float* Qp = base + hh * DHEAD;
    const float* Kp = base + INNER + hh * DHEAD;
    const float* Vp = base + 2*INNER + hh * DHEAD;
    int t = threadIdx.x;
    int tx = t & 15, ty = t >> 4;

    #pragma unroll
    for (int it = 0; it < 4; it++) {
        int idx = it*256 + t;
        int m = idx >> 4, d = (idx & 15) << 2;
        float4 q4 = *(const float4*)(Qp + (size_t)(m0+m)*(3*INNER) + d);
        Qs[d+0][m] = q4.x; Qs[d+1][m] = q4.y; Qs[d+2][m] = q4.z; Qs[d+3][m] = q4.w;
    }

    float mi[4], li[4], acc[4][4];
    #pragma unroll
    for (int i = 0; i < 4; i++) {
        mi[i] = -1e30f; li[i] = 0.f;
        #pragma unroll
        for (int j = 0; j < 4; j++) acc[i][j] = 0.f;
    }

    for (int k0 = 0; k0 < SEQ; k0 += 64) {
        __syncthreads();   // prev-iter PV readers done (also orders Q load, iter 0)
        #pragma unroll
        for (int it = 0; it < 4; it++) {
            int idx = it*256 + t;
            int n = idx >> 4, d = (idx & 15) << 2;
            float4 k4 = *(const float4*)(Kp + (size_t)(k0+n)*(3*INNER) + d);
            Ks[d+0][n] = k4.x; Ks[d+1][n] = k4.y; Ks[d+2][n] = k4.z; Ks[d+3][n] = k4.w;
            float4 v4 = *(const float4*)(Vp + (size_t)(k0+n)*(3*INNER) + d);
            *(float4*)&Vs[n][d] = v4;
        }
        __syncthreads();

        float s[4][4] = {};
        #pragma unroll
        for (int d = 0; d < 64; d++) {
            float ra[4], rk[4];
            #pragma unroll
            for (int i = 0; i < 4; i++) ra[i] = Qs[d][ty*4+i];
            #pragma unroll
            for (int j = 0; j < 4; j++) rk[j] = Ks[d][tx*4+j];
            #pragma unroll
            for (int i = 0; i < 4; i++)
                #pragma unroll
                for (int j = 0; j < 4; j++)
                    s[i][j] += ra[i] * rk[j];
        }

        float p[4][4];
        #pragma unroll
        for (int i = 0; i < 4; i++) {
            float rm = -1e30f;
            #pragma unroll
            for (int j = 0; j < 4; j++) { s[i][j] *= SCALE; rm = fmaxf(rm, s[i][j]); }
            #pragma unroll
            for (int o = 1; o < 16; o <<= 1)
                rm = fmaxf(rm, __shfl_xor_sync(0xffffffffu, rm, o));
            float mn = fmaxf(mi[i], rm);
            float f = __expf(mi[i] - mn);
            mi[i] = mn;
            float sum = 0.f;
            #pragma unroll
            for (int j = 0; j < 4; j++) { p[i][j] = __expf(s[i][j] - mn); sum += p[i][j]; }
            #pragma unroll
            for (int o = 1; o < 16; o <<= 1)
                sum += __shfl_xor_sync(0xffffffffu, sum, o);
            li[i] = li[i]*f + sum;
            #pragma unroll
            for (int j = 0; j < 4; j++) acc[i][j] *= f;
        }

        #pragma unroll
        for (int i = 0; i < 4; i++)
            #pragma unroll
            for (int j = 0; j < 4; j++)
                Ps[tx*4+j][ty*4+i] = p[i][j];
        __syncthreads();

        #pragma unroll
        for (int k = 0; k < 64; k++) {
            float rp[4];
            #pragma unroll
            for (int i = 0; i < 4; i++) rp[i] = Ps[k][ty*4+i];
            float4 rv = *(const float4*)&Vs[k][tx*4];
            float rvv[4] = {rv.x, rv.y, rv.z, rv.w};
            #pragma unroll
            for (int i = 0; i < 4; i++)
                #pragma unroll
                for (int j = 0; j < 4; j++)
                    acc[i][j] += rp[i] * rvv[j];
        }
    }

    #pragma unroll
    for (int i = 0; i < 4; i++) {
        float inv = 1.0f / li[i];
        #pragma unroll
        for (int j = 0; j < 4; j++)
            O[((size_t)b*SEQ + m0 + ty*4+i)*INNER + hh*DHEAD + tx*4+j] = acc[i][j] * inv;
    }
}

// ---------------- host driver -----------------------------------------------
extern "C" void kernel_launch(void* const* d_in, const int* in_sizes, int n_in,
                              void* d_out, int out_size) {
    const float* x    = (const float*)d_in[0];
    const float* ln1g = (const float*)d_in[1];
    const float* ln1b = (const float*)d_in[2];
    const float* Wqkv = (const float*)d_in[3];
    const float* ln2g = (const float*)d_in[4];
    const float* ln2b = (const float*)d_in[5];
    const float* Wo   = (const float*)d_in[6];
    const float* bo   = (const float*)d_in[7];
    const float* f1g  = (const float*)d_in[8];
    const float* f1b  = (const float*)d_in[9];
    const float* W1   = (const float*)d_in[10];
    const float* b1   = (const float*)d_in[11];
    const float* f2g  = (const float*)d_in[12];
    const float* f2b  = (const float*)d_in[13];
    const float* W2   = (const float*)d_in[14];
    const float* b2   = (const float*)d_in[15];
    float* h = (float*)d_out;

    float *lnb, *qkv, *ob, *mlp, *wqkvq, *woq, *w1q, *w2q, *scal;
    cudaGetSymbolAddress((void**)&lnb,   g_ln);
    cudaGetSymbolAddress((void**)&qkv,   g_qkv);
    cudaGetSymbolAddress((void**)&ob,    g_obuf);
    cudaGetSymbolAddress((void**)&mlp,   g_mlp);
    cudaGetSymbolAddress((void**)&wqkvq, g_wqkv);
    cudaGetSymbolAddress((void**)&woq,   g_wo);
    cudaGetSymbolAddress((void**)&w1q,   g_w1);
    cudaGetSymbolAddress((void**)&w2q,   g_w2);
    cudaGetSymbolAddress((void**)&scal,  g_scal);

    cudaFuncSetAttribute(gemm_tf32<2,0>, cudaFuncAttributeMaxDynamicSharedMemorySize, GSMEM2);
    cudaFuncSetAttribute(gemm_tf32<2,1>, cudaFuncAttributeMaxDynamicSharedMemorySize, GSMEM2);
    cudaFuncSetAttribute(gemm_tf32<3,0>, cudaFuncAttributeMaxDynamicSharedMemorySize, GSMEM3);
    cudaFuncSetAttribute(gemm_tf32<3,1>, cudaFuncAttributeMaxDynamicSharedMemorySize, GSMEM3);
    cudaFuncSetAttribute(attn_flash,     cudaFuncAttributeMaxDynamicSharedMemorySize, FLASH_SMEM);

    cudaMemcpyAsync(h, x, sizeof(float)*(size_t)ROWS*DIMM, cudaMemcpyDeviceToDevice);

    const int NQKV = 3*INNER;
    for (int l = 0; l < DEPTH; l++) {
        const float* wqkv_l = Wqkv + (size_t)l * NQKV*DIMM;
        const float* wo_l   = Wo   + (size_t)l * DIMM*INNER;
        const float* w1_l   = W1   + (size_t)l * MLPD*DIMM;
        const float* w2_l   = W2   + (size_t)l * DIMM*MLPD;
        bool tern = (l < DEPTH - 1);

        if (tern) {
            cudaMemsetAsync(scal, 0, 4*sizeof(float));
            abs_sum_kernel<<<512,256>>>(wqkv_l, scal+0, NQKV*DIMM);
            abs_sum_kernel<<<512,256>>>(wo_l,   scal+1, DIMM*INNER);
            abs_sum_kernel<<<512,256>>>(w1_l,   scal+2, MLPD*DIMM);
            abs_sum_kernel<<<512,256>>>(w2_l,   scal+3, DIMM*MLPD);
            quant_kernel<<<512,256>>>(wqkv_l, wqkvq, scal, 0, NQKV*DIMM);
            quant_kernel<<<512,256>>>(wo_l,   woq,   scal, 1, DIMM*INNER);
            quant_kernel<<<512,256>>>(w1_l,   w1q,   scal, 2, MLPD*DIMM);
            quant_kernel<<<512,256>>>(w2_l,   w2q,   scal, 3, DIMM*MLPD);
        }

        // attention block
        ln_kernel<<<ROWS,256,DIMM*4>>>(h, lnb, ln1g + l*DIMM, ln1b + l*DIMM, DIMM);
        if (tern)
            gemm_tf32<2,0><<<dim3(NQKV/128, ROWS/128),256,GSMEM2>>>(lnb, wqkvq, scal+0,
                (float)(NQKV*DIMM), nullptr, nullptr, qkv, ROWS, NQKV, DIMM);
        else
            gemm_tf32<3,0><<<dim3(NQKV/128, ROWS/128),256,GSMEM3>>>(lnb, wqkv_l, nullptr,
                1.0f, nullptr, nullptr, qkv, ROWS, NQKV, DIMM);
        attn_flash<<<dim3(16, BB*HEADS),256,FLASH_SMEM>>>(qkv, ob);
        ln_kernel<<<ROWS,256,INNER*4>>>(ob, ob, ln2g + l*INNER, ln2b + l*INNER, INNER);
        if (tern)
            gemm_tf32<2,0><<<dim3(DIMM/128, ROWS/128),256,GSMEM2>>>(ob, woq, scal+1,
                (float)(DIMM*INNER), bo + l*DIMM, h, h, ROWS, DIMM, INNER);
        else
            gemm_tf32<3,0><<<dim3(DIMM/128, ROWS/128),256,GSMEM3>>>(ob, wo_l, nullptr,
                1.0f, bo + l*DIMM, h, h, ROWS, DIMM, INNER);

        // MLP block (GELU fused into FF1 epilogue)
        ln_kernel<<<ROWS,256,DIMM*4>>>(h, lnb, f1g + l*DIMM, f1b + l*DIMM, DIMM);
        if (tern)
            gemm_tf32<2,1><<<dim3(MLPD/128, ROWS/128),256,GSMEM2>>>(lnb, w1q, scal+2,
                (float)(MLPD*DIMM), b1 + l*MLPD, nullptr, mlp, ROWS, MLPD, DIMM);
        else
            gemm_tf32<3,1><<<dim3(MLPD/128, ROWS/128),256,GSMEM3>>>(lnb, w1_l, nullptr,
                1.0f, b1 + l*MLPD, nullptr, mlp, ROWS, MLPD, DIMM);
        ln_kernel<<<ROWS,256,MLPD*4>>>(mlp, mlp, f2g + l*MLPD, f2b + l*MLPD, MLPD);
        if (tern)
            gemm_tf32<2,0><<<dim3(DIMM/128, ROWS/128),256,GSMEM2>>>(mlp, w2q, scal+3,
                (float)(DIMM*MLPD), b2 + l*DIMM, h, h, ROWS, DIMM, MLPD);
        else
            gemm_tf32<3,0><<<dim3(DIMM/128, ROWS/128),256,GSMEM3>>>(mlp, w2_l, nullptr,
                1.0f, b2 + l*DIMM, h, h, ROWS, DIMM, MLPD);
    }
}

// round 6
// speedup vs baseline: 2.3202x; 1.2859x over previous
#include <cuda_runtime.h>
#include <cuda_bf16.h>
#include <math.h>
#include <stdint.h>

#define DIMM  768
#define HEADS 12
#define DHEAD 64
#define INNER 768
#define MLPD  3072
#define BB    8
#define SEQ   1024
#define ROWS  (BB*SEQ)   /* 8192 */
#define DEPTH 6
#define SCALE 0.125f     /* 64^-0.5 */
#define NQKV  (3*INNER)

// ---------------- scratch (device globals: no allocations allowed) ----------
__device__ __align__(16) float g_qkv[(size_t)ROWS*NQKV];
__device__ __align__(16) float g_obuf[ROWS*INNER];
__device__ __align__(16) float g_mlp[(size_t)ROWS*MLPD];
__device__ __align__(16) __nv_bfloat16 g_ah[(size_t)ROWS*MLPD];   // LN out hi
__device__ __align__(16) __nv_bfloat16 g_al[(size_t)ROWS*MLPD];   // LN out lo
__device__ __align__(16) __nv_bfloat16 g_whq[NQKV*DIMM];
__device__ __align__(16) __nv_bfloat16 g_wlq[NQKV*DIMM];
__device__ __align__(16) __nv_bfloat16 g_who[DIMM*INNER];
__device__ __align__(16) __nv_bfloat16 g_wlo[DIMM*INNER];
__device__ __align__(16) __nv_bfloat16 g_wh1[MLPD*DIMM];
__device__ __align__(16) __nv_bfloat16 g_wl1[MLPD*DIMM];
__device__ __align__(16) __nv_bfloat16 g_wh2[DIMM*MLPD];
__device__ __align__(16) __nv_bfloat16 g_wl2[DIMM*MLPD];
__device__ float g_scal[4];

// ---------------- batched abs-sum / quant / split ---------------------------
__global__ void abs_sum4(const float* __restrict__ w0, const float* __restrict__ w1,
                         const float* __restrict__ w2, const float* __restrict__ w3,
                         int n0, int n1, int n2, int n3, float* out) {
    int z = blockIdx.y;
    const float* w = z==0?w0 : z==1?w1 : z==2?w2 : w3;
    int n = z==0?n0 : z==1?n1 : z==2?n2 : n3;
    float s = 0.f;
    for (int i = blockIdx.x*blockDim.x + threadIdx.x; i < n; i += gridDim.x*blockDim.x)
        s += fabsf(w[i]);
    #pragma unroll
    for (int o = 16; o; o >>= 1) s += __shfl_down_sync(0xffffffffu, s, o);
    __shared__ float sh[8];
    if ((threadIdx.x & 31) == 0) sh[threadIdx.x >> 5] = s;
    __syncthreads();
    if (threadIdx.x < 8) {
        float v = sh[threadIdx.x];
        #pragma unroll
        for (int o = 4; o; o >>= 1) v += __shfl_down_sync(0xffu, v, o);
        if (threadIdx.x == 0) atomicAdd(out + z, v);
    }
}

// ternary {-1,0,+1} to bf16 (exact); scale applied in GEMM epilogue
__global__ void quant4(const float* __restrict__ w0, const float* __restrict__ w1,
                       const float* __restrict__ w2, const float* __restrict__ w3,
                       __nv_bfloat16* __restrict__ q0, __nv_bfloat16* __restrict__ q1,
                       __nv_bfloat16* __restrict__ q2, __nv_bfloat16* __restrict__ q3,
                       const float* __restrict__ sums, int n0, int n1, int n2, int n3) {
    int z = blockIdx.y;
    const float* w = z==0?w0 : z==1?w1 : z==2?w2 : w3;
    __nv_bfloat16* q = z==0?q0 : z==1?q1 : z==2?q2 : q3;
    int n = z==0?n0 : z==1?n1 : z==2?n2 : n3;
    float s = sums[z] / (float)n + 1e-8f;
    float inv = 1.0f / s;
    for (int i = blockIdx.x*blockDim.x + threadIdx.x; i < n; i += gridDim.x*blockDim.x) {
        float t = rintf(w[i] * inv);           // half-to-even, matches jnp.round
        t = fminf(1.0f, fmaxf(-1.0f, t));
        q[i] = __float2bfloat16_rn(t);
    }
}

// dense fp32 -> bf16 hi/lo split (layer DEPTH-1)
__global__ void split4(const float* __restrict__ w0, const float* __restrict__ w1,
                       const float* __restrict__ w2, const float* __restrict__ w3,
                       __nv_bfloat16* __restrict__ h0, __nv_bfloat16* __restrict__ h1,
                       __nv_bfloat16* __restrict__ h2, __nv_bfloat16* __restrict__ h3,
                       __nv_bfloat16* __restrict__ l0, __nv_bfloat16* __restrict__ l1,
                       __nv_bfloat16* __restrict__ l2, __nv_bfloat16* __restrict__ l3,
                       int n0, int n1, int n2, int n3) {
    int z = blockIdx.y;
    const float* w = z==0?w0 : z==1?w1 : z==2?w2 : w3;
    __nv_bfloat16* hh = z==0?h0 : z==1?h1 : z==2?h2 : h3;
    __nv_bfloat16* ll = z==0?l0 : z==1?l1 : z==2?l2 : l3;
    int n = z==0?n0 : z==1?n1 : z==2?n2 : n3;
    for (int i = blockIdx.x*blockDim.x + threadIdx.x; i < n; i += gridDim.x*blockDim.x) {
        float v = w[i];
        __nv_bfloat16 hi = __float2bfloat16_rn(v);
        hh[i] = hi;
        ll[i] = __float2bfloat16_rn(v - __bfloat162float(hi));
    }
}

// ---------------- layernorm -> split bf16 ------------------------------------
__device__ __forceinline__ float blockReduceSum(float v) {
    __shared__ float sh[33];
    __syncthreads();
    int lane = threadIdx.x & 31, wid = threadIdx.x >> 5;
    #pragma unroll
    for (int o = 16; o; o >>= 1) v += __shfl_down_sync(0xffffffffu, v, o);
    if (!lane) sh[wid] = v;
    __syncthreads();
    if (threadIdx.x < 8) {
        float t = sh[threadIdx.x];
        #pragma unroll
        for (int o = 4; o; o >>= 1) t += __shfl_down_sync(0xffu, t, o);
        if (!threadIdx.x) sh[32] = t;
    }
    __syncthreads();
    return sh[32];
}

__global__ void __launch_bounds__(256) ln_kernel(const float* __restrict__ x,
                                                 __nv_bfloat16* __restrict__ yh,
                                                 __nv_bfloat16* __restrict__ yl,
                                                 const float* __restrict__ g,
                                                 const float* __restrict__ b,
                                                 int width) {
    extern __shared__ float row[];
    const float* xr = x + (size_t)blockIdx.x * width;
    float s = 0.f;
    for (int i = threadIdx.x; i < width; i += blockDim.x) { float v = xr[i]; row[i] = v; s += v; }
    float m = blockReduceSum(s) / (float)width;
    float v2 = 0.f;
    for (int i = threadIdx.x; i < width; i += blockDim.x) { float d = row[i] - m; v2 += d*d; }
    float var = blockReduceSum(v2) / (float)width;
    float r = rsqrtf(var + 1e-5f);
    __nv_bfloat16* yhr = yh + (size_t)blockIdx.x * width;
    __nv_bfloat16* ylr = yl + (size_t)blockIdx.x * width;
    for (int i = threadIdx.x; i < width; i += blockDim.x) {
        float v = (row[i] - m) * r * g[i] + b[i];
        __nv_bfloat16 hi = __float2bfloat16_rn(v);
        yhr[i] = hi;
        ylr[i] = __float2bfloat16_rn(v - __bfloat162float(hi));
    }
}

// ---------------- bf16 tensor-core GEMM (double-buffered) -------------------
// C = s*(A @ W^T) + bias [+gelu] [+resid],  A = Ah + Al (bf16 split, exact LN out)
// CHAINS==2: W exact in bf16 (ternary):  Ah*W + Al*W
// CHAINS==3: W split hi/lo:              Ah*Wh + Al*Wh + Ah*Wl
__device__ __forceinline__ void mma16(float c[4], const uint32_t a[4], const uint32_t b[2]) {
    asm volatile(
        "mma.sync.aligned.m16n8k16.row.col.f32.bf16.bf16.f32 "
        "{%0,%1,%2,%3}, {%4,%5,%6,%7}, {%8,%9}, {%0,%1,%2,%3};\n"
        : "+f"(c[0]), "+f"(c[1]), "+f"(c[2]), "+f"(c[3])
        : "r"(a[0]), "r"(a[1]), "r"(a[2]), "r"(a[3]), "r"(b[0]), "r"(b[1]));
}

#define GW 20            /* words per 32-elem K-slice row (16 + 4 pad; 80B = 16B-aligned) */
#define GT (128*GW)      /* words per array per stage */
#define GSMEM2 (3*2*GT*4)   /* 61440 B */
#define GSMEM3 (4*2*GT*4)   /* 81920 B */

template<int CHAINS, int EPI>
__global__ void __launch_bounds__(256) gemm_bf16(
    const uint32_t* __restrict__ AHg, const uint32_t* __restrict__ ALg,
    const uint32_t* __restrict__ WHg, const uint32_t* __restrict__ WLg,
    const float* __restrict__ sumptr, float wcount,
    const float* __restrict__ bias, const float* __restrict__ resid,
    float* __restrict__ C, int M, int N, int K)
{
    extern __shared__ uint32_t smw[];
    uint32_t* AH = smw;
    uint32_t* AL = smw + 2*GT;
    uint32_t* WH = smw + 4*GT;
    uint32_t* WL = smw + 6*GT;      // CHAINS==3 only (smem sized accordingly)
    int t = threadIdx.x, lane = t & 31, wid = t >> 5;
    int wm = wid >> 2, wn = wid & 3;
    int bm = blockIdx.y * 128, bn = blockIdx.x * 128;
    int Kw = K >> 1;
    float acc[4][4][4] = {};
    uint4 pa[2], pl[2], pw[2], pwl[2];

    // preload stage 0
    #pragma unroll
    for (int it = 0; it < 2; it++) {
        int idx = it*256 + t, row = idx >> 2, wg = (idx & 3) << 2;
        pa[it] = *(const uint4*)(AHg + (size_t)(bm+row)*Kw + wg);
        pl[it] = *(const uint4*)(ALg + (size_t)(bm+row)*Kw + wg);
        pw[it] = *(const uint4*)(WHg + (size_t)(bn+row)*Kw + wg);
        if (CHAINS == 3) pwl[it] = *(const uint4*)(WLg + (size_t)(bn+row)*Kw + wg);
    }
    #pragma unroll
    for (int it = 0; it < 2; it++) {
        int idx = it*256 + t, row = idx >> 2, wg = (idx & 3) << 2;
        *(uint4*)(AH + row*GW + wg) = pa[it];
        *(uint4*)(AL + row*GW + wg) = pl[it];
        *(uint4*)(WH + row*GW + wg) = pw[it];
        if (CHAINS == 3) *(uint4*)(WL + row*GW + wg) = pwl[it];
    }
    __syncthreads();

    for (int k0 = 0; k0 < K; k0 += 32) {
        int st = (k0 >> 5) & 1;
        bool more = (k0 + 32 < K);
        if (more) {
            int kw = (k0 >> 1) + 16;
            #pragma unroll
            for (int it = 0; it < 2; it++) {
                int idx = it*256 + t, row = idx >> 2, wg = (idx & 3) << 2;
                pa[it] = *(const uint4*)(AHg + (size_t)(bm+row)*Kw + kw + wg);
                pl[it] = *(const uint4*)(ALg + (size_t)(bm+row)*Kw + kw + wg);
                pw[it] = *(const uint4*)(WHg + (size_t)(bn+row)*Kw + kw + wg);
                if (CHAINS == 3) pwl[it] = *(const uint4*)(WLg + (size_t)(bn+row)*Kw + kw + wg);
            }
        }
        const uint32_t* AHs = AH + st*GT;
        const uint32_t* ALs = AL + st*GT;
        const uint32_t* WHs = WH + st*GT;
        const uint32_t* WLs = WL + st*GT;

        #pragma unroll
        for (int g = 0; g < 2; g++) {           // two k16 groups in BK=32
            int wb = g*8 + (lane & 3);
            uint32_t bh[4][2], bl[4][2];
            #pragma unroll
            for (int j = 0; j < 4; j++) {
                int n0 = wn*32 + j*8 + (lane >> 2);
                bh[j][0] = WHs[n0*GW + wb];
                bh[j][1] = WHs[n0*GW + wb + 4];
                if (CHAINS == 3) {
                    bl[j][0] = WLs[n0*GW + wb];
                    bl[j][1] = WLs[n0*GW + wb + 4];
                }
            }
            #pragma unroll
            for (int i = 0; i < 4; i++) {
                int r0 = wm*64 + i*16 + (lane >> 2);
                uint32_t ah[4], al[4];
                ah[0] = AHs[r0*GW + wb];       ah[1] = AHs[(r0+8)*GW + wb];
                ah[2] = AHs[r0*GW + wb + 4];   ah[3] = AHs[(r0+8)*GW + wb + 4];
                al[0] = ALs[r0*GW + wb];       al[1] = ALs[(r0+8)*GW + wb];
                al[2] = ALs[r0*GW + wb + 4];   al[3] = ALs[(r0+8)*GW + wb + 4];
                #pragma unroll
                for (int j = 0; j < 4; j++) {
                    mma16(acc[i][j], ah, bh[j]);
                    mma16(acc[i][j], al, bh[j]);
                    if (CHAINS == 3) mma16(acc[i][j], ah, bl[j]);
                }
            }
        }

        if (more) {
            int nx = (st ^ 1) * GT;
            #pragma unroll
            for (int it = 0; it < 2; it++) {
                int idx = it*256 + t, row = idx >> 2, wg = (idx & 3) << 2;
                *(uint4*)(AH + nx + row*GW + wg) = pa[it];
                *(uint4*)(AL + nx + row*GW + wg) = pl[it];
                *(uint4*)(WH + nx + row*GW + wg) = pw[it];
                if (CHAINS == 3) *(uint4*)(WL + nx + row*GW + wg) = pwl[it];
            }
        }
        __syncthreads();
    }

    float s = 1.0f;
    if (sumptr) s = sumptr[0] / wcount + 1e-8f;
    #pragma unroll
    for (int i = 0; i < 4; i++) {
        int r0 = bm + wm*64 + i*16 + (lane >> 2);
        #pragma unroll
        for (int j = 0; j < 4; j++) {
            int c0 = bn + wn*32 + j*8 + ((lane & 3) << 1);
            float v[4] = {acc[i][j][0]*s, acc[i][j][1]*s, acc[i][j][2]*s, acc[i][j][3]*s};
            if (bias) { v[0] += bias[c0]; v[1] += bias[c0+1]; v[2] += bias[c0]; v[3] += bias[c0+1]; }
            if (EPI == 1) {
                #pragma unroll
                for (int u = 0; u < 4; u++)
                    v[u] = v[u] * 0.5f * (1.0f + erff(v[u] * 0.70710678118654752f));
            }
            if (resid) {
                v[0] += resid[(size_t)r0*N + c0];     v[1] += resid[(size_t)r0*N + c0+1];
                v[2] += resid[(size_t)(r0+8)*N + c0]; v[3] += resid[(size_t)(r0+8)*N + c0+1];
            }
            C[(size_t)r0*N + c0]       = v[0]; C[(size_t)r0*N + c0+1]     = v[1];
            C[(size_t)(r0+8)*N + c0]   = v[2]; C[(size_t)(r0+8)*N + c0+1] = v[3];
        }
    }
}

// ---------------- fused flash attention (fp32) ------------------------------
#define FLASH_SMEM ((3*64*65 + 64*68)*4)   /* 67328 B */

__global__ void __launch_bounds__(256) attn_flash(const float* __restrict__ qkv,
                                                  float* __restrict__ O) {
    extern __shared__ float fs[];
    float (*Qs)[65] = (float(*)[65])fs;
    float (*Ks)[65] = (float(*)[65])(fs + 64*65);
    float (*Ps)[65] = (float(*)[65])(fs + 2*64*65);
    float (*Vs)[68] = (float(*)[68])(fs + 3*64*65);

    int bh = blockIdx.y;
    int b = bh / HEADS, hh = bh % HEADS;
    int m0 = blockIdx.x * 64;
    const float* base = qkv + (size_t)b * SEQ * NQKV;
    const float* Qp = base + hh * DHEAD;
    const float* Kp = base + INNER + hh * DHEAD;
    const float* Vp = base + 2*INNER + hh * DHEAD;
    int t = threadIdx.x;
    int tx = t & 15, ty = t >> 4;

    #pragma unroll
    for (int it = 0; it < 4; it++) {
        int idx = it*256 + t;
        int m = idx >> 4, d = (idx & 15) << 2;
        float4 q4 = *(const float4*)(Qp + (size_t)(m0+m)*NQKV + d);
        Qs[d+0][m] = q4.x; Qs[d+1][m] = q4.y; Qs[d+2][m] = q4.z; Qs[d+3][m] = q4.w;
    }

    float mi[4], li[4], acc[4][4];
    #pragma unroll
    for (int i = 0; i < 4; i++) {
        mi[i] = -1e30f; li[i] = 0.f;
        #pragma unroll
        for (int j = 0; j < 4; j++) acc[i][j] = 0.f;
    }

    for (int k0 = 0; k0 < SEQ; k0 += 64) {
        __syncthreads();
        #pragma unroll
        for (int it = 0; it < 4; it++) {
            int idx = it*256 + t;
            int n = idx >> 4, d = (idx & 15) << 2;
            float4 k4 = *(const float4*)(Kp + (size_t)(k0+n)*NQKV + d);
            Ks[d+0][n] = k4.x; Ks[d+1][n] = k4.y; Ks[d+2][n] = k4.z; Ks[d+3][n] = k4.w;
            float4 v4 = *(const float4*)(Vp + (size_t)(k0+n)*NQKV + d);
            *(float4*)&Vs[n][d] = v4;
        }
        __syncthreads();

        float s[4][4] = {};
        #pragma unroll
        for (int d = 0; d < 64; d++) {
            float ra[4], rk[4];
            #pragma unroll
            for (int i = 0; i < 4; i++) ra[i] = Qs[d][ty*4+i];
            #pragma unroll
            for (int j = 0; j < 4; j++) rk[j] = Ks[d][tx*4+j];
            #pragma unroll
            for (int i = 0; i < 4; i++)
                #pragma unroll
                for (int j = 0; j < 4; j++)
                    s[i][j] += ra[i] * rk[j];
        }

        float p[4][4];
        #pragma unroll
        for (int i = 0; i < 4; i++) {
            float rm = -1e30f;
            #pragma unroll
            for (int j = 0; j < 4; j++) { s[i][j] *= SCALE; rm = fmaxf(rm, s[i][j]); }
            #pragma unroll
            for (int o = 1; o < 16; o <<= 1)
                rm = fmaxf(rm, __shfl_xor_sync(0xffffffffu, rm, o));
            float mn = fmaxf(mi[i], rm);
            float f = __expf(mi[i] - mn);
            mi[i] = mn;
            float sum = 0.f;
            #pragma unroll
            for (int j = 0; j < 4; j++) { p[i][j] = __expf(s[i][j] - mn); sum += p[i][j]; }
            #pragma unroll
            for (int o = 1; o < 16; o <<= 1)
                sum += __shfl_xor_sync(0xffffffffu, sum, o);
            li[i] = li[i]*f + sum;
            #pragma unroll
            for (int j = 0; j < 4; j++) acc[i][j] *= f;
        }

        #pragma unroll
        for (int i = 0; i < 4; i++)
            #pragma unroll
            for (int j = 0; j < 4; j++)
                Ps[tx*4+j][ty*4+i] = p[i][j];
        __syncthreads();

        #pragma unroll
        for (int k = 0; k < 64; k++) {
            float rp[4];
            #pragma unroll
            for (int i = 0; i < 4; i++) rp[i] = Ps[k][ty*4+i];
            float4 rv = *(const float4*)&Vs[k][tx*4];
            float rvv[4] = {rv.x, rv.y, rv.z, rv.w};
            #pragma unroll
            for (int i = 0; i < 4; i++)
                #pragma unroll
                for (int j = 0; j < 4; j++)
                    acc[i][j] += rp[i] * rvv[j];
        }
    }

    #pragma unroll
    for (int i = 0; i < 4; i++) {
        float inv = 1.0f / li[i];
        #pragma unroll
        for (int j = 0; j < 4; j++)
            O[((size_t)b*SEQ + m0 + ty*4+i)*INNER + hh*DHEAD + tx*4+j] = acc[i][j] * inv;
    }
}

// ---------------- host driver -----------------------------------------------
extern "C" void kernel_launch(void* const* d_in, const int* in_sizes, int n_in,
                              void* d_out, int out_size) {
    const float* x    = (const float*)d_in[0];
    const float* ln1g = (const float*)d_in[1];
    const float* ln1b = (const float*)d_in[2];
    const float* Wqkv = (const float*)d_in[3];
    const float* ln2g = (const float*)d_in[4];
    const float* ln2b = (const float*)d_in[5];
    const float* Wo   = (const float*)d_in[6];
    const float* bo   = (const float*)d_in[7];
    const float* f1g  = (const float*)d_in[8];
    const float* f1b  = (const float*)d_in[9];
    const float* W1   = (const float*)d_in[10];
    const float* b1   = (const float*)d_in[11];
    const float* f2g  = (const float*)d_in[12];
    const float* f2b  = (const float*)d_in[13];
    const float* W2   = (const float*)d_in[14];
    const float* b2   = (const float*)d_in[15];
    float* h = (float*)d_out;

    float *qkv, *ob, *mlp, *scal;
    __nv_bfloat16 *ah, *al, *whq, *wlq, *who, *wlo, *wh1, *wl1, *wh2, *wl2;
    cudaGetSymbolAddress((void**)&qkv, g_qkv);
    cudaGetSymbolAddress((void**)&ob,  g_obuf);
    cudaGetSymbolAddress((void**)&mlp, g_mlp);
    cudaGetSymbolAddress((void**)&ah,  g_ah);
    cudaGetSymbolAddress((void**)&al,  g_al);
    cudaGetSymbolAddress((void**)&whq, g_whq);
    cudaGetSymbolAddress((void**)&wlq, g_wlq);
    cudaGetSymbolAddress((void**)&who, g_who);
    cudaGetSymbolAddress((void**)&wlo, g_wlo);
    cudaGetSymbolAddress((void**)&wh1, g_wh1);
    cudaGetSymbolAddress((void**)&wl1, g_wl1);
    cudaGetSymbolAddress((void**)&wh2, g_wh2);
    cudaGetSymbolAddress((void**)&wl2, g_wl2);
    cudaGetSymbolAddress((void**)&scal, g_scal);

    cudaFuncSetAttribute(gemm_bf16<2,0>, cudaFuncAttributeMaxDynamicSharedMemorySize, GSMEM2);
    cudaFuncSetAttribute(gemm_bf16<2,1>, cudaFuncAttributeMaxDynamicSharedMemorySize, GSMEM2);
    cudaFuncSetAttribute(gemm_bf16<3,0>, cudaFuncAttributeMaxDynamicSharedMemorySize, GSMEM3);
    cudaFuncSetAttribute(gemm_bf16<3,1>, cudaFuncAttributeMaxDynamicSharedMemorySize, GSMEM3);
    cudaFuncSetAttribute(attn_flash,     cudaFuncAttributeMaxDynamicSharedMemorySize, FLASH_SMEM);

    cudaMemcpyAsync(h, x, sizeof(float)*(size_t)ROWS*DIMM, cudaMemcpyDeviceToDevice);

    const int nA = NQKV*DIMM, nO = DIMM*INNER, n1 = MLPD*DIMM, n2 = DIMM*MLPD;

    for (int l = 0; l < DEPTH; l++) {
        bool tern = (l < DEPTH - 1);
        if (tern) {
            cudaMemsetAsync(scal, 0, 4*sizeof(float));
            abs_sum4<<<dim3(160,4),256>>>(
                Wqkv + (size_t)l*nA, Wo + (size_t)l*nO, W1 + (size_t)l*n1, W2 + (size_t)l*n2,
                nA, nO, n1, n2, scal);
            quant4<<<dim3(160,4),256>>>(
                Wqkv + (size_t)l*nA, Wo + (size_t)l*nO, W1 + (size_t)l*n1, W2 + (size_t)l*n2,
                whq, who, wh1, wh2, scal, nA, nO, n1, n2);
        } else {
            split4<<<dim3(160,4),256>>>(
                Wqkv + (size_t)l*nA, Wo + (size_t)l*nO, W1 + (size_t)l*n1, W2 + (size_t)l*n2,
                whq, who, wh1, wh2, wlq, wlo, wl1, wl2, nA, nO, n1, n2);
        }

        // attention block
        ln_kernel<<<ROWS,256,DIMM*4>>>(h, ah, al, ln1g + l*DIMM, ln1b + l*DIMM, DIMM);
        if (tern)
            gemm_bf16<2,0><<<dim3(NQKV/128, ROWS/128),256,GSMEM2>>>(
                (uint32_t*)ah, (uint32_t*)al, (uint32_t*)whq, nullptr,
                scal+0, (float)nA, nullptr, nullptr, qkv, ROWS, NQKV, DIMM);
        else
            gemm_bf16<3,0><<<dim3(NQKV/128, ROWS/128),256,GSMEM3>>>(
                (uint32_t*)ah, (uint32_t*)al, (uint32_t*)whq, (uint32_t*)wlq,
                nullptr, 1.0f, nullptr, nullptr, qkv, ROWS, NQKV, DIMM);
        attn_flash<<<dim3(16, BB*HEADS),256,FLASH_SMEM>>>(qkv, ob);
        ln_kernel<<<ROWS,256,INNER*4>>>(ob, ah, al, ln2g + l*INNER, ln2b + l*INNER, INNER);
        if (tern)
            gemm_bf16<2,0><<<dim3(DIMM/128, ROWS/128),256,GSMEM2>>>(
                (uint32_t*)ah, (uint32_t*)al, (uint32_t*)who, nullptr,
                scal+1, (float)nO, bo + l*DIMM, h, h, ROWS, DIMM, INNER);
        else
            gemm_bf16<3,0><<<dim3(DIMM/128, ROWS/128),256,GSMEM3>>>(
                (uint32_t*)ah, (uint32_t*)al, (uint32_t*)who, (uint32_t*)wlo,
                nullptr, 1.0f, bo + l*DIMM, h, h, ROWS, DIMM, INNER);

        // MLP block (GELU fused into FF1 epilogue)
        ln_kernel<<<ROWS,256,DIMM*4>>>(h, ah, al, f1g + l*DIMM, f1b + l*DIMM, DIMM);
        if (tern)
            gemm_bf16<2,1><<<dim3(MLPD/128, ROWS/128),256,GSMEM2>>>(
                (uint32_t*)ah, (uint32_t*)al, (uint32_t*)wh1, nullptr,
                scal+2, (float)n1, b1 + l*MLPD, nullptr, mlp, ROWS, MLPD, DIMM);
        else
            gemm_bf16<3,1><<<dim3(MLPD/128, ROWS/128),256,GSMEM3>>>(
                (uint32_t*)ah, (uint32_t*)al, (uint32_t*)wh1, (uint32_t*)wl1,
                nullptr, 1.0f, b1 + l*MLPD, nullptr, mlp, ROWS, MLPD, DIMM);
        ln_kernel<<<ROWS,256,MLPD*4>>>(mlp, ah, al, f2g + l*MLPD, f2b + l*MLPD, MLPD);
        if (tern)
            gemm_bf16<2,0><<<dim3(DIMM/128, ROWS/128),256,GSMEM2>>>(
                (uint32_t*)ah, (uint32_t*)al, (uint32_t*)wh2, nullptr,
                scal+3, (float)n2, b2 + l*DIMM, h, h, ROWS, DIMM, MLPD);
        else
            gemm_bf16<3,0><<<dim3(DIMM/128, ROWS/128),256,GSMEM3>>>(
                (uint32_t*)ah, (uint32_t*)al, (uint32_t*)wh2, (uint32_t*)wl2,
                nullptr, 1.0f, b2 + l*DIMM, h, h, ROWS, DIMM, MLPD);
    }
}

// round 7
// speedup vs baseline: 2.5340x; 1.0921x over previous
#include <cuda_runtime.h>
#include <cuda_bf16.h>
#include <math.h>
#include <stdint.h>

#define DIMM  768
#define HEADS 12
#define DHEAD 64
#define INNER 768
#define MLPD  3072
#define BB    8
#define SEQ   1024
#define ROWS  (BB*SEQ)   /* 8192 */
#define DEPTH 6
#define SCALE 0.125f     /* 64^-0.5 */
#define NQKV  (3*INNER)

// ---------------- scratch (device globals: no allocations allowed) ----------
__device__ __align__(16) float g_qkv[(size_t)ROWS*NQKV];
__device__ __align__(16) float g_obuf[ROWS*INNER];
__device__ __align__(16) float g_mlp[(size_t)ROWS*MLPD];
__device__ __align__(16) __nv_bfloat16 g_ah[(size_t)ROWS*MLPD];   // LN out hi
__device__ __align__(16) __nv_bfloat16 g_al[(size_t)ROWS*MLPD];   // LN out lo
__device__ __align__(16) __nv_bfloat16 g_whq[NQKV*DIMM];
__device__ __align__(16) __nv_bfloat16 g_wlq[NQKV*DIMM];
__device__ __align__(16) __nv_bfloat16 g_who[DIMM*INNER];
__device__ __align__(16) __nv_bfloat16 g_wlo[DIMM*INNER];
__device__ __align__(16) __nv_bfloat16 g_wh1[MLPD*DIMM];
__device__ __align__(16) __nv_bfloat16 g_wl1[MLPD*DIMM];
__device__ __align__(16) __nv_bfloat16 g_wh2[DIMM*MLPD];
__device__ __align__(16) __nv_bfloat16 g_wl2[DIMM*MLPD];
__device__ float g_scal[4];

// ---------------- async-copy / ldmatrix helpers -----------------------------
__device__ __forceinline__ void cp_async16(void* smem, const void* gmem) {
    uint32_t s = (uint32_t)__cvta_generic_to_shared(smem);
    asm volatile("cp.async.cg.shared.global [%0], [%1], 16;\n" :: "r"(s), "l"(gmem));
}
__device__ __forceinline__ void ldsm4(uint32_t& a0, uint32_t& a1, uint32_t& a2,
                                      uint32_t& a3, const uint32_t* p) {
    uint32_t s = (uint32_t)__cvta_generic_to_shared(p);
    asm volatile("ldmatrix.sync.aligned.m8n8.x4.shared.b16 {%0,%1,%2,%3}, [%4];\n"
                 : "=r"(a0), "=r"(a1), "=r"(a2), "=r"(a3) : "r"(s));
}

// ---------------- batched abs-sum / quant / split ---------------------------
__global__ void abs_sum4(const float* __restrict__ w0, const float* __restrict__ w1,
                         const float* __restrict__ w2, const float* __restrict__ w3,
                         int n0, int n1, int n2, int n3, float* out) {
    int z = blockIdx.y;
    const float* w = z==0?w0 : z==1?w1 : z==2?w2 : w3;
    int n = z==0?n0 : z==1?n1 : z==2?n2 : n3;
    float s = 0.f;
    for (int i = blockIdx.x*blockDim.x + threadIdx.x; i < n; i += gridDim.x*blockDim.x)
        s += fabsf(w[i]);
    #pragma unroll
    for (int o = 16; o; o >>= 1) s += __shfl_down_sync(0xffffffffu, s, o);
    __shared__ float sh[8];
    if ((threadIdx.x & 31) == 0) sh[threadIdx.x >> 5] = s;
    __syncthreads();
    if (threadIdx.x < 8) {
        float v = sh[threadIdx.x];
        #pragma unroll
        for (int o = 4; o; o >>= 1) v += __shfl_down_sync(0xffu, v, o);
        if (threadIdx.x == 0) atomicAdd(out + z, v);
    }
}

// ternary {-1,0,+1} to bf16 (exact); scale applied in GEMM epilogue
__global__ void quant4(const float* __restrict__ w0, const float* __restrict__ w1,
                       const float* __restrict__ w2, const float* __restrict__ w3,
                       __nv_bfloat16* __restrict__ q0, __nv_bfloat16* __restrict__ q1,
                       __nv_bfloat16* __restrict__ q2, __nv_bfloat16* __restrict__ q3,
                       const float* __restrict__ sums, int n0, int n1, int n2, int n3) {
    int z = blockIdx.y;
    const float* w = z==0?w0 : z==1?w1 : z==2?w2 : w3;
    __nv_bfloat16* q = z==0?q0 : z==1?q1 : z==2?q2 : q3;
    int n = z==0?n0 : z==1?n1 : z==2?n2 : n3;
    float s = sums[z] / (float)n + 1e-8f;
    float inv = 1.0f / s;
    for (int i = blockIdx.x*blockDim.x + threadIdx.x; i < n; i += gridDim.x*blockDim.x) {
        float t = rintf(w[i] * inv);           // half-to-even, matches jnp.round
        t = fminf(1.0f, fmaxf(-1.0f, t));
        q[i] = __float2bfloat16_rn(t);
    }
}

// dense fp32 -> bf16 hi/lo split (layer DEPTH-1)
__global__ void split4(const float* __restrict__ w0, const float* __restrict__ w1,
                       const float* __restrict__ w2, const float* __restrict__ w3,
                       __nv_bfloat16* __restrict__ h0, __nv_bfloat16* __restrict__ h1,
                       __nv_bfloat16* __restrict__ h2, __nv_bfloat16* __restrict__ h3,
                       __nv_bfloat16* __restrict__ l0, __nv_bfloat16* __restrict__ l1,
                       __nv_bfloat16* __restrict__ l2, __nv_bfloat16* __restrict__ l3,
                       int n0, int n1, int n2, int n3) {
    int z = blockIdx.y;
    const float* w = z==0?w0 : z==1?w1 : z==2?w2 : w3;
    __nv_bfloat16* hh = z==0?h0 : z==1?h1 : z==2?h2 : h3;
    __nv_bfloat16* ll = z==0?l0 : z==1?l1 : z==2?l2 : l3;
    int n = z==0?n0 : z==1?n1 : z==2?n2 : n3;
    for (int i = blockIdx.x*blockDim.x + threadIdx.x; i < n; i += gridDim.x*blockDim.x) {
        float v = w[i];
        __nv_bfloat16 hi = __float2bfloat16_rn(v);
        hh[i] = hi;
        ll[i] = __float2bfloat16_rn(v - __bfloat162float(hi));
    }
}

// ---------------- layernorm -> split bf16 ------------------------------------
__device__ __forceinline__ float blockReduceSum(float v) {
    __shared__ float sh[33];
    __syncthreads();
    int lane = threadIdx.x & 31, wid = threadIdx.x >> 5;
    #pragma unroll
    for (int o = 16; o; o >>= 1) v += __shfl_down_sync(0xffffffffu, v, o);
    if (!lane) sh[wid] = v;
    __syncthreads();
    if (threadIdx.x < 8) {
        float t = sh[threadIdx.x];
        #pragma unroll
        for (int o = 4; o; o >>= 1) t += __shfl_down_sync(0xffu, t, o);
        if (!threadIdx.x) sh[32] = t;
    }
    __syncthreads();
    return sh[32];
}

__global__ void __launch_bounds__(256) ln_kernel(const float* __restrict__ x,
                                                 __nv_bfloat16* __restrict__ yh,
                                                 __nv_bfloat16* __restrict__ yl,
                                                 const float* __restrict__ g,
                                                 const float* __restrict__ b,
                                                 int width) {
    extern __shared__ float row[];
    const float* xr = x + (size_t)blockIdx.x * width;
    float s = 0.f;
    for (int i = threadIdx.x; i < width; i += blockDim.x) { float v = xr[i]; row[i] = v; s += v; }
    float m = blockReduceSum(s) / (float)width;
    float v2 = 0.f;
    for (int i = threadIdx.x; i < width; i += blockDim.x) { float d = row[i] - m; v2 += d*d; }
    float var = blockReduceSum(v2) / (float)width;
    float r = rsqrtf(var + 1e-5f);
    __nv_bfloat16* yhr = yh + (size_t)blockIdx.x * width;
    __nv_bfloat16* ylr = yl + (size_t)blockIdx.x * width;
    for (int i = threadIdx.x; i < width; i += blockDim.x) {
        float v = (row[i] - m) * r * g[i] + b[i];
        __nv_bfloat16 hi = __float2bfloat16_rn(v);
        yhr[i] = hi;
        ylr[i] = __float2bfloat16_rn(v - __bfloat162float(hi));
    }
}

// ---------------- bf16 tensor-core GEMM (cp.async 2-stage + ldmatrix) -------
// C = s*(A @ W^T) + bias [+gelu] [+resid],  A = Ah + Al (bf16 split, exact LN out)
// CHAINS==2: W exact in bf16 (ternary):  Ah*W + Al*W
// CHAINS==3: W split hi/lo:              Ah*Wh + Al*Wh + Ah*Wl
__device__ __forceinline__ void mma16(float c[4], const uint32_t a[4], const uint32_t b[2]) {
    asm volatile(
        "mma.sync.aligned.m16n8k16.row.col.f32.bf16.bf16.f32 "
        "{%0,%1,%2,%3}, {%4,%5,%6,%7}, {%8,%9}, {%0,%1,%2,%3};\n"
        : "+f"(c[0]), "+f"(c[1]), "+f"(c[2]), "+f"(c[3])
        : "r"(a[0]), "r"(a[1]), "r"(a[2]), "r"(a[3]), "r"(b[0]), "r"(b[1]));
}

#define GW 20            /* words per 32-elem K-slice row (16 + 4 pad; 80B = 16B-aligned) */
#define GT (128*GW)      /* words per array per stage */
#define GSMEM2 (3*2*GT*4)   /* 61440 B */
#define GSMEM3 (4*2*GT*4)   /* 81920 B */

template<int CHAINS, int EPI>
__global__ void __launch_bounds__(256,2) gemm_bf16(
    const uint32_t* __restrict__ AHg, const uint32_t* __restrict__ ALg,
    const uint32_t* __restrict__ WHg, const uint32_t* __restrict__ WLg,
    const float* __restrict__ sumptr, float wcount,
    const float* __restrict__ bias, const float* __restrict__ resid,
    float* __restrict__ C, int M, int N, int K)
{
    extern __shared__ uint32_t smw[];
    uint32_t* AH = smw;
    uint32_t* AL = smw + 2*GT;
    uint32_t* WH = smw + 4*GT;
    uint32_t* WL = smw + 6*GT;      // CHAINS==3 only (smem sized accordingly)
    int t = threadIdx.x, lane = t & 31, wid = t >> 5;
    int wm = wid >> 2, wn = wid & 3;
    int bm = blockIdx.y * 128, bn = blockIdx.x * 128;
    int Kw = K >> 1;
    float acc[4][4][4] = {};

    int crow = t >> 2, cwg = (t & 3) << 2;   // copy pattern: 4 thr/row, 16B each

    // prologue: fill stage 0
    #pragma unroll
    for (int it = 0; it < 2; it++) {
        int row = it*64 + crow;
        cp_async16(AH + row*GW + cwg, AHg + (size_t)(bm+row)*Kw + cwg);
        cp_async16(AL + row*GW + cwg, ALg + (size_t)(bm+row)*Kw + cwg);
        cp_async16(WH + row*GW + cwg, WHg + (size_t)(bn+row)*Kw + cwg);
        if (CHAINS == 3) cp_async16(WL + row*GW + cwg, WLg + (size_t)(bn+row)*Kw + cwg);
    }
    asm volatile("cp.async.commit_group;\n");

    // ldmatrix lane mapping (per m16 tile): sub-matrix 0..3
    int lsub = lane >> 3, lrow = lane & 7;
    int lmrow = (lsub & 1) * 8 + lrow;       // row within m16 tile
    int lkoff = (lsub >> 1) * 4;             // word offset within k16 (0 or 4)

    for (int k0 = 0; k0 < K; k0 += 32) {
        int st = (k0 >> 5) & 1;
        bool more = (k0 + 32 < K);
        if (more) {
            int nx = (st ^ 1) * GT;
            int kw = (k0 >> 1) + 16;
            #pragma unroll
            for (int it = 0; it < 2; it++) {
                int row = it*64 + crow;
                cp_async16(AH + nx + row*GW + cwg, AHg + (size_t)(bm+row)*Kw + kw + cwg);
                cp_async16(AL + nx + row*GW + cwg, ALg + (size_t)(bm+row)*Kw + kw + cwg);
                cp_async16(WH + nx + row*GW + cwg, WHg + (size_t)(bn+row)*Kw + kw + cwg);
                if (CHAINS == 3) cp_async16(WL + nx + row*GW + cwg, WLg + (size_t)(bn+row)*Kw + kw + cwg);
            }
            asm volatile("cp.async.commit_group;\n");
            asm volatile("cp.async.wait_group 1;\n");
        } else {
            asm volatile("cp.async.wait_group 0;\n");
        }
        __syncthreads();

        const uint32_t* AHs = AH + st*GT;
        const uint32_t* ALs = AL + st*GT;
        const uint32_t* WHs = WH + st*GT;
        const uint32_t* WLs = WL + st*GT;

        #pragma unroll
        for (int g = 0; g < 2; g++) {           // two k16 groups in BK=32
            int wb = g*8 + (lane & 3);
            uint32_t bh[4][2], bl[4][2];
            #pragma unroll
            for (int j = 0; j < 4; j++) {
                int n0 = wn*32 + j*8 + (lane >> 2);
                bh[j][0] = WHs[n0*GW + wb];
                bh[j][1] = WHs[n0*GW + wb + 4];
                if (CHAINS == 3) {
                    bl[j][0] = WLs[n0*GW + wb];
                    bl[j][1] = WLs[n0*GW + wb + 4];
                }
            }
            #pragma unroll
            for (int i = 0; i < 4; i++) {
                int mr = wm*64 + i*16 + lmrow;
                int kc = g*8 + lkoff;
                uint32_t ah[4], al[4];
                ldsm4(ah[0], ah[1], ah[2], ah[3], AHs + mr*GW + kc);
                ldsm4(al[0], al[1], al[2], al[3], ALs + mr*GW + kc);
                #pragma unroll
                for (int j = 0; j < 4; j++) {
                    mma16(acc[i][j], ah, bh[j]);
                    mma16(acc[i][j], al, bh[j]);
                    if (CHAINS == 3) mma16(acc[i][j], ah, bl[j]);
                }
            }
        }
        __syncthreads();
    }

    float s = 1.0f;
    if (sumptr) s = sumptr[0] / wcount + 1e-8f;
    #pragma unroll
    for (int i = 0; i < 4; i++) {
        int r0 = bm + wm*64 + i*16 + (lane >> 2);
        #pragma unroll
        for (int j = 0; j < 4; j++) {
            int c0 = bn + wn*32 + j*8 + ((lane & 3) << 1);
            float v[4] = {acc[i][j][0]*s, acc[i][j][1]*s, acc[i][j][2]*s, acc[i][j][3]*s};
            if (bias) { v[0] += bias[c0]; v[1] += bias[c0+1]; v[2] += bias[c0]; v[3] += bias[c0+1]; }
            if (EPI == 1) {
                #pragma unroll
                for (int u = 0; u < 4; u++)
                    v[u] = v[u] * 0.5f * (1.0f + erff(v[u] * 0.70710678118654752f));
            }
            if (resid) {
                v[0] += resid[(size_t)r0*N + c0];     v[1] += resid[(size_t)r0*N + c0+1];
                v[2] += resid[(size_t)(r0+8)*N + c0]; v[3] += resid[(size_t)(r0+8)*N + c0+1];
            }
            C[(size_t)r0*N + c0]       = v[0]; C[(size_t)r0*N + c0+1]     = v[1];
            C[(size_t)(r0+8)*N + c0]   = v[2]; C[(size_t)(r0+8)*N + c0+1] = v[3];
        }
    }
}

// ---------------- fused flash attention (fp32) ------------------------------
#define FLASH_SMEM ((3*64*65 + 64*68)*4)   /* 67328 B */

__global__ void __launch_bounds__(256) attn_flash(const float* __restrict__ qkv,
                                                  float* __restrict__ O) {
    extern __shared__ float fs[];
    float (*Qs)[65] = (float(*)[65])fs;
    float (*Ks)[65] = (float(*)[65])(fs + 64*65);
    float (*Ps)[65] = (float(*)[65])(fs + 2*64*65);
    float (*Vs)[68] = (float(*)[68])(fs + 3*64*65);

    int bh = blockIdx.y;
    int b = bh / HEADS, hh = bh % HEADS;
    int m0 = blockIdx.x * 64;
    const float* base = qkv + (size_t)b * SEQ * NQKV;
    const float* Qp = base + hh * DHEAD;
    const float* Kp = base + INNER + hh * DHEAD;
    const float* Vp = base + 2*INNER + hh * DHEAD;
    int t = threadIdx.x;
    int tx = t & 15, ty = t >> 4;

    #pragma unroll
    for (int it = 0; it < 4; it++) {
        int idx = it*256 + t;
        int m = idx >> 4, d = (idx & 15) << 2;
        float4 q4 = *(const float4*)(Qp + (size_t)(m0+m)*NQKV + d);
        Qs[d+0][m] = q4.x; Qs[d+1][m] = q4.y; Qs[d+2][m] = q4.z; Qs[d+3][m] = q4.w;
    }

    float mi[4], li[4], acc[4][4];
    #pragma unroll
    for (int i = 0; i < 4; i++) {
        mi[i] = -1e30f; li[i] = 0.f;
        #pragma unroll
        for (int j = 0; j < 4; j++) acc[i][j] = 0.f;
    }

    for (int k0 = 0; k0 < SEQ; k0 += 64) {
        __syncthreads();
        #pragma unroll
        for (int it = 0; it < 4; it++) {
            int idx = it*256 + t;
            int n = idx >> 4, d = (idx & 15) << 2;
            float4 k4 = *(const float4*)(Kp + (size_t)(k0+n)*NQKV + d);
            Ks[d+0][n] = k4.x; Ks[d+1][n] = k4.y; Ks[d+2][n] = k4.z; Ks[d+3][n] = k4.w;
            float4 v4 = *(const float4*)(Vp + (size_t)(k0+n)*NQKV + d);
            *(float4*)&Vs[n][d] = v4;
        }
        __syncthreads();

        float s[4][4] = {};
        #pragma unroll
        for (int d = 0; d < 64; d++) {
            float ra[4], rk[4];
            #pragma unroll
            for (int i = 0; i < 4; i++) ra[i] = Qs[d][ty*4+i];
            #pragma unroll
            for (int j = 0; j < 4; j++) rk[j] = Ks[d][tx*4+j];
            #pragma unroll
            for (int i = 0; i < 4; i++)
                #pragma unroll
                for (int j = 0; j < 4; j++)
                    s[i][j] += ra[i] * rk[j];
        }

        float p[4][4];
        #pragma unroll
        for (int i = 0; i < 4; i++) {
            float rm = -1e30f;
            #pragma unroll
            for (int j = 0; j < 4; j++) { s[i][j] *= SCALE; rm = fmaxf(rm, s[i][j]); }
            #pragma unroll
            for (int o = 1; o < 16; o <<= 1)
                rm = fmaxf(rm, __shfl_xor_sync(0xffffffffu, rm, o));
            float mn = fmaxf(mi[i], rm);
            float f = __expf(mi[i] - mn);
            mi[i] = mn;
            float sum = 0.f;
            #pragma unroll
            for (int j = 0; j < 4; j++) { p[i][j] = __expf(s[i][j] - mn); sum += p[i][j]; }
            #pragma unroll
            for (int o = 1; o < 16; o <<= 1)
                sum += __shfl_xor_sync(0xffffffffu, sum, o);
            li[i] = li[i]*f + sum;
            #pragma unroll
            for (int j = 0; j < 4; j++) acc[i][j] *= f;
        }

        #pragma unroll
        for (int i = 0; i < 4; i++)
            #pragma unroll
            for (int j = 0; j < 4; j++)
                Ps[tx*4+j][ty*4+i] = p[i][j];
        __syncthreads();

        #pragma unroll
        for (int k = 0; k < 64; k++) {
            float rp[4];
            #pragma unroll
            for (int i = 0; i < 4; i++) rp[i] = Ps[k][ty*4+i];
            float4 rv = *(const float4*)&Vs[k][tx*4];
            float rvv[4] = {rv.x, rv.y, rv.z, rv.w};
            #pragma unroll
            for (int i = 0; i < 4; i++)
                #pragma unroll
                for (int j = 0; j < 4; j++)
                    acc[i][j] += rp[i] * rvv[j];
        }
    }

    #pragma unroll
    for (int i = 0; i < 4; i++) {
        float inv = 1.0f / li[i];
        #pragma unroll
        for (int j = 0; j < 4; j++)
            O[((size_t)b*SEQ + m0 + ty*4+i)*INNER + hh*DHEAD + tx*4+j] = acc[i][j] * inv;
    }
}

// ---------------- host driver -----------------------------------------------
extern "C" void kernel_launch(void* const* d_in, const int* in_sizes, int n_in,
                              void* d_out, int out_size) {
    const float* x    = (const float*)d_in[0];
    const float* ln1g = (const float*)d_in[1];
    const float* ln1b = (const float*)d_in[2];
    const float* Wqkv = (const float*)d_in[3];
    const float* ln2g = (const float*)d_in[4];
    const float* ln2b = (const float*)d_in[5];
    const float* Wo   = (const float*)d_in[6];
    const float* bo   = (const float*)d_in[7];
    const float* f1g  = (const float*)d_in[8];
    const float* f1b  = (const float*)d_in[9];
    const float* W1   = (const float*)d_in[10];
    const float* b1   = (const float*)d_in[11];
    const float* f2g  = (const float*)d_in[12];
    const float* f2b  = (const float*)d_in[13];
    const float* W2   = (const float*)d_in[14];
    const float* b2   = (const float*)d_in[15];
    float* h = (float*)d_out;

    float *qkv, *ob, *mlp, *scal;
    __nv_bfloat16 *ah, *al, *whq, *wlq, *who, *wlo, *wh1, *wl1, *wh2, *wl2;
    cudaGetSymbolAddress((void**)&qkv, g_qkv);
    cudaGetSymbolAddress((void**)&ob,  g_obuf);
    cudaGetSymbolAddress((void**)&mlp, g_mlp);
    cudaGetSymbolAddress((void**)&ah,  g_ah);
    cudaGetSymbolAddress((void**)&al,  g_al);
    cudaGetSymbolAddress((void**)&whq, g_whq);
    cudaGetSymbolAddress((void**)&wlq, g_wlq);
    cudaGetSymbolAddress((void**)&who, g_who);
    cudaGetSymbolAddress((void**)&wlo, g_wlo);
    cudaGetSymbolAddress((void**)&wh1, g_wh1);
    cudaGetSymbolAddress((void**)&wl1, g_wl1);
    cudaGetSymbolAddress((void**)&wh2, g_wh2);
    cudaGetSymbolAddress((void**)&wl2, g_wl2);
    cudaGetSymbolAddress((void**)&scal, g_scal);

    cudaFuncSetAttribute(gemm_bf16<2,0>, cudaFuncAttributeMaxDynamicSharedMemorySize, GSMEM2);
    cudaFuncSetAttribute(gemm_bf16<2,1>, cudaFuncAttributeMaxDynamicSharedMemorySize, GSMEM2);
    cudaFuncSetAttribute(gemm_bf16<3,0>, cudaFuncAttributeMaxDynamicSharedMemorySize, GSMEM3);
    cudaFuncSetAttribute(gemm_bf16<3,1>, cudaFuncAttributeMaxDynamicSharedMemorySize, GSMEM3);
    cudaFuncSetAttribute(attn_flash,     cudaFuncAttributeMaxDynamicSharedMemorySize, FLASH_SMEM);

    cudaMemcpyAsync(h, x, sizeof(float)*(size_t)ROWS*DIMM, cudaMemcpyDeviceToDevice);

    const int nA = NQKV*DIMM, nO = DIMM*INNER, n1 = MLPD*DIMM, n2 = DIMM*MLPD;

    for (int l = 0; l < DEPTH; l++) {
        bool tern = (l < DEPTH - 1);
        if (tern) {
            cudaMemsetAsync(scal, 0, 4*sizeof(float));
            abs_sum4<<<dim3(160,4),256>>>(
                Wqkv + (size_t)l*nA, Wo + (size_t)l*nO, W1 + (size_t)l*n1, W2 + (size_t)l*n2,
                nA, nO, n1, n2, scal);
            quant4<<<dim3(160,4),256>>>(
                Wqkv + (size_t)l*nA, Wo + (size_t)l*nO, W1 + (size_t)l*n1, W2 + (size_t)l*n2,
                whq, who, wh1, wh2, scal, nA, nO, n1, n2);
        } else {
            split4<<<dim3(160,4),256>>>(
                Wqkv + (size_t)l*nA, Wo + (size_t)l*nO, W1 + (size_t)l*n1, W2 + (size_t)l*n2,
                whq, who, wh1, wh2, wlq, wlo, wl1, wl2, nA, nO, n1, n2);
        }

        // attention block
        ln_kernel<<<ROWS,256,DIMM*4>>>(h, ah, al, ln1g + l*DIMM, ln1b + l*DIMM, DIMM);
        if (tern)
            gemm_bf16<2,0><<<dim3(NQKV/128, ROWS/128),256,GSMEM2>>>(
                (uint32_t*)ah, (uint32_t*)al, (uint32_t*)whq, nullptr,
                scal+0, (float)nA, nullptr, nullptr, qkv, ROWS, NQKV, DIMM);
        else
            gemm_bf16<3,0><<<dim3(NQKV/128, ROWS/128),256,GSMEM3>>>(
                (uint32_t*)ah, (uint32_t*)al, (uint32_t*)whq, (uint32_t*)wlq,
                nullptr, 1.0f, nullptr, nullptr, qkv, ROWS, NQKV, DIMM);
        attn_flash<<<dim3(16, BB*HEADS),256,FLASH_SMEM>>>(qkv, ob);
        ln_kernel<<<ROWS,256,INNER*4>>>(ob, ah, al, ln2g + l*INNER, ln2b + l*INNER, INNER);
        if (tern)
            gemm_bf16<2,0><<<dim3(DIMM/128, ROWS/128),256,GSMEM2>>>(
                (uint32_t*)ah, (uint32_t*)al, (uint32_t*)who, nullptr,
                scal+1, (float)nO, bo + l*DIMM, h, h, ROWS, DIMM, INNER);
        else
            gemm_bf16<3,0><<<dim3(DIMM/128, ROWS/128),256,GSMEM3>>>(
                (uint32_t*)ah, (uint32_t*)al, (uint32_t*)who, (uint32_t*)wlo,
                nullptr, 1.0f, bo + l*DIMM, h, h, ROWS, DIMM, INNER);

        // MLP block (GELU fused into FF1 epilogue)
        ln_kernel<<<ROWS,256,DIMM*4>>>(h, ah, al, f1g + l*DIMM, f1b + l*DIMM, DIMM);
        if (tern)
            gemm_bf16<2,1><<<dim3(MLPD/128, ROWS/128),256,GSMEM2>>>(
                (uint32_t*)ah, (uint32_t*)al, (uint32_t*)wh1, nullptr,
                scal+2, (float)n1, b1 + l*MLPD, nullptr, mlp, ROWS, MLPD, DIMM);
        else
            gemm_bf16<3,1><<<dim3(MLPD/128, ROWS/128),256,GSMEM3>>>(
                (uint32_t*)ah, (uint32_t*)al, (uint32_t*)wh1, (uint32_t*)wl1,
                nullptr, 1.0f, b1 + l*MLPD, nullptr, mlp, ROWS, MLPD, DIMM);
        ln_kernel<<<ROWS,256,MLPD*4>>>(mlp, ah, al, f2g + l*MLPD, f2b + l*MLPD, MLPD);
        if (tern)
            gemm_bf16<2,0><<<dim3(DIMM/128, ROWS/128),256,GSMEM2>>>(
                (uint32_t*)ah, (uint32_t*)al, (uint32_t*)wh2, nullptr,
                scal+3, (float)n2, b2 + l*DIMM, h, h, ROWS, DIMM, MLPD);
        else
            gemm_bf16<3,0><<<dim3(DIMM/128, ROWS/128),256,GSMEM3>>>(
                (uint32_t*)ah, (uint32_t*)al, (uint32_t*)wh2, (uint32_t*)wl2,
                nullptr, 1.0f, b2 + l*DIMM, h, h, ROWS, DIMM, MLPD);
    }
}

// round 8
// speedup vs baseline: 3.2575x; 1.2855x over previous
#include <cuda_runtime.h>
#include <cuda_bf16.h>
#include <math.h>
#include <stdint.h>

#define DIMM  768
#define HEADS 12
#define DHEAD 64
#define INNER 768
#define MLPD  3072
#define BB    8
#define SEQ   1024
#define ROWS  (BB*SEQ)   /* 8192 */
#define DEPTH 6
#define SCALE 0.125f     /* 64^-0.5 */
#define NQKV  (3*INNER)

// ---------------- scratch (device globals: no allocations allowed) ----------
__device__ __align__(16) float g_qkv[(size_t)ROWS*NQKV];
__device__ __align__(16) float g_obuf[ROWS*INNER];
__device__ __align__(16) float g_mlp[(size_t)ROWS*MLPD];
__device__ __align__(16) __nv_bfloat16 g_ah[(size_t)ROWS*MLPD];   // LN out hi
__device__ __align__(16) __nv_bfloat16 g_al[(size_t)ROWS*MLPD];   // LN out lo
__device__ __align__(16) __nv_bfloat16 g_whq[NQKV*DIMM];
__device__ __align__(16) __nv_bfloat16 g_wlq[NQKV*DIMM];
__device__ __align__(16) __nv_bfloat16 g_who[DIMM*INNER];
__device__ __align__(16) __nv_bfloat16 g_wlo[DIMM*INNER];
__device__ __align__(16) __nv_bfloat16 g_wh1[MLPD*DIMM];
__device__ __align__(16) __nv_bfloat16 g_wl1[MLPD*DIMM];
__device__ __align__(16) __nv_bfloat16 g_wh2[DIMM*MLPD];
__device__ __align__(16) __nv_bfloat16 g_wl2[DIMM*MLPD];
__device__ float g_scal[4];

// ---------------- asm helpers ------------------------------------------------
__device__ __forceinline__ void cp_async16(void* smem, const void* gmem) {
    uint32_t s = (uint32_t)__cvta_generic_to_shared(smem);
    asm volatile("cp.async.cg.shared.global [%0], [%1], 16;\n" :: "r"(s), "l"(gmem));
}
__device__ __forceinline__ void ldsm4(uint32_t& a0, uint32_t& a1, uint32_t& a2,
                                      uint32_t& a3, const uint32_t* p) {
    uint32_t s = (uint32_t)__cvta_generic_to_shared(p);
    asm volatile("ldmatrix.sync.aligned.m8n8.x4.shared.b16 {%0,%1,%2,%3}, [%4];\n"
                 : "=r"(a0), "=r"(a1), "=r"(a2), "=r"(a3) : "r"(s));
}
__device__ __forceinline__ void ldsm2(uint32_t& a0, uint32_t& a1, const uint32_t* p) {
    uint32_t s = (uint32_t)__cvta_generic_to_shared(p);
    asm volatile("ldmatrix.sync.aligned.m8n8.x2.shared.b16 {%0,%1}, [%2];\n"
                 : "=r"(a0), "=r"(a1) : "r"(s));
}
__device__ __forceinline__ void ldsm2t(uint32_t& a0, uint32_t& a1, const uint32_t* p) {
    uint32_t s = (uint32_t)__cvta_generic_to_shared(p);
    asm volatile("ldmatrix.sync.aligned.m8n8.x2.trans.shared.b16 {%0,%1}, [%2];\n"
                 : "=r"(a0), "=r"(a1) : "r"(s));
}
__device__ __forceinline__ void mma16(float c[4], const uint32_t a[4], const uint32_t b[2]) {
    asm volatile(
        "mma.sync.aligned.m16n8k16.row.col.f32.bf16.bf16.f32 "
        "{%0,%1,%2,%3}, {%4,%5,%6,%7}, {%8,%9}, {%0,%1,%2,%3};\n"
        : "+f"(c[0]), "+f"(c[1]), "+f"(c[2]), "+f"(c[3])
        : "r"(a[0]), "r"(a[1]), "r"(a[2]), "r"(a[3]), "r"(b[0]), "r"(b[1]));
}
// fp32 pair -> bf16x2 hi word + bf16x2 lo (residual) word
__device__ __forceinline__ void split2(float a, float b, uint32_t& hi, uint32_t& lo) {
    __nv_bfloat162 h = __floats2bfloat162_rn(a, b);
    hi = *reinterpret_cast<uint32_t*>(&h);
    float la = a - __bfloat162float(h.x);
    float lb = b - __bfloat162float(h.y);
    __nv_bfloat162 l = __floats2bfloat162_rn(la, lb);
    lo = *reinterpret_cast<uint32_t*>(&l);
}

// ---------------- batched abs-sum / quant / split ---------------------------
__global__ void abs_sum4(const float* __restrict__ w0, const float* __restrict__ w1,
                         const float* __restrict__ w2, const float* __restrict__ w3,
                         int n0, int n1, int n2, int n3, float* out) {
    int z = blockIdx.y;
    const float* w = z==0?w0 : z==1?w1 : z==2?w2 : w3;
    int n = z==0?n0 : z==1?n1 : z==2?n2 : n3;
    float s = 0.f;
    for (int i = blockIdx.x*blockDim.x + threadIdx.x; i < n; i += gridDim.x*blockDim.x)
        s += fabsf(w[i]);
    #pragma unroll
    for (int o = 16; o; o >>= 1) s += __shfl_down_sync(0xffffffffu, s, o);
    __shared__ float sh[8];
    if ((threadIdx.x & 31) == 0) sh[threadIdx.x >> 5] = s;
    __syncthreads();
    if (threadIdx.x < 8) {
        float v = sh[threadIdx.x];
        #pragma unroll
        for (int o = 4; o; o >>= 1) v += __shfl_down_sync(0xffu, v, o);
        if (threadIdx.x == 0) atomicAdd(out + z, v);
    }
}

__global__ void quant4(const float* __restrict__ w0, const float* __restrict__ w1,
                       const float* __restrict__ w2, const float* __restrict__ w3,
                       __nv_bfloat16* __restrict__ q0, __nv_bfloat16* __restrict__ q1,
                       __nv_bfloat16* __restrict__ q2, __nv_bfloat16* __restrict__ q3,
                       const float* __restrict__ sums, int n0, int n1, int n2, int n3) {
    int z = blockIdx.y;
    const float* w = z==0?w0 : z==1?w1 : z==2?w2 : w3;
    __nv_bfloat16* q = z==0?q0 : z==1?q1 : z==2?q2 : q3;
    int n = z==0?n0 : z==1?n1 : z==2?n2 : n3;
    float s = sums[z] / (float)n + 1e-8f;
    float inv = 1.0f / s;
    for (int i = blockIdx.x*blockDim.x + threadIdx.x; i < n; i += gridDim.x*blockDim.x) {
        float t = rintf(w[i] * inv);           // half-to-even, matches jnp.round
        t = fminf(1.0f, fmaxf(-1.0f, t));
        q[i] = __float2bfloat16_rn(t);
    }
}

__global__ void split4(const float* __restrict__ w0, const float* __restrict__ w1,
                       const float* __restrict__ w2, const float* __restrict__ w3,
                       __nv_bfloat16* __restrict__ h0, __nv_bfloat16* __restrict__ h1,
                       __nv_bfloat16* __restrict__ h2, __nv_bfloat16* __restrict__ h3,
                       __nv_bfloat16* __restrict__ l0, __nv_bfloat16* __restrict__ l1,
                       __nv_bfloat16* __restrict__ l2, __nv_bfloat16* __restrict__ l3,
                       int n0, int n1, int n2, int n3) {
    int z = blockIdx.y;
    const float* w = z==0?w0 : z==1?w1 : z==2?w2 : w3;
    __nv_bfloat16* hh = z==0?h0 : z==1?h1 : z==2?h2 : h3;
    __nv_bfloat16* ll = z==0?l0 : z==1?l1 : z==2?l2 : l3;
    int n = z==0?n0 : z==1?n1 : z==2?n2 : n3;
    for (int i = blockIdx.x*blockDim.x + threadIdx.x; i < n; i += gridDim.x*blockDim.x) {
        float v = w[i];
        __nv_bfloat16 hi = __float2bfloat16_rn(v);
        hh[i] = hi;
        ll[i] = __float2bfloat16_rn(v - __bfloat162float(hi));
    }
}

// ---------------- layernorm -> split bf16 ------------------------------------
__device__ __forceinline__ float blockReduceSum(float v) {
    __shared__ float sh[33];
    __syncthreads();
    int lane = threadIdx.x & 31, wid = threadIdx.x >> 5;
    #pragma unroll
    for (int o = 16; o; o >>= 1) v += __shfl_down_sync(0xffffffffu, v, o);
    if (!lane) sh[wid] = v;
    __syncthreads();
    if (threadIdx.x < 8) {
        float t = sh[threadIdx.x];
        #pragma unroll
        for (int o = 4; o; o >>= 1) t += __shfl_down_sync(0xffu, t, o);
        if (!threadIdx.x) sh[32] = t;
    }
    __syncthreads();
    return sh[32];
}

__global__ void __launch_bounds__(256) ln_kernel(const float* __restrict__ x,
                                                 __nv_bfloat16* __restrict__ yh,
                                                 __nv_bfloat16* __restrict__ yl,
                                                 const float* __restrict__ g,
                                                 const float* __restrict__ b,
                                                 int width) {
    extern __shared__ float row[];
    const float* xr = x + (size_t)blockIdx.x * width;
    float s = 0.f;
    for (int i = threadIdx.x; i < width; i += blockDim.x) { float v = xr[i]; row[i] = v; s += v; }
    float m = blockReduceSum(s) / (float)width;
    float v2 = 0.f;
    for (int i = threadIdx.x; i < width; i += blockDim.x) { float d = row[i] - m; v2 += d*d; }
    float var = blockReduceSum(v2) / (float)width;
    float r = rsqrtf(var + 1e-5f);
    __nv_bfloat16* yhr = yh + (size_t)blockIdx.x * width;
    __nv_bfloat16* ylr = yl + (size_t)blockIdx.x * width;
    for (int i = threadIdx.x; i < width; i += blockDim.x) {
        float v = (row[i] - m) * r * g[i] + b[i];
        __nv_bfloat16 hi = __float2bfloat16_rn(v);
        yhr[i] = hi;
        ylr[i] = __float2bfloat16_rn(v - __bfloat162float(hi));
    }
}

// ---------------- bf16 tensor-core GEMM (cp.async 2-stage + ldmatrix) -------
#define GW 20
#define GT (128*GW)
#define GSMEM2 (3*2*GT*4)   /* 61440 B */
#define GSMEM3 (4*2*GT*4)   /* 81920 B */

template<int CHAINS, int EPI>
__global__ void __launch_bounds__(256,2) gemm_bf16(
    const uint32_t* __restrict__ AHg, const uint32_t* __restrict__ ALg,
    const uint32_t* __restrict__ WHg, const uint32_t* __restrict__ WLg,
    const float* __restrict__ sumptr, float wcount,
    const float* __restrict__ bias, const float* __restrict__ resid,
    float* __restrict__ C, int M, int N, int K)
{
    extern __shared__ uint32_t smw[];
    uint32_t* AH = smw;
    uint32_t* AL = smw + 2*GT;
    uint32_t* WH = smw + 4*GT;
    uint32_t* WL = smw + 6*GT;
    int t = threadIdx.x, lane = t & 31, wid = t >> 5;
    int wm = wid >> 2, wn = wid & 3;
    int bm = blockIdx.y * 128, bn = blockIdx.x * 128;
    int Kw = K >> 1;
    float acc[4][4][4] = {};

    int crow = t >> 2, cwg = (t & 3) << 2;

    #pragma unroll
    for (int it = 0; it < 2; it++) {
        int row = it*64 + crow;
        cp_async16(AH + row*GW + cwg, AHg + (size_t)(bm+row)*Kw + cwg);
        cp_async16(AL + row*GW + cwg, ALg + (size_t)(bm+row)*Kw + cwg);
        cp_async16(WH + row*GW + cwg, WHg + (size_t)(bn+row)*Kw + cwg);
        if (CHAINS == 3) cp_async16(WL + row*GW + cwg, WLg + (size_t)(bn+row)*Kw + cwg);
    }
    asm volatile("cp.async.commit_group;\n");

    int lsub = lane >> 3, lrow = lane & 7;
    int lmrow = (lsub & 1) * 8 + lrow;
    int lkoff = (lsub >> 1) * 4;

    for (int k0 = 0; k0 < K; k0 += 32) {
        int st = (k0 >> 5) & 1;
        bool more = (k0 + 32 < K);
        if (more) {
            int nx = (st ^ 1) * GT;
            int kw = (k0 >> 1) + 16;
            #pragma unroll
            for (int it = 0; it < 2; it++) {
                int row = it*64 + crow;
                cp_async16(AH + nx + row*GW + cwg, AHg + (size_t)(bm+row)*Kw + kw + cwg);
                cp_async16(AL + nx + row*GW + cwg, ALg + (size_t)(bm+row)*Kw + kw + cwg);
                cp_async16(WH + nx + row*GW + cwg, WHg + (size_t)(bn+row)*Kw + kw + cwg);
                if (CHAINS == 3) cp_async16(WL + nx + row*GW + cwg, WLg + (size_t)(bn+row)*Kw + kw + cwg);
            }
            asm volatile("cp.async.commit_group;\n");
            asm volatile("cp.async.wait_group 1;\n");
        } else {
            asm volatile("cp.async.wait_group 0;\n");
        }
        __syncthreads();

        const uint32_t* AHs = AH + st*GT;
        const uint32_t* ALs = AL + st*GT;
        const uint32_t* WHs = WH + st*GT;
        const uint32_t* WLs = WL + st*GT;

        #pragma unroll
        for (int g = 0; g < 2; g++) {
            int wb = g*8 + (lane & 3);
            uint32_t bh[4][2], bl[4][2];
            #pragma unroll
            for (int j = 0; j < 4; j++) {
                int n0 = wn*32 + j*8 + (lane >> 2);
                bh[j][0] = WHs[n0*GW + wb];
                bh[j][1] = WHs[n0*GW + wb + 4];
                if (CHAINS == 3) {
                    bl[j][0] = WLs[n0*GW + wb];
                    bl[j][1] = WLs[n0*GW + wb + 4];
                }
            }
            #pragma unroll
            for (int i = 0; i < 4; i++) {
                int mr = wm*64 + i*16 + lmrow;
                int kc = g*8 + lkoff;
                uint32_t ah[4], al[4];
                ldsm4(ah[0], ah[1], ah[2], ah[3], AHs + mr*GW + kc);
                ldsm4(al[0], al[1], al[2], al[3], ALs + mr*GW + kc);
                #pragma unroll
                for (int j = 0; j < 4; j++) {
                    mma16(acc[i][j], ah, bh[j]);
                    mma16(acc[i][j], al, bh[j]);
                    if (CHAINS == 3) mma16(acc[i][j], ah, bl[j]);
                }
            }
        }
        __syncthreads();
    }

    float s = 1.0f;
    if (sumptr) s = sumptr[0] / wcount + 1e-8f;
    #pragma unroll
    for (int i = 0; i < 4; i++) {
        int r0 = bm + wm*64 + i*16 + (lane >> 2);
        #pragma unroll
        for (int j = 0; j < 4; j++) {
            int c0 = bn + wn*32 + j*8 + ((lane & 3) << 1);
            float v[4] = {acc[i][j][0]*s, acc[i][j][1]*s, acc[i][j][2]*s, acc[i][j][3]*s};
            if (bias) { v[0] += bias[c0]; v[1] += bias[c0+1]; v[2] += bias[c0]; v[3] += bias[c0+1]; }
            if (EPI == 1) {
                #pragma unroll
                for (int u = 0; u < 4; u++)
                    v[u] = v[u] * 0.5f * (1.0f + erff(v[u] * 0.70710678118654752f));
            }
            if (resid) {
                v[0] += resid[(size_t)r0*N + c0];     v[1] += resid[(size_t)r0*N + c0+1];
                v[2] += resid[(size_t)(r0+8)*N + c0]; v[3] += resid[(size_t)(r0+8)*N + c0+1];
            }
            C[(size_t)r0*N + c0]       = v[0]; C[(size_t)r0*N + c0+1]     = v[1];
            C[(size_t)(r0+8)*N + c0]   = v[2]; C[(size_t)(r0+8)*N + c0+1] = v[3];
        }
    }
}

// ---------------- tensor-core flash attention (split bf16) ------------------
// Block: 128 q rows x full head. 8 warps, warp w owns rows w*16..w*16+15.
// Q (pre-scaled by SCALE) / K / V / P all split hi/lo bf16, 3 mma chains each.
#define AW 36    /* words per 64-dhead row (32 + 4 pad; 144B, 16B-aligned) */
#define AQW (128*AW)
#define AKW (64*AW)
#define AFSMEM ((2*AQW + 4*AKW)*4)   /* 73728 B */

__global__ void __launch_bounds__(256) attn_flash(const float* __restrict__ qkv,
                                                  float* __restrict__ O) {
    extern __shared__ uint32_t asw[];
    uint32_t* Qh = asw;
    uint32_t* Ql = asw + AQW;
    uint32_t* Kh = asw + 2*AQW;
    uint32_t* Kl = Kh + AKW;
    uint32_t* Vh = Kl + AKW;
    uint32_t* Vl = Vh + AKW;

    int t = threadIdx.x, lane = t & 31, wid = t >> 5;
    int bh = blockIdx.y;
    int b = bh / HEADS, hh = bh % HEADS;
    int m0 = blockIdx.x * 128;
    const float* Qp = qkv + (size_t)b * SEQ * NQKV + hh * DHEAD;
    const float* Kp = Qp + INNER;
    const float* Vp = Qp + 2*INNER;

    // ---- load Q (scaled), split to bf16 hi/lo ----
    #pragma unroll
    for (int it = 0; it < 8; it++) {
        int idx = it*256 + t;
        int row = idx >> 4, d4 = (idx & 15) << 2;
        float4 q = *(const float4*)(Qp + (size_t)(m0+row)*NQKV + d4);
        q.x *= SCALE; q.y *= SCALE; q.z *= SCALE; q.w *= SCALE;
        uint32_t h0, l0, h1, l1;
        split2(q.x, q.y, h0, l0);
        split2(q.z, q.w, h1, l1);
        int w = row*AW + (d4 >> 1);
        Qh[w] = h0; Qh[w+1] = h1;
        Ql[w] = l0; Ql[w+1] = l1;
    }
    __syncthreads();

    // ---- hoist Q fragments (loop-invariant) ----
    int lsub = lane >> 3, lrow = lane & 7;
    int mr = wid*16 + (lsub & 1)*8 + lrow;
    int lk = (lsub >> 1) * 4;
    uint32_t qfh[4][4], qfl[4][4];
    #pragma unroll
    for (int g = 0; g < 4; g++) {
        ldsm4(qfh[g][0], qfh[g][1], qfh[g][2], qfh[g][3], Qh + mr*AW + g*8 + lk);
        ldsm4(qfl[g][0], qfl[g][1], qfl[g][2], qfl[g][3], Ql + mr*AW + g*8 + lk);
    }

    float mi0 = -1e30f, mi1 = -1e30f, li0 = 0.f, li1 = 0.f;
    float acc[8][4] = {};

    for (int kv = 0; kv < SEQ; kv += 64) {
        __syncthreads();   // previous iter's K/V reads complete
        // ---- load + split K, V tiles ----
        #pragma unroll
        for (int it = 0; it < 4; it++) {
            int idx = it*256 + t;
            int row = idx >> 4, d4 = (idx & 15) << 2;
            int w = row*AW + (d4 >> 1);
            float4 k = *(const float4*)(Kp + (size_t)(kv+row)*NQKV + d4);
            uint32_t h0, l0, h1, l1;
            split2(k.x, k.y, h0, l0); split2(k.z, k.w, h1, l1);
            Kh[w] = h0; Kh[w+1] = h1; Kl[w] = l0; Kl[w+1] = l1;
            float4 v = *(const float4*)(Vp + (size_t)(kv+row)*NQKV + d4);
            split2(v.x, v.y, h0, l0); split2(v.z, v.w, h1, l1);
            Vh[w] = h0; Vh[w+1] = h1; Vl[w] = l0; Vl[w+1] = l1;
        }
        __syncthreads();

        // ---- S = Q K^T (pre-scaled) ----
        float s[8][4] = {};
        int koff = ((lane >> 3) & 1) * 4;
        #pragma unroll
        for (int g = 0; g < 4; g++) {
            #pragma unroll
            for (int j = 0; j < 8; j++) {
                const uint32_t* pk = Kh + (j*8 + (lane & 7))*AW + g*8 + koff;
                uint32_t bhv[2], blv[2];
                ldsm2(bhv[0], bhv[1], pk);
                ldsm2(blv[0], blv[1], Kl + (j*8 + (lane & 7))*AW + g*8 + koff);
                mma16(s[j], qfh[g], bhv);
                mma16(s[j], qfl[g], bhv);
                mma16(s[j], qfh[g], blv);
            }
        }

        // ---- online softmax (rows r = lane>>2, r+8; reduce within quad) ----
        float rm0 = -1e30f, rm1 = -1e30f;
        #pragma unroll
        for (int j = 0; j < 8; j++) {
            rm0 = fmaxf(rm0, fmaxf(s[j][0], s[j][1]));
            rm1 = fmaxf(rm1, fmaxf(s[j][2], s[j][3]));
        }
        rm0 = fmaxf(rm0, __shfl_xor_sync(0xffffffffu, rm0, 1));
        rm0 = fmaxf(rm0, __shfl_xor_sync(0xffffffffu, rm0, 2));
        rm1 = fmaxf(rm1, __shfl_xor_sync(0xffffffffu, rm1, 1));
        rm1 = fmaxf(rm1, __shfl_xor_sync(0xffffffffu, rm1, 2));
        float mn0 = fmaxf(mi0, rm0), mn1 = fmaxf(mi1, rm1);
        float f0 = __expf(mi0 - mn0), f1 = __expf(mi1 - mn1);
        mi0 = mn0; mi1 = mn1;
        float sum0 = 0.f, sum1 = 0.f;
        #pragma unroll
        for (int j = 0; j < 8; j++) {
            s[j][0] = __expf(s[j][0] - mn0); s[j][1] = __expf(s[j][1] - mn0);
            s[j][2] = __expf(s[j][2] - mn1); s[j][3] = __expf(s[j][3] - mn1);
            sum0 += s[j][0] + s[j][1];
            sum1 += s[j][2] + s[j][3];
        }
        sum0 += __shfl_xor_sync(0xffffffffu, sum0, 1);
        sum0 += __shfl_xor_sync(0xffffffffu, sum0, 2);
        sum1 += __shfl_xor_sync(0xffffffffu, sum1, 1);
        sum1 += __shfl_xor_sync(0xffffffffu, sum1, 2);
        li0 = li0*f0 + sum0; li1 = li1*f1 + sum1;
        #pragma unroll
        for (int j = 0; j < 8; j++) {
            acc[j][0] *= f0; acc[j][1] *= f0;
            acc[j][2] *= f1; acc[j][3] *= f1;
        }

        // ---- O += P V ----
        #pragma unroll
        for (int g = 0; g < 4; g++) {
            uint32_t aph[4], apl[4];
            split2(s[2*g][0],   s[2*g][1],   aph[0], apl[0]);
            split2(s[2*g][2],   s[2*g][3],   aph[1], apl[1]);
            split2(s[2*g+1][0], s[2*g+1][1], aph[2], apl[2]);
            split2(s[2*g+1][2], s[2*g+1][3], aph[3], apl[3]);
            #pragma unroll
            for (int j = 0; j < 8; j++) {
                const uint32_t* pv = Vh + (g*16 + (lane & 15))*AW + j*4;
                uint32_t bhv[2], blv[2];
                ldsm2t(bhv[0], bhv[1], pv);
                ldsm2t(blv[0], blv[1], Vl + (g*16 + (lane & 15))*AW + j*4);
                mma16(acc[j], aph, bhv);
                mma16(acc[j], apl, bhv);
                mma16(acc[j], aph, blv);
            }
        }
    }

    // ---- epilogue ----
    float inv0 = 1.0f / li0, inv1 = 1.0f / li1;
    int r = m0 + wid*16 + (lane >> 2);
    #pragma unroll
    for (int j = 0; j < 8; j++) {
        int col = hh*DHEAD + j*8 + ((lane & 3) << 1);
        float2 o0 = {acc[j][0]*inv0, acc[j][1]*inv0};
        float2 o1 = {acc[j][2]*inv1, acc[j][3]*inv1};
        *(float2*)(O + ((size_t)b*SEQ + r)*INNER + col)     = o0;
        *(float2*)(O + ((size_t)b*SEQ + r + 8)*INNER + col) = o1;
    }
}

// ---------------- host driver -----------------------------------------------
extern "C" void kernel_launch(void* const* d_in, const int* in_sizes, int n_in,
                              void* d_out, int out_size) {
    const float* x    = (const float*)d_in[0];
    const float* ln1g = (const float*)d_in[1];
    const float* ln1b = (const float*)d_in[2];
    const float* Wqkv = (const float*)d_in[3];
    const float* ln2g = (const float*)d_in[4];
    const float* ln2b = (const float*)d_in[5];
    const float* Wo   = (const float*)d_in[6];
    const float* bo   = (const float*)d_in[7];
    const float* f1g  = (const float*)d_in[8];
    const float* f1b  = (const float*)d_in[9];
    const float* W1   = (const float*)d_in[10];
    const float* b1   = (const float*)d_in[11];
    const float* f2g  = (const float*)d_in[12];
    const float* f2b  = (const float*)d_in[13];
    const float* W2   = (const float*)d_in[14];
    const float* b2   = (const float*)d_in[15];
    float* h = (float*)d_out;

    float *qkv, *ob, *mlp, *scal;
    __nv_bfloat16 *ah, *al, *whq, *wlq, *who, *wlo, *wh1, *wl1, *wh2, *wl2;
    cudaGetSymbolAddress((void**)&qkv, g_qkv);
    cudaGetSymbolAddress((void**)&ob,  g_obuf);
    cudaGetSymbolAddress((void**)&mlp, g_mlp);
    cudaGetSymbolAddress((void**)&ah,  g_ah);
    cudaGetSymbolAddress((void**)&al,  g_al);
    cudaGetSymbolAddress((void**)&whq, g_whq);
    cudaGetSymbolAddress((void**)&wlq, g_wlq);
    cudaGetSymbolAddress((void**)&who, g_who);
    cudaGetSymbolAddress((void**)&wlo, g_wlo);
    cudaGetSymbolAddress((void**)&wh1, g_wh1);
    cudaGetSymbolAddress((void**)&wl1, g_wl1);
    cudaGetSymbolAddress((void**)&wh2, g_wh2);
    cudaGetSymbolAddress((void**)&wl2, g_wl2);
    cudaGetSymbolAddress((void**)&scal, g_scal);

    cudaFuncSetAttribute(gemm_bf16<2,0>, cudaFuncAttributeMaxDynamicSharedMemorySize, GSMEM2);
    cudaFuncSetAttribute(gemm_bf16<2,1>, cudaFuncAttributeMaxDynamicSharedMemorySize, GSMEM2);
    cudaFuncSetAttribute(gemm_bf16<3,0>, cudaFuncAttributeMaxDynamicSharedMemorySize, GSMEM3);
    cudaFuncSetAttribute(gemm_bf16<3,1>, cudaFuncAttributeMaxDynamicSharedMemorySize, GSMEM3);
    cudaFuncSetAttribute(attn_flash,     cudaFuncAttributeMaxDynamicSharedMemorySize, AFSMEM);

    cudaMemcpyAsync(h, x, sizeof(float)*(size_t)ROWS*DIMM, cudaMemcpyDeviceToDevice);

    const int nA = NQKV*DIMM, nO = DIMM*INNER, n1 = MLPD*DIMM, n2 = DIMM*MLPD;

    for (int l = 0; l < DEPTH; l++) {
        bool tern = (l < DEPTH - 1);
        if (tern) {
            cudaMemsetAsync(scal, 0, 4*sizeof(float));
            abs_sum4<<<dim3(160,4),256>>>(
                Wqkv + (size_t)l*nA, Wo + (size_t)l*nO, W1 + (size_t)l*n1, W2 + (size_t)l*n2,
                nA, nO, n1, n2, scal);
            quant4<<<dim3(160,4),256>>>(
                Wqkv + (size_t)l*nA, Wo + (size_t)l*nO, W1 + (size_t)l*n1, W2 + (size_t)l*n2,
                whq, who, wh1, wh2, scal, nA, nO, n1, n2);
        } else {
            split4<<<dim3(160,4),256>>>(
                Wqkv + (size_t)l*nA, Wo + (size_t)l*nO, W1 + (size_t)l*n1, W2 + (size_t)l*n2,
                whq, who, wh1, wh2, wlq, wlo, wl1, wl2, nA, nO, n1, n2);
        }

        // attention block
        ln_kernel<<<ROWS,256,DIMM*4>>>(h, ah, al, ln1g + l*DIMM, ln1b + l*DIMM, DIMM);
        if (tern)
            gemm_bf16<2,0><<<dim3(NQKV/128, ROWS/128),256,GSMEM2>>>(
                (uint32_t*)ah, (uint32_t*)al, (uint32_t*)whq, nullptr,
                scal+0, (float)nA, nullptr, nullptr, qkv, ROWS, NQKV, DIMM);
        else
            gemm_bf16<3,0><<<dim3(NQKV/128, ROWS/128),256,GSMEM3>>>(
                (uint32_t*)ah, (uint32_t*)al, (uint32_t*)whq, (uint32_t*)wlq,
                nullptr, 1.0f, nullptr, nullptr, qkv, ROWS, NQKV, DIMM);
        attn_flash<<<dim3(SEQ/128, BB*HEADS),256,AFSMEM>>>(qkv, ob);
        ln_kernel<<<ROWS,256,INNER*4>>>(ob, ah, al, ln2g + l*INNER, ln2b + l*INNER, INNER);
        if (tern)
            gemm_bf16<2,0><<<dim3(DIMM/128, ROWS/128),256,GSMEM2>>>(
                (uint32_t*)ah, (uint32_t*)al, (uint32_t*)who, nullptr,
                scal+1, (float)nO, bo + l*DIMM, h, h, ROWS, DIMM, INNER);
        else
            gemm_bf16<3,0><<<dim3(DIMM/128, ROWS/128),256,GSMEM3>>>(
                (uint32_t*)ah, (uint32_t*)al, (uint32_t*)who, (uint32_t*)wlo,
                nullptr, 1.0f, bo + l*DIMM, h, h, ROWS, DIMM, INNER);

        // MLP block (GELU fused into FF1 epilogue)
        ln_kernel<<<ROWS,256,DIMM*4>>>(h, ah, al, f1g + l*DIMM, f1b + l*DIMM, DIMM);
        if (tern)
            gemm_bf16<2,1><<<dim3(MLPD/128, ROWS/128),256,GSMEM2>>>(
                (uint32_t*)ah, (uint32_t*)al, (uint32_t*)wh1, nullptr,
                scal+2, (float)n1, b1 + l*MLPD, nullptr, mlp, ROWS, MLPD, DIMM);
        else
            gemm_bf16<3,1><<<dim3(MLPD/128, ROWS/128),256,GSMEM3>>>(
                (uint32_t*)ah, (uint32_t*)al, (uint32_t*)wh1, (uint32_t*)wl1,
                nullptr, 1.0f, b1 + l*MLPD, nullptr, mlp, ROWS, MLPD, DIMM);
        ln_kernel<<<ROWS,256,MLPD*4>>>(mlp, ah, al, f2g + l*MLPD, f2b + l*MLPD, MLPD);
        if (tern)
            gemm_bf16<2,0><<<dim3(DIMM/128, ROWS/128),256,GSMEM2>>>(
                (uint32_t*)ah, (uint32_t*)al, (uint32_t*)wh2, nullptr,
                scal+3, (float)n2, b2 + l*DIMM, h, h, ROWS, DIMM, MLPD);
        else
            gemm_bf16<3,0><<<dim3(DIMM/128, ROWS/128),256,GSMEM3>>>(
                (uint32_t*)ah, (uint32_t*)al, (uint32_t*)wh2, (uint32_t*)wl2,
                nullptr, 1.0f, b2 + l*DIMM, h, h, ROWS, DIMM, MLPD);
    }
}

// round 9
// speedup vs baseline: 3.2845x; 1.0083x over previous
#include <cuda_runtime.h>
#include <cuda_bf16.h>
#include <math.h>
#include <stdint.h>

#define DIMM  768
#define HEADS 12
#define DHEAD 64
#define INNER 768
#define MLPD  3072
#define BB    8
#define SEQ   1024
#define ROWS  (BB*SEQ)   /* 8192 */
#define DEPTH 6
#define SCALE 0.125f     /* 64^-0.5 */
#define NQKV  (3*INNER)

// ---------------- scratch (device globals: no allocations allowed) ----------
__device__ __align__(16) float g_qkv[(size_t)ROWS*NQKV];
__device__ __align__(16) float g_obuf[ROWS*INNER];
__device__ __align__(16) float g_mlp[(size_t)ROWS*MLPD];
__device__ __align__(16) __nv_bfloat16 g_ah[(size_t)ROWS*MLPD];   // LN out hi
__device__ __align__(16) __nv_bfloat16 g_al[(size_t)ROWS*MLPD];   // LN out lo
__device__ __align__(16) __nv_bfloat16 g_whq[NQKV*DIMM];
__device__ __align__(16) __nv_bfloat16 g_wlq[NQKV*DIMM];
__device__ __align__(16) __nv_bfloat16 g_who[DIMM*INNER];
__device__ __align__(16) __nv_bfloat16 g_wlo[DIMM*INNER];
__device__ __align__(16) __nv_bfloat16 g_wh1[MLPD*DIMM];
__device__ __align__(16) __nv_bfloat16 g_wl1[MLPD*DIMM];
__device__ __align__(16) __nv_bfloat16 g_wh2[DIMM*MLPD];
__device__ __align__(16) __nv_bfloat16 g_wl2[DIMM*MLPD];
__device__ float g_scal[4];

// ---------------- asm helpers ------------------------------------------------
__device__ __forceinline__ void cp_async16(void* smem, const void* gmem) {
    uint32_t s = (uint32_t)__cvta_generic_to_shared(smem);
    asm volatile("cp.async.cg.shared.global [%0], [%1], 16;\n" :: "r"(s), "l"(gmem));
}
__device__ __forceinline__ void ldsm4(uint32_t& a0, uint32_t& a1, uint32_t& a2,
                                      uint32_t& a3, const uint32_t* p) {
    uint32_t s = (uint32_t)__cvta_generic_to_shared(p);
    asm volatile("ldmatrix.sync.aligned.m8n8.x4.shared.b16 {%0,%1,%2,%3}, [%4];\n"
                 : "=r"(a0), "=r"(a1), "=r"(a2), "=r"(a3) : "r"(s));
}
__device__ __forceinline__ void ldsm2(uint32_t& a0, uint32_t& a1, const uint32_t* p) {
    uint32_t s = (uint32_t)__cvta_generic_to_shared(p);
    asm volatile("ldmatrix.sync.aligned.m8n8.x2.shared.b16 {%0,%1}, [%2];\n"
                 : "=r"(a0), "=r"(a1) : "r"(s));
}
__device__ __forceinline__ void ldsm2t(uint32_t& a0, uint32_t& a1, const uint32_t* p) {
    uint32_t s = (uint32_t)__cvta_generic_to_shared(p);
    asm volatile("ldmatrix.sync.aligned.m8n8.x2.trans.shared.b16 {%0,%1}, [%2];\n"
                 : "=r"(a0), "=r"(a1) : "r"(s));
}
__device__ __forceinline__ void mma16(float c[4], const uint32_t a[4], const uint32_t b[2]) {
    asm volatile(
        "mma.sync.aligned.m16n8k16.row.col.f32.bf16.bf16.f32 "
        "{%0,%1,%2,%3}, {%4,%5,%6,%7}, {%8,%9}, {%0,%1,%2,%3};\n"
        : "+f"(c[0]), "+f"(c[1]), "+f"(c[2]), "+f"(c[3])
        : "r"(a[0]), "r"(a[1]), "r"(a[2]), "r"(a[3]), "r"(b[0]), "r"(b[1]));
}
__device__ __forceinline__ void split2(float a, float b, uint32_t& hi, uint32_t& lo) {
    __nv_bfloat162 h = __floats2bfloat162_rn(a, b);
    hi = *reinterpret_cast<uint32_t*>(&h);
    float la = a - __bfloat162float(h.x);
    float lb = b - __bfloat162float(h.y);
    __nv_bfloat162 l = __floats2bfloat162_rn(la, lb);
    lo = *reinterpret_cast<uint32_t*>(&l);
}

// ---------------- batched abs-sum / quant / split ---------------------------
__global__ void abs_sum4(const float* __restrict__ w0, const float* __restrict__ w1,
                         const float* __restrict__ w2, const float* __restrict__ w3,
                         int n0, int n1, int n2, int n3, float* out) {
    int z = blockIdx.y;
    const float* w = z==0?w0 : z==1?w1 : z==2?w2 : w3;
    int n = z==0?n0 : z==1?n1 : z==2?n2 : n3;
    float s = 0.f;
    for (int i = blockIdx.x*blockDim.x + threadIdx.x; i < n; i += gridDim.x*blockDim.x)
        s += fabsf(w[i]);
    #pragma unroll
    for (int o = 16; o; o >>= 1) s += __shfl_down_sync(0xffffffffu, s, o);
    __shared__ float sh[8];
    if ((threadIdx.x & 31) == 0) sh[threadIdx.x >> 5] = s;
    __syncthreads();
    if (threadIdx.x < 8) {
        float v = sh[threadIdx.x];
        #pragma unroll
        for (int o = 4; o; o >>= 1) v += __shfl_down_sync(0xffu, v, o);
        if (threadIdx.x == 0) atomicAdd(out + z, v);
    }
}

__global__ void quant4(const float* __restrict__ w0, const float* __restrict__ w1,
                       const float* __restrict__ w2, const float* __restrict__ w3,
                       __nv_bfloat16* __restrict__ q0, __nv_bfloat16* __restrict__ q1,
                       __nv_bfloat16* __restrict__ q2, __nv_bfloat16* __restrict__ q3,
                       const float* __restrict__ sums, int n0, int n1, int n2, int n3) {
    int z = blockIdx.y;
    const float* w = z==0?w0 : z==1?w1 : z==2?w2 : w3;
    __nv_bfloat16* q = z==0?q0 : z==1?q1 : z==2?q2 : q3;
    int n = z==0?n0 : z==1?n1 : z==2?n2 : n3;
    float s = sums[z] / (float)n + 1e-8f;
    float inv = 1.0f / s;
    for (int i = blockIdx.x*blockDim.x + threadIdx.x; i < n; i += gridDim.x*blockDim.x) {
        float t = rintf(w[i] * inv);           // half-to-even, matches jnp.round
        t = fminf(1.0f, fmaxf(-1.0f, t));
        q[i] = __float2bfloat16_rn(t);
    }
}

__global__ void split4(const float* __restrict__ w0, const float* __restrict__ w1,
                       const float* __restrict__ w2, const float* __restrict__ w3,
                       __nv_bfloat16* __restrict__ h0, __nv_bfloat16* __restrict__ h1,
                       __nv_bfloat16* __restrict__ h2, __nv_bfloat16* __restrict__ h3,
                       __nv_bfloat16* __restrict__ l0, __nv_bfloat16* __restrict__ l1,
                       __nv_bfloat16* __restrict__ l2, __nv_bfloat16* __restrict__ l3,
                       int n0, int n1, int n2, int n3) {
    int z = blockIdx.y;
    const float* w = z==0?w0 : z==1?w1 : z==2?w2 : w3;
    __nv_bfloat16* hh = z==0?h0 : z==1?h1 : z==2?h2 : h3;
    __nv_bfloat16* ll = z==0?l0 : z==1?l1 : z==2?l2 : l3;
    int n = z==0?n0 : z==1?n1 : z==2?n2 : n3;
    for (int i = blockIdx.x*blockDim.x + threadIdx.x; i < n; i += gridDim.x*blockDim.x) {
        float v = w[i];
        __nv_bfloat16 hi = __float2bfloat16_rn(v);
        hh[i] = hi;
        ll[i] = __float2bfloat16_rn(v - __bfloat162float(hi));
    }
}

// ---------------- layernorm -> split bf16 ------------------------------------
__device__ __forceinline__ float blockReduceSum(float v) {
    __shared__ float sh[33];
    __syncthreads();
    int lane = threadIdx.x & 31, wid = threadIdx.x >> 5;
    #pragma unroll
    for (int o = 16; o; o >>= 1) v += __shfl_down_sync(0xffffffffu, v, o);
    if (!lane) sh[wid] = v;
    __syncthreads();
    if (threadIdx.x < 8) {
        float t = sh[threadIdx.x];
        #pragma unroll
        for (int o = 4; o; o >>= 1) t += __shfl_down_sync(0xffu, t, o);
        if (!threadIdx.x) sh[32] = t;
    }
    __syncthreads();
    return sh[32];
}

__global__ void __launch_bounds__(256) ln_kernel(const float* __restrict__ x,
                                                 __nv_bfloat16* __restrict__ yh,
                                                 __nv_bfloat16* __restrict__ yl,
                                                 const float* __restrict__ g,
                                                 const float* __restrict__ b,
                                                 int width) {
    extern __shared__ float row[];
    const float* xr = x + (size_t)blockIdx.x * width;
    float s = 0.f;
    for (int i = threadIdx.x; i < width; i += blockDim.x) { float v = xr[i]; row[i] = v; s += v; }
    float m = blockReduceSum(s) / (float)width;
    float v2 = 0.f;
    for (int i = threadIdx.x; i < width; i += blockDim.x) { float d = row[i] - m; v2 += d*d; }
    float var = blockReduceSum(v2) / (float)width;
    float r = rsqrtf(var + 1e-5f);
    __nv_bfloat16* yhr = yh + (size_t)blockIdx.x * width;
    __nv_bfloat16* ylr = yl + (size_t)blockIdx.x * width;
    for (int i = threadIdx.x; i < width; i += blockDim.x) {
        float v = (row[i] - m) * r * g[i] + b[i];
        __nv_bfloat16 hi = __float2bfloat16_rn(v);
        yhr[i] = hi;
        ylr[i] = __float2bfloat16_rn(v - __bfloat162float(hi));
    }
}

// ---------------- bf16 tensor-core GEMM (3-stage cp.async, 1 sync/step) -----
// C = s*(A @ W^T) + bias [+gelu] [+resid],  A = Ah + Al (bf16 split)
// CHAINS==2: W exact in bf16 (ternary). CHAINS==3: W split hi/lo.
#define GW 20            /* words per 32-elem K-slice row (16 + 4 pad) */
#define GT (128*GW)      /* words per array per stage */
#define GSMEM2 (3*3*GT*4)   /* 92160 B  (3 stages x {AH,AL,WH}) */
#define GSMEM3 (3*4*GT*4)   /* 122880 B (3 stages x {AH,AL,WH,WL}) */

template<int CHAINS, int EPI>
__global__ void __launch_bounds__(256,2) gemm_bf16(
    const uint32_t* __restrict__ AHg, const uint32_t* __restrict__ ALg,
    const uint32_t* __restrict__ WHg, const uint32_t* __restrict__ WLg,
    const float* __restrict__ sumptr, float wcount,
    const float* __restrict__ bias, const float* __restrict__ resid,
    float* __restrict__ C, int M, int N, int K)
{
    extern __shared__ uint32_t smw[];
    const int PS = (CHAINS + 1) * GT;     // words per stage
    int t = threadIdx.x, lane = t & 31, wid = t >> 5;
    int wm = wid >> 2, wn = wid & 3;
    int bm = blockIdx.y * 128, bn = blockIdx.x * 128;
    int Kw = K >> 1;
    float acc[4][4][4] = {};

    int crow = t >> 2, cwg = (t & 3) << 2;

    auto do_copy = [&](int slot, int kw) {
        uint32_t* S = smw + slot*PS;
        #pragma unroll
        for (int it = 0; it < 2; it++) {
            int row = it*64 + crow;
            cp_async16(S +        row*GW + cwg, AHg + (size_t)(bm+row)*Kw + kw + cwg);
            cp_async16(S +   GT + row*GW + cwg, ALg + (size_t)(bm+row)*Kw + kw + cwg);
            cp_async16(S + 2*GT + row*GW + cwg, WHg + (size_t)(bn+row)*Kw + kw + cwg);
            if (CHAINS == 3)
                cp_async16(S + 3*GT + row*GW + cwg, WLg + (size_t)(bn+row)*Kw + kw + cwg);
        }
        asm volatile("cp.async.commit_group;\n");
    };

    int nsteps = K >> 5;
    do_copy(0, 0);
    do_copy(1, 16);

    // ldmatrix lane mappings
    int lsub = lane >> 3, lrow = lane & 7;
    int lmrow = (lsub & 1) * 8 + lrow;       // A: row within m16 tile
    int lkoff = (lsub >> 1) * 4;             // A: word offset within k16
    int bl8 = lane & 7;                      // B: row within n8 tile
    int btile = lsub >> 1;                   // B: which n8 tile of the pair
    int bkh = (lsub & 1) * 4;                // B: k-half word offset

    for (int i = 0; i < nsteps; i++) {
        if (i + 1 < nsteps) asm volatile("cp.async.wait_group 1;\n");
        else                asm volatile("cp.async.wait_group 0;\n");
        __syncthreads();
        if (i + 2 < nsteps) do_copy((i + 2) % 3, (i + 2) * 16);

        uint32_t* S = smw + (i % 3) * PS;
        const uint32_t* AHs = S;
        const uint32_t* ALs = S + GT;
        const uint32_t* WHs = S + 2*GT;
        const uint32_t* WLs = S + 3*GT;

        #pragma unroll
        for (int g = 0; g < 2; g++) {
            uint32_t bh[4][2], bl[4][2];
            #pragma unroll
            for (int p = 0; p < 2; p++) {
                int brow = wn*32 + p*16 + btile*8 + bl8;
                ldsm4(bh[2*p][0], bh[2*p][1], bh[2*p+1][0], bh[2*p+1][1],
                      WHs + brow*GW + g*8 + bkh);
                if (CHAINS == 3)
                    ldsm4(bl[2*p][0], bl[2*p][1], bl[2*p+1][0], bl[2*p+1][1],
                          WLs + brow*GW + g*8 + bkh);
            }
            #pragma unroll
            for (int ii = 0; ii < 4; ii++) {
                int mr = wm*64 + ii*16 + lmrow;
                int kc = g*8 + lkoff;
                uint32_t ah[4], al[4];
                ldsm4(ah[0], ah[1], ah[2], ah[3], AHs + mr*GW + kc);
                ldsm4(al[0], al[1], al[2], al[3], ALs + mr*GW + kc);
                #pragma unroll
                for (int j = 0; j < 4; j++) {
                    mma16(acc[ii][j], ah, bh[j]);
                    mma16(acc[ii][j], al, bh[j]);
                    if (CHAINS == 3) mma16(acc[ii][j], ah, bl[j]);
                }
            }
        }
    }

    float s = 1.0f;
    if (sumptr) s = sumptr[0] / wcount + 1e-8f;
    #pragma unroll
    for (int i = 0; i < 4; i++) {
        int r0 = bm + wm*64 + i*16 + (lane >> 2);
        #pragma unroll
        for (int j = 0; j < 4; j++) {
            int c0 = bn + wn*32 + j*8 + ((lane & 3) << 1);
            float v[4] = {acc[i][j][0]*s, acc[i][j][1]*s, acc[i][j][2]*s, acc[i][j][3]*s};
            if (bias) { v[0] += bias[c0]; v[1] += bias[c0+1]; v[2] += bias[c0]; v[3] += bias[c0+1]; }
            if (EPI == 1) {
                #pragma unroll
                for (int u = 0; u < 4; u++)
                    v[u] = v[u] * 0.5f * (1.0f + erff(v[u] * 0.70710678118654752f));
            }
            if (resid) {
                v[0] += resid[(size_t)r0*N + c0];     v[1] += resid[(size_t)r0*N + c0+1];
                v[2] += resid[(size_t)(r0+8)*N + c0]; v[3] += resid[(size_t)(r0+8)*N + c0+1];
            }
            C[(size_t)r0*N + c0]       = v[0]; C[(size_t)r0*N + c0+1]     = v[1];
            C[(size_t)(r0+8)*N + c0]   = v[2]; C[(size_t)(r0+8)*N + c0+1] = v[3];
        }
    }
}

// ---------------- tensor-core flash attention (split bf16) ------------------
#define AW 36    /* words per 64-dhead row (32 + 4 pad; 144B, 16B-aligned) */
#define AQW (128*AW)
#define AKW (64*AW)
#define AFSMEM ((2*AQW + 4*AKW)*4)   /* 73728 B */

__global__ void __launch_bounds__(256) attn_flash(const float* __restrict__ qkv,
                                                  float* __restrict__ O) {
    extern __shared__ uint32_t asw[];
    uint32_t* Qh = asw;
    uint32_t* Ql = asw + AQW;
    uint32_t* Kh = asw + 2*AQW;
    uint32_t* Kl = Kh + AKW;
    uint32_t* Vh = Kl + AKW;
    uint32_t* Vl = Vh + AKW;

    int t = threadIdx.x, lane = t & 31, wid = t >> 5;
    int bh = blockIdx.y;
    int b = bh / HEADS, hh = bh % HEADS;
    int m0 = blockIdx.x * 128;
    const float* Qp = qkv + (size_t)b * SEQ * NQKV + hh * DHEAD;
    const float* Kp = Qp + INNER;
    const float* Vp = Qp + 2*INNER;

    #pragma unroll
    for (int it = 0; it < 8; it++) {
        int idx = it*256 + t;
        int row = idx >> 4, d4 = (idx & 15) << 2;
        float4 q = *(const float4*)(Qp + (size_t)(m0+row)*NQKV + d4);
        q.x *= SCALE; q.y *= SCALE; q.z *= SCALE; q.w *= SCALE;
        uint32_t h0, l0, h1, l1;
        split2(q.x, q.y, h0, l0);
        split2(q.z, q.w, h1, l1);
        int w = row*AW + (d4 >> 1);
        Qh[w] = h0; Qh[w+1] = h1;
        Ql[w] = l0; Ql[w+1] = l1;
    }
    __syncthreads();

    int lsub = lane >> 3, lrow = lane & 7;
    int mr = wid*16 + (lsub & 1)*8 + lrow;
    int lk = (lsub >> 1) * 4;
    uint32_t qfh[4][4], qfl[4][4];
    #pragma unroll
    for (int g = 0; g < 4; g++) {
        ldsm4(qfh[g][0], qfh[g][1], qfh[g][2], qfh[g][3], Qh + mr*AW + g*8 + lk);
        ldsm4(qfl[g][0], qfl[g][1], qfl[g][2], qfl[g][3], Ql + mr*AW + g*8 + lk);
    }

    float mi0 = -1e30f, mi1 = -1e30f, li0 = 0.f, li1 = 0.f;
    float acc[8][4] = {};

    for (int kv = 0; kv < SEQ; kv += 64) {
        __syncthreads();
        #pragma unroll
        for (int it = 0; it < 4; it++) {
            int idx = it*256 + t;
            int row = idx >> 4, d4 = (idx & 15) << 2;
            int w = row*AW + (d4 >> 1);
            float4 k = *(const float4*)(Kp + (size_t)(kv+row)*NQKV + d4);
            uint32_t h0, l0, h1, l1;
            split2(k.x, k.y, h0, l0); split2(k.z, k.w, h1, l1);
            Kh[w] = h0; Kh[w+1] = h1; Kl[w] = l0; Kl[w+1] = l1;
            float4 v = *(const float4*)(Vp + (size_t)(kv+row)*NQKV + d4);
            split2(v.x, v.y, h0, l0); split2(v.z, v.w, h1, l1);
            Vh[w] = h0; Vh[w+1] = h1; Vl[w] = l0; Vl[w+1] = l1;
        }
        __syncthreads();

        float s[8][4] = {};
        int koff = ((lane >> 3) & 1) * 4;
        #pragma unroll
        for (int g = 0; g < 4; g++) {
            #pragma unroll
            for (int j = 0; j < 8; j++) {
                const uint32_t* pk = Kh + (j*8 + (lane & 7))*AW + g*8 + koff;
                uint32_t bhv[2], blv[2];
                ldsm2(bhv[0], bhv[1], pk);
                ldsm2(blv[0], blv[1], Kl + (j*8 + (lane & 7))*AW + g*8 + koff);
                mma16(s[j], qfh[g], bhv);
                mma16(s[j], qfl[g], bhv);
                mma16(s[j], qfh[g], blv);
            }
        }

        float rm0 = -1e30f, rm1 = -1e30f;
        #pragma unroll
        for (int j = 0; j < 8; j++) {
            rm0 = fmaxf(rm0, fmaxf(s[j][0], s[j][1]));
            rm1 = fmaxf(rm1, fmaxf(s[j][2], s[j][3]));
        }
        rm0 = fmaxf(rm0, __shfl_xor_sync(0xffffffffu, rm0, 1));
        rm0 = fmaxf(rm0, __shfl_xor_sync(0xffffffffu, rm0, 2));
        rm1 = fmaxf(rm1, __shfl_xor_sync(0xffffffffu, rm1, 1));
        rm1 = fmaxf(rm1, __shfl_xor_sync(0xffffffffu, rm1, 2));
        float mn0 = fmaxf(mi0, rm0), mn1 = fmaxf(mi1, rm1);
        float f0 = __expf(mi0 - mn0), f1 = __expf(mi1 - mn1);
        mi0 = mn0; mi1 = mn1;
        float sum0 = 0.f, sum1 = 0.f;
        #pragma unroll
        for (int j = 0; j < 8; j++) {
            s[j][0] = __expf(s[j][0] - mn0); s[j][1] = __expf(s[j][1] - mn0);
            s[j][2] = __expf(s[j][2] - mn1); s[j][3] = __expf(s[j][3] - mn1);
            sum0 += s[j][0] + s[j][1];
            sum1 += s[j][2] + s[j][3];
        }
        sum0 += __shfl_xor_sync(0xffffffffu, sum0, 1);
        sum0 += __shfl_xor_sync(0xffffffffu, sum0, 2);
        sum1 += __shfl_xor_sync(0xffffffffu, sum1, 1);
        sum1 += __shfl_xor_sync(0xffffffffu, sum1, 2);
        li0 = li0*f0 + sum0; li1 = li1*f1 + sum1;
        #pragma unroll
        for (int j = 0; j < 8; j++) {
            acc[j][0] *= f0; acc[j][1] *= f0;
            acc[j][2] *= f1; acc[j][3] *= f1;
        }

        #pragma unroll
        for (int g = 0; g < 4; g++) {
            uint32_t aph[4], apl[4];
            split2(s[2*g][0],   s[2*g][1],   aph[0], apl[0]);
            split2(s[2*g][2],   s[2*g][3],   aph[1], apl[1]);
            split2(s[2*g+1][0], s[2*g+1][1], aph[2], apl[2]);
            split2(s[2*g+1][2], s[2*g+1][3], aph[3], apl[3]);
            #pragma unroll
            for (int j = 0; j < 8; j++) {
                const uint32_t* pv = Vh + (g*16 + (lane & 15))*AW + j*4;
                uint32_t bhv[2], blv[2];
                ldsm2t(bhv[0], bhv[1], pv);
                ldsm2t(blv[0], blv[1], Vl + (g*16 + (lane & 15))*AW + j*4);
                mma16(acc[j], aph, bhv);
                mma16(acc[j], apl, bhv);
                mma16(acc[j], aph, blv);
            }
        }
    }

    float inv0 = 1.0f / li0, inv1 = 1.0f / li1;
    int r = m0 + wid*16 + (lane >> 2);
    #pragma unroll
    for (int j = 0; j < 8; j++) {
        int col = hh*DHEAD + j*8 + ((lane & 3) << 1);
        float2 o0 = {acc[j][0]*inv0, acc[j][1]*inv0};
        float2 o1 = {acc[j][2]*inv1, acc[j][3]*inv1};
        *(float2*)(O + ((size_t)b*SEQ + r)*INNER + col)     = o0;
        *(float2*)(O + ((size_t)b*SEQ + r + 8)*INNER + col) = o1;
    }
}

// ---------------- host driver -----------------------------------------------
extern "C" void kernel_launch(void* const* d_in, const int* in_sizes, int n_in,
                              void* d_out, int out_size) {
    const float* x    = (const float*)d_in[0];
    const float* ln1g = (const float*)d_in[1];
    const float* ln1b = (const float*)d_in[2];
    const float* Wqkv = (const float*)d_in[3];
    const float* ln2g = (const float*)d_in[4];
    const float* ln2b = (const float*)d_in[5];
    const float* Wo   = (const float*)d_in[6];
    const float* bo   = (const float*)d_in[7];
    const float* f1g  = (const float*)d_in[8];
    const float* f1b  = (const float*)d_in[9];
    const float* W1   = (const float*)d_in[10];
    const float* b1   = (const float*)d_in[11];
    const float* f2g  = (const float*)d_in[12];
    const float* f2b  = (const float*)d_in[13];
    const float* W2   = (const float*)d_in[14];
    const float* b2   = (const float*)d_in[15];
    float* h = (float*)d_out;

    float *qkv, *ob, *mlp, *scal;
    __nv_bfloat16 *ah, *al, *whq, *wlq, *who, *wlo, *wh1, *wl1, *wh2, *wl2;
    cudaGetSymbolAddress((void**)&qkv, g_qkv);
    cudaGetSymbolAddress((void**)&ob,  g_obuf);
    cudaGetSymbolAddress((void**)&mlp, g_mlp);
    cudaGetSymbolAddress((void**)&ah,  g_ah);
    cudaGetSymbolAddress((void**)&al,  g_al);
    cudaGetSymbolAddress((void**)&whq, g_whq);
    cudaGetSymbolAddress((void**)&wlq, g_wlq);
    cudaGetSymbolAddress((void**)&who, g_who);
    cudaGetSymbolAddress((void**)&wlo, g_wlo);
    cudaGetSymbolAddress((void**)&wh1, g_wh1);
    cudaGetSymbolAddress((void**)&wl1, g_wl1);
    cudaGetSymbolAddress((void**)&wh2, g_wh2);
    cudaGetSymbolAddress((void**)&wl2, g_wl2);
    cudaGetSymbolAddress((void**)&scal, g_scal);

    cudaFuncSetAttribute(gemm_bf16<2,0>, cudaFuncAttributeMaxDynamicSharedMemorySize, GSMEM2);
    cudaFuncSetAttribute(gemm_bf16<2,1>, cudaFuncAttributeMaxDynamicSharedMemorySize, GSMEM2);
    cudaFuncSetAttribute(gemm_bf16<3,0>, cudaFuncAttributeMaxDynamicSharedMemorySize, GSMEM3);
    cudaFuncSetAttribute(gemm_bf16<3,1>, cudaFuncAttributeMaxDynamicSharedMemorySize, GSMEM3);
    cudaFuncSetAttribute(attn_flash,     cudaFuncAttributeMaxDynamicSharedMemorySize, AFSMEM);

    cudaMemcpyAsync(h, x, sizeof(float)*(size_t)ROWS*DIMM, cudaMemcpyDeviceToDevice);

    const int nA = NQKV*DIMM, nO = DIMM*INNER, n1 = MLPD*DIMM, n2 = DIMM*MLPD;

    for (int l = 0; l < DEPTH; l++) {
        bool tern = (l < DEPTH - 1);
        if (tern) {
            cudaMemsetAsync(scal, 0, 4*sizeof(float));
            abs_sum4<<<dim3(160,4),256>>>(
                Wqkv + (size_t)l*nA, Wo + (size_t)l*nO, W1 + (size_t)l*n1, W2 + (size_t)l*n2,
                nA, nO, n1, n2, scal);
            quant4<<<dim3(160,4),256>>>(
                Wqkv + (size_t)l*nA, Wo + (size_t)l*nO, W1 + (size_t)l*n1, W2 + (size_t)l*n2,
                whq, who, wh1, wh2, scal, nA, nO, n1, n2);
        } else {
            split4<<<dim3(160,4),256>>>(
                Wqkv + (size_t)l*nA, Wo + (size_t)l*nO, W1 + (size_t)l*n1, W2 + (size_t)l*n2,
                whq, who, wh1, wh2, wlq, wlo, wl1, wl2, nA, nO, n1, n2);
        }

        // attention block
        ln_kernel<<<ROWS,256,DIMM*4>>>(h, ah, al, ln1g + l*DIMM, ln1b + l*DIMM, DIMM);
        if (tern)
            gemm_bf16<2,0><<<dim3(NQKV/128, ROWS/128),256,GSMEM2>>>(
                (uint32_t*)ah, (uint32_t*)al, (uint32_t*)whq, nullptr,
                scal+0, (float)nA, nullptr, nullptr, qkv, ROWS, NQKV, DIMM);
        else
            gemm_bf16<3,0><<<dim3(NQKV/128, ROWS/128),256,GSMEM3>>>(
                (uint32_t*)ah, (uint32_t*)al, (uint32_t*)whq, (uint32_t*)wlq,
                nullptr, 1.0f, nullptr, nullptr, qkv, ROWS, NQKV, DIMM);
        attn_flash<<<dim3(SEQ/128, BB*HEADS),256,AFSMEM>>>(qkv, ob);
        ln_kernel<<<ROWS,256,INNER*4>>>(ob, ah, al, ln2g + l*INNER, ln2b + l*INNER, INNER);
        if (tern)
            gemm_bf16<2,0><<<dim3(DIMM/128, ROWS/128),256,GSMEM2>>>(
                (uint32_t*)ah, (uint32_t*)al, (uint32_t*)who, nullptr,
                scal+1, (float)nO, bo + l*DIMM, h, h, ROWS, DIMM, INNER);
        else
            gemm_bf16<3,0><<<dim3(DIMM/128, ROWS/128),256,GSMEM3>>>(
                (uint32_t*)ah, (uint32_t*)al, (uint32_t*)who, (uint32_t*)wlo,
                nullptr, 1.0f, bo + l*DIMM, h, h, ROWS, DIMM, INNER);

        // MLP block (GELU fused into FF1 epilogue)
        ln_kernel<<<ROWS,256,DIMM*4>>>(h, ah, al, f1g + l*DIMM, f1b + l*DIMM, DIMM);
        if (tern)
            gemm_bf16<2,1><<<dim3(MLPD/128, ROWS/128),256,GSMEM2>>>(
                (uint32_t*)ah, (uint32_t*)al, (uint32_t*)wh1, nullptr,
                scal+2, (float)n1, b1 + l*MLPD, nullptr, mlp, ROWS, MLPD, DIMM);
        else
            gemm_bf16<3,1><<<dim3(MLPD/128, ROWS/128),256,GSMEM3>>>(
                (uint32_t*)ah, (uint32_t*)al, (uint32_t*)wh1, (uint32_t*)wl1,
                nullptr, 1.0f, b1 + l*MLPD, nullptr, mlp, ROWS, MLPD, DIMM);
        ln_kernel<<<ROWS,256,MLPD*4>>>(mlp, ah, al, f2g + l*MLPD, f2b + l*MLPD, MLPD);
        if (tern)
            gemm_bf16<2,0><<<dim3(DIMM/128, ROWS/128),256,GSMEM2>>>(
                (uint32_t*)ah, (uint32_t*)al, (uint32_t*)wh2, nullptr,
                scal+3, (float)n2, b2 + l*DIMM, h, h, ROWS, DIMM, MLPD);
        else
            gemm_bf16<3,0><<<dim3(DIMM/128, ROWS/128),256,GSMEM3>>>(
                (uint32_t*)ah, (uint32_t*)al, (uint32_t*)wh2, (uint32_t*)wl2,
                nullptr, 1.0f, b2 + l*DIMM, h, h, ROWS, DIMM, MLPD);
    }
}

// round 11
// speedup vs baseline: 3.5543x; 1.0822x over previous
#include <cuda_runtime.h>
#include <cuda_bf16.h>
#include <math.h>
#include <stdint.h>

#define DIMM  768
#define HEADS 12
#define DHEAD 64
#define INNER 768
#define MLPD  3072
#define BB    8
#define SEQ   1024
#define ROWS  (BB*SEQ)   /* 8192 */
#define DEPTH 6
#define SCALE 0.125f     /* 64^-0.5 */
#define NQKV  (3*INNER)

// ---------------- scratch (device globals: no allocations allowed) ----------
__device__ __align__(16) float g_qkv[(size_t)ROWS*NQKV];
__device__ __align__(16) float g_obuf[ROWS*INNER];
__device__ __align__(16) float g_mlp[(size_t)ROWS*MLPD];
__device__ __align__(16) __nv_bfloat16 g_ah[(size_t)ROWS*MLPD];   // LN out hi
__device__ __align__(16) __nv_bfloat16 g_al[(size_t)ROWS*MLPD];   // LN out lo
__device__ __align__(16) __nv_bfloat16 g_whq[NQKV*DIMM];
__device__ __align__(16) __nv_bfloat16 g_wlq[NQKV*DIMM];
__device__ __align__(16) __nv_bfloat16 g_who[DIMM*INNER];
__device__ __align__(16) __nv_bfloat16 g_wlo[DIMM*INNER];
__device__ __align__(16) __nv_bfloat16 g_wh1[MLPD*DIMM];
__device__ __align__(16) __nv_bfloat16 g_wl1[MLPD*DIMM];
__device__ __align__(16) __nv_bfloat16 g_wh2[DIMM*MLPD];
__device__ __align__(16) __nv_bfloat16 g_wl2[DIMM*MLPD];
__device__ float g_scal[4];

// ---------------- asm helpers ------------------------------------------------
__device__ __forceinline__ void cp_async16(void* smem, const void* gmem) {
    uint32_t s = (uint32_t)__cvta_generic_to_shared(smem);
    asm volatile("cp.async.cg.shared.global [%0], [%1], 16;\n" :: "r"(s), "l"(gmem));
}
__device__ __forceinline__ void ldsm4(uint32_t& a0, uint32_t& a1, uint32_t& a2,
                                      uint32_t& a3, const uint32_t* p) {
    uint32_t s = (uint32_t)__cvta_generic_to_shared(p);
    asm volatile("ldmatrix.sync.aligned.m8n8.x4.shared.b16 {%0,%1,%2,%3}, [%4];\n"
                 : "=r"(a0), "=r"(a1), "=r"(a2), "=r"(a3) : "r"(s));
}
__device__ __forceinline__ void ldsm2(uint32_t& a0, uint32_t& a1, const uint32_t* p) {
    uint32_t s = (uint32_t)__cvta_generic_to_shared(p);
    asm volatile("ldmatrix.sync.aligned.m8n8.x2.shared.b16 {%0,%1}, [%2];\n"
                 : "=r"(a0), "=r"(a1) : "r"(s));
}
__device__ __forceinline__ void ldsm2t(uint32_t& a0, uint32_t& a1, const uint32_t* p) {
    uint32_t s = (uint32_t)__cvta_generic_to_shared(p);
    asm volatile("ldmatrix.sync.aligned.m8n8.x2.trans.shared.b16 {%0,%1}, [%2];\n"
                 : "=r"(a0), "=r"(a1) : "r"(s));
}
__device__ __forceinline__ void mma16(float c[4], const uint32_t a[4], const uint32_t b[2]) {
    asm volatile(
        "mma.sync.aligned.m16n8k16.row.col.f32.bf16.bf16.f32 "
        "{%0,%1,%2,%3}, {%4,%5,%6,%7}, {%8,%9}, {%0,%1,%2,%3};\n"
        : "+f"(c[0]), "+f"(c[1]), "+f"(c[2]), "+f"(c[3])
        : "r"(a[0]), "r"(a[1]), "r"(a[2]), "r"(a[3]), "r"(b[0]), "r"(b[1]));
}
__device__ __forceinline__ void split2(float a, float b, uint32_t& hi, uint32_t& lo) {
    __nv_bfloat162 h = __floats2bfloat162_rn(a, b);
    hi = *reinterpret_cast<uint32_t*>(&h);
    float la = a - __bfloat162float(h.x);
    float lb = b - __bfloat162float(h.y);
    __nv_bfloat162 l = __floats2bfloat162_rn(la, lb);
    lo = *reinterpret_cast<uint32_t*>(&l);
}

// ---------------- batched abs-sum / quant / split (float4) ------------------
__global__ void abs_sum4(const float* __restrict__ w0, const float* __restrict__ w1,
                         const float* __restrict__ w2, const float* __restrict__ w3,
                         int n0, int n1, int n2, int n3, float* out) {
    int z = blockIdx.y;
    const float* w = z==0?w0 : z==1?w1 : z==2?w2 : w3;
    int n4 = (z==0?n0 : z==1?n1 : z==2?n2 : n3) >> 2;
    float s = 0.f;
    for (int i = blockIdx.x*blockDim.x + threadIdx.x; i < n4; i += gridDim.x*blockDim.x) {
        float4 v = ((const float4*)w)[i];
        s += fabsf(v.x) + fabsf(v.y) + fabsf(v.z) + fabsf(v.w);
    }
    #pragma unroll
    for (int o = 16; o; o >>= 1) s += __shfl_down_sync(0xffffffffu, s, o);
    __shared__ float sh[8];
    if ((threadIdx.x & 31) == 0) sh[threadIdx.x >> 5] = s;
    __syncthreads();
    if (threadIdx.x < 8) {
        float v = sh[threadIdx.x];
        #pragma unroll
        for (int o = 4; o; o >>= 1) v += __shfl_down_sync(0xffu, v, o);
        if (threadIdx.x == 0) atomicAdd(out + z, v);
    }
}

// ternary {-1,0,+1} to bf16 (exact); scale applied in GEMM epilogue
__global__ void quant4(const float* __restrict__ w0, const float* __restrict__ w1,
                       const float* __restrict__ w2, const float* __restrict__ w3,
                       __nv_bfloat16* __restrict__ q0, __nv_bfloat16* __restrict__ q1,
                       __nv_bfloat16* __restrict__ q2, __nv_bfloat16* __restrict__ q3,
                       const float* __restrict__ sums, int n0, int n1, int n2, int n3) {
    int z = blockIdx.y;
    const float* w = z==0?w0 : z==1?w1 : z==2?w2 : w3;
    __nv_bfloat16* q = z==0?q0 : z==1?q1 : z==2?q2 : q3;
    int n = z==0?n0 : z==1?n1 : z==2?n2 : n3;
    float s = sums[z] / (float)n + 1e-8f;
    float inv = 1.0f / s;
    int n4 = n >> 2;
    for (int i = blockIdx.x*blockDim.x + threadIdx.x; i < n4; i += gridDim.x*blockDim.x) {
        float4 v = ((const float4*)w)[i];
        float t0 = fminf(1.f, fmaxf(-1.f, rintf(v.x * inv)));   // half-to-even
        float t1 = fminf(1.f, fmaxf(-1.f, rintf(v.y * inv)));
        float t2 = fminf(1.f, fmaxf(-1.f, rintf(v.z * inv)));
        float t3 = fminf(1.f, fmaxf(-1.f, rintf(v.w * inv)));
        __nv_bfloat162 p0 = __floats2bfloat162_rn(t0, t1);
        __nv_bfloat162 p1 = __floats2bfloat162_rn(t2, t3);
        uint2 o = { *(uint32_t*)&p0, *(uint32_t*)&p1 };
        ((uint2*)q)[i] = o;
    }
}

// dense fp32 -> bf16 hi/lo split (layer DEPTH-1)
__global__ void split4(const float* __restrict__ w0, const float* __restrict__ w1,
                       const float* __restrict__ w2, const float* __restrict__ w3,
                       __nv_bfloat16* __restrict__ h0, __nv_bfloat16* __restrict__ h1,
                       __nv_bfloat16* __restrict__ h2, __nv_bfloat16* __restrict__ h3,
                       __nv_bfloat16* __restrict__ l0, __nv_bfloat16* __restrict__ l1,
                       __nv_bfloat16* __restrict__ l2, __nv_bfloat16* __restrict__ l3,
                       int n0, int n1, int n2, int n3) {
    int z = blockIdx.y;
    const float* w = z==0?w0 : z==1?w1 : z==2?w2 : w3;
    __nv_bfloat16* hh = z==0?h0 : z==1?h1 : z==2?h2 : h3;
    __nv_bfloat16* ll = z==0?l0 : z==1?l1 : z==2?l2 : l3;
    int n4 = (z==0?n0 : z==1?n1 : z==2?n2 : n3) >> 2;
    for (int i = blockIdx.x*blockDim.x + threadIdx.x; i < n4; i += gridDim.x*blockDim.x) {
        float4 v = ((const float4*)w)[i];
        uint32_t h01, l01, h23, l23;
        split2(v.x, v.y, h01, l01);
        split2(v.z, v.w, h23, l23);
        uint2 ho = {h01, h23}, lo = {l01, l23};
        ((uint2*)hh)[i] = ho;
        ((uint2*)ll)[i] = lo;
    }
}

// ---------------- layernorm -> split bf16 (register-resident) ----------------
__device__ __forceinline__ float blockReduceSum(float v) {
    __shared__ float sh[33];
    __syncthreads();
    int lane = threadIdx.x & 31, wid = threadIdx.x >> 5;
    #pragma unroll
    for (int o = 16; o; o >>= 1) v += __shfl_down_sync(0xffffffffu, v, o);
    if (!lane) sh[wid] = v;
    __syncthreads();
    if (threadIdx.x < 8) {
        float t = sh[threadIdx.x];
        #pragma unroll
        for (int o = 4; o; o >>= 1) t += __shfl_down_sync(0xffu, t, o);
        if (!threadIdx.x) sh[32] = t;
    }
    __syncthreads();
    return sh[32];
}

__global__ void __launch_bounds__(256) ln_kernel(const float* __restrict__ x,
                                                 __nv_bfloat16* __restrict__ yh,
                                                 __nv_bfloat16* __restrict__ yl,
                                                 const float* __restrict__ g,
                                                 const float* __restrict__ b,
                                                 int width) {
    int t = threadIdx.x;
    int n4 = width >> 2;
    const float4* xr = (const float4*)(x + (size_t)blockIdx.x * width);
    float4 v[3];
    float s = 0.f;
    #pragma unroll
    for (int c = 0; c < 3; c++) {
        int i = t + c*256;
        if (i < n4) {
            v[c] = xr[i];
            s += v[c].x + v[c].y + v[c].z + v[c].w;
        }
    }
    float m = blockReduceSum(s) / (float)width;
    float v2 = 0.f;
    #pragma unroll
    for (int c = 0; c < 3; c++) {
        int i = t + c*256;
        if (i < n4) {
            float dx = v[c].x - m, dy = v[c].y - m, dz = v[c].z - m, dw = v[c].w - m;
            v2 += dx*dx + dy*dy + dz*dz + dw*dw;
        }
    }
    float var = blockReduceSum(v2) / (float)width;
    float r = rsqrtf(var + 1e-5f);
    uint2* yhr = (uint2*)(yh + (size_t)blockIdx.x * width);
    uint2* ylr = (uint2*)(yl + (size_t)blockIdx.x * width);
    #pragma unroll
    for (int c = 0; c < 3; c++) {
        int i = t + c*256;
        if (i < n4) {
            float4 gg = ((const float4*)g)[i];
            float4 bb = ((const float4*)b)[i];
            float o0 = (v[c].x - m) * r * gg.x + bb.x;
            float o1 = (v[c].y - m) * r * gg.y + bb.y;
            float o2 = (v[c].z - m) * r * gg.z + bb.z;
            float o3 = (v[c].w - m) * r * gg.w + bb.w;
            uint32_t h01, l01, h23, l23;
            split2(o0, o1, h01, l01);
            split2(o2, o3, h23, l23);
            uint2 ho = {h01, h23}, lo = {l01, l23};
            yhr[i] = ho;
            ylr[i] = lo;
        }
    }
}

// ---------------- bf16 tensor-core GEMM (3-stage cp.async, 32m x 64n warps) --
// C = s*(A @ W^T) + bias [+gelu] [+resid],  A = Ah + Al (bf16 split)
// CHAINS==2: W exact in bf16 (ternary). CHAINS==3: W split hi/lo.
#define GW 20            /* words per 32-elem K-slice row (16 + 4 pad) */
#define GT (128*GW)      /* words per array per stage */
#define GSMEM2 (3*3*GT*4)   /* 92160 B  (3 stages x {AH,AL,WH}) */
#define GSMEM3 (3*4*GT*4)   /* 122880 B (3 stages x {AH,AL,WH,WL}) */

template<int CHAINS, int EPI>
__global__ void __launch_bounds__(256,2) gemm_bf16(
    const uint32_t* __restrict__ AHg, const uint32_t* __restrict__ ALg,
    const uint32_t* __restrict__ WHg, const uint32_t* __restrict__ WLg,
    const float* __restrict__ sumptr, float wcount,
    const float* __restrict__ bias, const float* __restrict__ resid,
    float* __restrict__ C, int M, int N, int K)
{
    extern __shared__ uint32_t smw[];
    const int PS = (CHAINS + 1) * GT;     // words per stage
    int t = threadIdx.x, lane = t & 31, wid = t >> 5;
    int wm = wid & 3, wn = wid >> 2;      // 4x2 warp grid: 32m x 64n per warp
    int bm = blockIdx.y * 128, bn = blockIdx.x * 128;
    int Kw = K >> 1;
    float acc[2][8][4] = {};

    int crow = t >> 2, cwg = (t & 3) << 2;

    auto do_copy = [&](int slot, int kw) {
        uint32_t* S = smw + slot*PS;
        #pragma unroll
        for (int it = 0; it < 2; it++) {
            int row = it*64 + crow;
            cp_async16(S +        row*GW + cwg, AHg + (size_t)(bm+row)*Kw + kw + cwg);
            cp_async16(S +   GT + row*GW + cwg, ALg + (size_t)(bm+row)*Kw + kw + cwg);
            cp_async16(S + 2*GT + row*GW + cwg, WHg + (size_t)(bn+row)*Kw + kw + cwg);
            if (CHAINS == 3)
                cp_async16(S + 3*GT + row*GW + cwg, WLg + (size_t)(bn+row)*Kw + kw + cwg);
        }
        asm volatile("cp.async.commit_group;\n");
    };

    int nsteps = K >> 5;
    do_copy(0, 0);
    do_copy(1, 16);

    // ldmatrix lane mappings
    int lsub = lane >> 3, lrow = lane & 7;
    int lmrow = (lsub & 1) * 8 + lrow;       // A: row within m16 tile
    int lkoff = (lsub >> 1) * 4;             // A: word offset within k16
    int bl8 = lane & 7;                      // B: row within n8 tile
    int btile = lsub >> 1;                   // B: which n8 tile of the pair
    int bkh = (lsub & 1) * 4;                // B: k-half word offset

    for (int i = 0; i < nsteps; i++) {
        if (i + 1 < nsteps) asm volatile("cp.async.wait_group 1;\n");
        else                asm volatile("cp.async.wait_group 0;\n");
        __syncthreads();
        if (i + 2 < nsteps) do_copy((i + 2) % 3, (i + 2) * 16);

        uint32_t* S = smw + (i % 3) * PS;
        const uint32_t* AHs = S;
        const uint32_t* ALs = S + GT;
        const uint32_t* WHs = S + 2*GT;
        const uint32_t* WLs = S + 3*GT;

        #pragma unroll
        for (int g = 0; g < 2; g++) {           // two k16 groups in BK=32
            uint32_t bh[8][2], bl[8][2];
            #pragma unroll
            for (int p = 0; p < 4; p++) {       // 4 pairs of n8 tiles = 64 n
                int brow = wn*64 + p*16 + btile*8 + bl8;
                ldsm4(bh[2*p][0], bh[2*p][1], bh[2*p+1][0], bh[2*p+1][1],
                      WHs + brow*GW + g*8 + bkh);
                if (CHAINS == 3)
                    ldsm4(bl[2*p][0], bl[2*p][1], bl[2*p+1][0], bl[2*p+1][1],
                          WLs + brow*GW + g*8 + bkh);
            }
            #pragma unroll
            for (int ii = 0; ii < 2; ii++) {    // 2 m16 tiles = 32 m
                int mr = wm*32 + ii*16 + lmrow;
                int kc = g*8 + lkoff;
                uint32_t ah[4], al[4];
                ldsm4(ah[0], ah[1], ah[2], ah[3], AHs + mr*GW + kc);
                ldsm4(al[0], al[1], al[2], al[3], ALs + mr*GW + kc);
                #pragma unroll
                for (int j = 0; j < 8; j++) {
                    mma16(acc[ii][j], ah, bh[j]);
                    mma16(acc[ii][j], al, bh[j]);
                    if (CHAINS == 3) mma16(acc[ii][j], ah, bl[j]);
                }
            }
        }
    }

    float s = 1.0f;
    if (sumptr) s = sumptr[0] / wcount + 1e-8f;
    #pragma unroll
    for (int i = 0; i < 2; i++) {
        int r0 = bm + wm*32 + i*16 + (lane >> 2);
        #pragma unroll
        for (int j = 0; j < 8; j++) {
            int c0 = bn + wn*64 + j*8 + ((lane & 3) << 1);
            float v[4] = {acc[i][j][0]*s, acc[i][j][1]*s, acc[i][j][2]*s, acc[i][j][3]*s};
            if (bias) { v[0] += bias[c0]; v[1] += bias[c0+1]; v[2] += bias[c0]; v[3] += bias[c0+1]; }
            if (EPI == 1) {
                #pragma unroll
                for (int u = 0; u < 4; u++)
                    v[u] = v[u] * 0.5f * (1.0f + erff(v[u] * 0.70710678118654752f));
            }
            if (resid) {
                v[0] += resid[(size_t)r0*N + c0];     v[1] += resid[(size_t)r0*N + c0+1];
                v[2] += resid[(size_t)(r0+8)*N + c0]; v[3] += resid[(size_t)(r0+8)*N + c0+1];
            }
            C[(size_t)r0*N + c0]       = v[0]; C[(size_t)r0*N + c0+1]     = v[1];
            C[(size_t)(r0+8)*N + c0]   = v[2]; C[(size_t)(r0+8)*N + c0+1] = v[3];
        }
    }
}

// ---------------- tensor-core flash attention (split bf16) ------------------
#define AW 36    /* words per 64-dhead row (32 + 4 pad; 144B, 16B-aligned) */
#define AQW (128*AW)
#define AKW (64*AW)
#define AFSMEM ((2*AQW + 4*AKW)*4)   /* 73728 B */

__global__ void __launch_bounds__(256) attn_flash(const float* __restrict__ qkv,
                                                  float* __restrict__ O) {
    extern __shared__ uint32_t asw[];
    uint32_t* Qh = asw;
    uint32_t* Ql = asw + AQW;
    uint32_t* Kh = asw + 2*AQW;
    uint32_t* Kl = Kh + AKW;
    uint32_t* Vh = Kl + AKW;
    uint32_t* Vl = Vh + AKW;

    int t = threadIdx.x, lane = t & 31, wid = t >> 5;
    int bh = blockIdx.y;
    int b = bh / HEADS, hh = bh % HEADS;
    int m0 = blockIdx.x * 128;
    const float* Qp = qkv + (size_t)b * SEQ * NQKV + hh * DHEAD;
    const float* Kp = Qp + INNER;
    const float* Vp = Qp + 2*INNER;

    #pragma unroll
    for (int it = 0; it < 8; it++) {
        int idx = it*256 + t;
        int row = idx >> 4, d4 = (idx & 15) << 2;
        float4 q = *(const float4*)(Qp + (size_t)(m0+row)*NQKV + d4);
        q.x *= SCALE; q.y *= SCALE; q.z *= SCALE; q.w *= SCALE;
        uint32_t h0, l0, h1, l1;
        split2(q.x, q.y, h0, l0);
        split2(q.z, q.w, h1, l1);
        int w = row*AW + (d4 >> 1);
        Qh[w] = h0; Qh[w+1] = h1;
        Ql[w] = l0; Ql[w+1] = l1;
    }
    __syncthreads();

    int lsub = lane >> 3, lrow = lane & 7;
    int mr = wid*16 + (lsub & 1)*8 + lrow;
    int lk = (lsub >> 1) * 4;
    uint32_t qfh[4][4], qfl[4][4];
    #pragma unroll
    for (int g = 0; g < 4; g++) {
        ldsm4(qfh[g][0], qfh[g][1], qfh[g][2], qfh[g][3], Qh + mr*AW + g*8 + lk);
        ldsm4(qfl[g][0], qfl[g][1], qfl[g][2], qfl[g][3], Ql + mr*AW + g*8 + lk);
    }

    float mi0 = -1e30f, mi1 = -1e30f, li0 = 0.f, li1 = 0.f;
    float acc[8][4] = {};

    for (int kv = 0; kv < SEQ; kv += 64) {
        __syncthreads();
        #pragma unroll
        for (int it = 0; it < 4; it++) {
            int idx = it*256 + t;
            int row = idx >> 4, d4 = (idx & 15) << 2;
            int w = row*AW + (d4 >> 1);
            float4 k = *(const float4*)(Kp + (size_t)(kv+row)*NQKV + d4);
            uint32_t h0, l0, h1, l1;
            split2(k.x, k.y, h0, l0); split2(k.z, k.w, h1, l1);
            Kh[w] = h0; Kh[w+1] = h1; Kl[w] = l0; Kl[w+1] = l1;
            float4 v = *(const float4*)(Vp + (size_t)(kv+row)*NQKV + d4);
            split2(v.x, v.y, h0, l0); split2(v.z, v.w, h1, l1);
            Vh[w] = h0; Vh[w+1] = h1; Vl[w] = l0; Vl[w+1] = l1;
        }
        __syncthreads();

        float s[8][4] = {};
        int koff = ((lane >> 3) & 1) * 4;
        #pragma unroll
        for (int g = 0; g < 4; g++) {
            #pragma unroll
            for (int j = 0; j < 8; j++) {
                const uint32_t* pk = Kh + (j*8 + (lane & 7))*AW + g*8 + koff;
                uint32_t bhv[2], blv[2];
                ldsm2(bhv[0], bhv[1], pk);
                ldsm2(blv[0], blv[1], Kl + (j*8 + (lane & 7))*AW + g*8 + koff);
                mma16(s[j], qfh[g], bhv);
                mma16(s[j], qfl[g], bhv);
                mma16(s[j], qfh[g], blv);
            }
        }

        float rm0 = -1e30f, rm1 = -1e30f;
        #pragma unroll
        for (int j = 0; j < 8; j++) {
            rm0 = fmaxf(rm0, fmaxf(s[j][0], s[j][1]));
            rm1 = fmaxf(rm1, fmaxf(s[j][2], s[j][3]));
        }
        rm0 = fmaxf(rm0, __shfl_xor_sync(0xffffffffu, rm0, 1));
        rm0 = fmaxf(rm0, __shfl_xor_sync(0xffffffffu, rm0, 2));
        rm1 = fmaxf(rm1, __shfl_xor_sync(0xffffffffu, rm1, 1));
        rm1 = fmaxf(rm1, __shfl_xor_sync(0xffffffffu, rm1, 2));
        float mn0 = fmaxf(mi0, rm0), mn1 = fmaxf(mi1, rm1);
        float f0 = __expf(mi0 - mn0), f1 = __expf(mi1 - mn1);
        mi0 = mn0; mi1 = mn1;
        float sum0 = 0.f, sum1 = 0.f;
        #pragma unroll
        for (int j = 0; j < 8; j++) {
            s[j][0] = __expf(s[j][0] - mn0); s[j][1] = __expf(s[j][1] - mn0);
            s[j][2] = __expf(s[j][2] - mn1); s[j][3] = __expf(s[j][3] - mn1);
            sum0 += s[j][0] + s[j][1];
            sum1 += s[j][2] + s[j][3];
        }
        sum0 += __shfl_xor_sync(0xffffffffu, sum0, 1);
        sum0 += __shfl_xor_sync(0xffffffffu, sum0, 2);
        sum1 += __shfl_xor_sync(0xffffffffu, sum1, 1);
        sum1 += __shfl_xor_sync(0xffffffffu, sum1, 2);
        li0 = li0*f0 + sum0; li1 = li1*f1 + sum1;
        #pragma unroll
        for (int j = 0; j < 8; j++) {
            acc[j][0] *= f0; acc[j][1] *= f0;
            acc[j][2] *= f1; acc[j][3] *= f1;
        }

        #pragma unroll
        for (int g = 0; g < 4; g++) {
            uint32_t aph[4], apl[4];
            split2(s[2*g][0],   s[2*g][1],   aph[0], apl[0]);
            split2(s[2*g][2],   s[2*g][3],   aph[1], apl[1]);
            split2(s[2*g+1][0], s[2*g+1][1], aph[2], apl[2]);
            split2(s[2*g+1][2], s[2*g+1][3], aph[3], apl[3]);
            #pragma unroll
            for (int j = 0; j < 8; j++) {
                const uint32_t* pv = Vh + (g*16 + (lane & 15))*AW + j*4;
                uint32_t bhv[2], blv[2];
                ldsm2t(bhv[0], bhv[1], pv);
                ldsm2t(blv[0], blv[1], Vl + (g*16 + (lane & 15))*AW + j*4);
                mma16(acc[j], aph, bhv);
                mma16(acc[j], apl, bhv);
                mma16(acc[j], aph, blv);
            }
        }
    }

    float inv0 = 1.0f / li0, inv1 = 1.0f / li1;
    int r = m0 + wid*16 + (lane >> 2);
    #pragma unroll
    for (int j = 0; j < 8; j++) {
        int col = hh*DHEAD + j*8 + ((lane & 3) << 1);
        float2 o0 = {acc[j][0]*inv0, acc[j][1]*inv0};
        float2 o1 = {acc[j][2]*inv1, acc[j][3]*inv1};
        *(float2*)(O + ((size_t)b*SEQ + r)*INNER + col)     = o0;
        *(float2*)(O + ((size_t)b*SEQ + r + 8)*INNER + col) = o1;
    }
}

// ---------------- host driver -----------------------------------------------
extern "C" void kernel_launch(void* const* d_in, const int* in_sizes, int n_in,
                              void* d_out, int out_size) {
    const float* x    = (const float*)d_in[0];
    const float* ln1g = (const float*)d_in[1];
    const float* ln1b = (const float*)d_in[2];
    const float* Wqkv = (const float*)d_in[3];
    const float* ln2g = (const float*)d_in[4];
    const float* ln2b = (const float*)d_in[5];
    const float* Wo   = (const float*)d_in[6];
    const float* bo   = (const float*)d_in[7];
    const float* f1g  = (const float*)d_in[8];
    const float* f1b  = (const float*)d_in[9];
    const float* W1   = (const float*)d_in[10];
    const float* b1   = (const float*)d_in[11];
    const float* f2g  = (const float*)d_in[12];
    const float* f2b  = (const float*)d_in[13];
    const float* W2   = (const float*)d_in[14];
    const float* b2   = (const float*)d_in[15];
    float* h = (float*)d_out;

    float *qkv, *ob, *mlp, *scal;
    __nv_bfloat16 *ah, *al, *whq, *wlq, *who, *wlo, *wh1, *wl1, *wh2, *wl2;
    cudaGetSymbolAddress((void**)&qkv, g_qkv);
    cudaGetSymbolAddress((void**)&ob,  g_obuf);
    cudaGetSymbolAddress((void**)&mlp, g_mlp);
    cudaGetSymbolAddress((void**)&ah,  g_ah);
    cudaGetSymbolAddress((void**)&al,  g_al);
    cudaGetSymbolAddress((void**)&whq, g_whq);
    cudaGetSymbolAddress((void**)&wlq, g_wlq);
    cudaGetSymbolAddress((void**)&who, g_who);
    cudaGetSymbolAddress((void**)&wlo, g_wlo);
    cudaGetSymbolAddress((void**)&wh1, g_wh1);
    cudaGetSymbolAddress((void**)&wl1, g_wl1);
    cudaGetSymbolAddress((void**)&wh2, g_wh2);
    cudaGetSymbolAddress((void**)&wl2, g_wl2);
    cudaGetSymbolAddress((void**)&scal, g_scal);

    cudaFuncSetAttribute(gemm_bf16<2,0>, cudaFuncAttributeMaxDynamicSharedMemorySize, GSMEM2);
    cudaFuncSetAttribute(gemm_bf16<2,1>, cudaFuncAttributeMaxDynamicSharedMemorySize, GSMEM2);
    cudaFuncSetAttribute(gemm_bf16<3,0>, cudaFuncAttributeMaxDynamicSharedMemorySize, GSMEM3);
    cudaFuncSetAttribute(gemm_bf16<3,1>, cudaFuncAttributeMaxDynamicSharedMemorySize, GSMEM3);
    cudaFuncSetAttribute(attn_flash,     cudaFuncAttributeMaxDynamicSharedMemorySize, AFSMEM);

    cudaMemcpyAsync(h, x, sizeof(float)*(size_t)ROWS*DIMM, cudaMemcpyDeviceToDevice);

    const int nA = NQKV*DIMM, nO = DIMM*INNER, n1 = MLPD*DIMM, n2 = DIMM*MLPD;

    for (int l = 0; l < DEPTH; l++) {
        bool tern = (l < DEPTH - 1);
        if (tern) {
            cudaMemsetAsync(scal, 0, 4*sizeof(float));
            abs_sum4<<<dim3(160,4),256>>>(
                Wqkv + (size_t)l*nA, Wo + (size_t)l*nO, W1 + (size_t)l*n1, W2 + (size_t)l*n2,
                nA, nO, n1, n2, scal);
            quant4<<<dim3(160,4),256>>>(
                Wqkv + (size_t)l*nA, Wo + (size_t)l*nO, W1 + (size_t)l*n1, W2 + (size_t)l*n2,
                whq, who, wh1, wh2, scal, nA, nO, n1, n2);
        } else {
            split4<<<dim3(160,4),256>>>(
                Wqkv + (size_t)l*nA, Wo + (size_t)l*nO, W1 + (size_t)l*n1, W2 + (size_t)l*n2,
                whq, who, wh1, wh2, wlq, wlo, wl1, wl2, nA, nO, n1, n2);
        }

        // attention block
        ln_kernel<<<ROWS,256>>>(h, ah, al, ln1g + l*DIMM, ln1b + l*DIMM, DIMM);
        if (tern)
            gemm_bf16<2,0><<<dim3(NQKV/128, ROWS/128),256,GSMEM2>>>(
                (uint32_t*)ah, (uint32_t*)al, (uint32_t*)whq, nullptr,
                scal+0, (float)nA, nullptr, nullptr, qkv, ROWS, NQKV, DIMM);
        else
            gemm_bf16<3,0><<<dim3(NQKV/128, ROWS/128),256,GSMEM3>>>(
                (uint32_t*)ah, (uint32_t*)al, (uint32_t*)whq, (uint32_t*)wlq,
                nullptr, 1.0f, nullptr, nullptr, qkv, ROWS, NQKV, DIMM);
        attn_flash<<<dim3(SEQ/128, BB*HEADS),256,AFSMEM>>>(qkv, ob);
        ln_kernel<<<ROWS,256>>>(ob, ah, al, ln2g + l*INNER, ln2b + l*INNER, INNER);
        if (tern)
            gemm_bf16<2,0><<<dim3(DIMM/128, ROWS/128),256,GSMEM2>>>(
                (uint32_t*)ah, (uint32_t*)al, (uint32_t*)who, nullptr,
                scal+1, (float)nO, bo + l*DIMM, h, h, ROWS, DIMM, INNER);
        else
            gemm_bf16<3,0><<<dim3(DIMM/128, ROWS/128),256,GSMEM3>>>(
                (uint32_t*)ah, (uint32_t*)al, (uint32_t*)who, (uint32_t*)wlo,
                nullptr, 1.0f, bo + l*DIMM, h, h, ROWS, DIMM, INNER);

        // MLP block (GELU fused into FF1 epilogue)
        ln_kernel<<<ROWS,256>>>(h, ah, al, f1g + l*DIMM, f1b + l*DIMM, DIMM);
        if (tern)
            gemm_bf16<2,1><<<dim3(MLPD/128, ROWS/128),256,GSMEM2>>>(
                (uint32_t*)ah, (uint32_t*)al, (uint32_t*)wh1, nullptr,
                scal+2, (float)n1, b1 + l*MLPD, nullptr, mlp, ROWS, MLPD, DIMM);
        else
            gemm_bf16<3,1><<<dim3(MLPD/128, ROWS/128),256,GSMEM3>>>(
                (uint32_t*)ah, (uint32_t*)al, (uint32_t*)wh1, (uint32_t*)wl1,
                nullptr, 1.0f, b1 + l*MLPD, nullptr, mlp, ROWS, MLPD, DIMM);
        ln_kernel<<<ROWS,256>>>(mlp, ah, al, f2g + l*MLPD, f2b + l*MLPD, MLPD);
        if (tern)
            gemm_bf16<2,0><<<dim3(DIMM/128, ROWS/128),256,GSMEM2>>>(
                (uint32_t*)ah, (uint32_t*)al, (uint32_t*)wh2, nullptr,
                scal+3, (float)n2, b2 + l*DIMM, h, h, ROWS, DIMM, MLPD);
        else
            gemm_bf16<3,0><<<dim3(DIMM/128, ROWS/128),256,GSMEM3>>>(
                (uint32_t*)ah, (uint32_t*)al, (uint32_t*)wh2, (uint32_t*)wl2,
                nullptr, 1.0f, b2 + l*DIMM, h, h, ROWS, DIMM, MLPD);
    }
}

// round 12
// speedup vs baseline: 3.7285x; 1.0490x over previous
#include <cuda_runtime.h>
#include <cuda_bf16.h>
#include <math.h>
#include <stdint.h>

#define DIMM  768
#define HEADS 12
#define DHEAD 64
#define INNER 768
#define MLPD  3072
#define BB    8
#define SEQ   1024
#define ROWS  (BB*SEQ)   /* 8192 */
#define DEPTH 6
#define SCALE 0.125f     /* 64^-0.5 */
#define NQKV  (3*INNER)
#define QKVW  (NQKV/2)   /* words per row in split-bf16 qkv plane: 1152 */
#define QPLANE ((size_t)ROWS*QKVW)   /* words per hi/lo plane */

// ---------------- scratch (device globals: no allocations allowed) ----------
__device__ __align__(16) float g_qkv[(size_t)ROWS*NQKV];   // 2 bf16 planes (hi, lo)
__device__ __align__(16) float g_obuf[ROWS*INNER];
__device__ __align__(16) float g_mlp[(size_t)ROWS*MLPD];
__device__ __align__(16) __nv_bfloat16 g_ah[(size_t)ROWS*MLPD];   // LN out hi
__device__ __align__(16) __nv_bfloat16 g_al[(size_t)ROWS*MLPD];   // LN out lo
__device__ __align__(16) __nv_bfloat16 g_whq[NQKV*DIMM];
__device__ __align__(16) __nv_bfloat16 g_wlq[NQKV*DIMM];
__device__ __align__(16) __nv_bfloat16 g_who[DIMM*INNER];
__device__ __align__(16) __nv_bfloat16 g_wlo[DIMM*INNER];
__device__ __align__(16) __nv_bfloat16 g_wh1[MLPD*DIMM];
__device__ __align__(16) __nv_bfloat16 g_wl1[MLPD*DIMM];
__device__ __align__(16) __nv_bfloat16 g_wh2[DIMM*MLPD];
__device__ __align__(16) __nv_bfloat16 g_wl2[DIMM*MLPD];
__device__ float g_scal[4];

// ---------------- asm helpers ------------------------------------------------
__device__ __forceinline__ void cp_async16(void* smem, const void* gmem) {
    uint32_t s = (uint32_t)__cvta_generic_to_shared(smem);
    asm volatile("cp.async.cg.shared.global [%0], [%1], 16;\n" :: "r"(s), "l"(gmem));
}
__device__ __forceinline__ void ldsm4(uint32_t& a0, uint32_t& a1, uint32_t& a2,
                                      uint32_t& a3, const uint32_t* p) {
    uint32_t s = (uint32_t)__cvta_generic_to_shared(p);
    asm volatile("ldmatrix.sync.aligned.m8n8.x4.shared.b16 {%0,%1,%2,%3}, [%4];\n"
                 : "=r"(a0), "=r"(a1), "=r"(a2), "=r"(a3) : "r"(s));
}
__device__ __forceinline__ void ldsm2(uint32_t& a0, uint32_t& a1, const uint32_t* p) {
    uint32_t s = (uint32_t)__cvta_generic_to_shared(p);
    asm volatile("ldmatrix.sync.aligned.m8n8.x2.shared.b16 {%0,%1}, [%2];\n"
                 : "=r"(a0), "=r"(a1) : "r"(s));
}
__device__ __forceinline__ void ldsm2t(uint32_t& a0, uint32_t& a1, const uint32_t* p) {
    uint32_t s = (uint32_t)__cvta_generic_to_shared(p);
    asm volatile("ldmatrix.sync.aligned.m8n8.x2.trans.shared.b16 {%0,%1}, [%2];\n"
                 : "=r"(a0), "=r"(a1) : "r"(s));
}
__device__ __forceinline__ void mma16(float c[4], const uint32_t a[4], const uint32_t b[2]) {
    asm volatile(
        "mma.sync.aligned.m16n8k16.row.col.f32.bf16.bf16.f32 "
        "{%0,%1,%2,%3}, {%4,%5,%6,%7}, {%8,%9}, {%0,%1,%2,%3};\n"
        : "+f"(c[0]), "+f"(c[1]), "+f"(c[2]), "+f"(c[3])
        : "r"(a[0]), "r"(a[1]), "r"(a[2]), "r"(a[3]), "r"(b[0]), "r"(b[1]));
}
__device__ __forceinline__ void split2(float a, float b, uint32_t& hi, uint32_t& lo) {
    __nv_bfloat162 h = __floats2bfloat162_rn(a, b);
    hi = *reinterpret_cast<uint32_t*>(&h);
    float la = a - __bfloat162float(h.x);
    float lb = b - __bfloat162float(h.y);
    __nv_bfloat162 l = __floats2bfloat162_rn(la, lb);
    lo = *reinterpret_cast<uint32_t*>(&l);
}

// ---------------- batched abs-sum / quant / split (float4) ------------------
__global__ void abs_sum4(const float* __restrict__ w0, const float* __restrict__ w1,
                         const float* __restrict__ w2, const float* __restrict__ w3,
                         int n0, int n1, int n2, int n3, float* out) {
    int z = blockIdx.y;
    const float* w = z==0?w0 : z==1?w1 : z==2?w2 : w3;
    int n4 = (z==0?n0 : z==1?n1 : z==2?n2 : n3) >> 2;
    float s = 0.f;
    for (int i = blockIdx.x*blockDim.x + threadIdx.x; i < n4; i += gridDim.x*blockDim.x) {
        float4 v = ((const float4*)w)[i];
        s += fabsf(v.x) + fabsf(v.y) + fabsf(v.z) + fabsf(v.w);
    }
    #pragma unroll
    for (int o = 16; o; o >>= 1) s += __shfl_down_sync(0xffffffffu, s, o);
    __shared__ float sh[8];
    if ((threadIdx.x & 31) == 0) sh[threadIdx.x >> 5] = s;
    __syncthreads();
    if (threadIdx.x < 8) {
        float v = sh[threadIdx.x];
        #pragma unroll
        for (int o = 4; o; o >>= 1) v += __shfl_down_sync(0xffu, v, o);
        if (threadIdx.x == 0) atomicAdd(out + z, v);
    }
}

__global__ void quant4(const float* __restrict__ w0, const float* __restrict__ w1,
                       const float* __restrict__ w2, const float* __restrict__ w3,
                       __nv_bfloat16* __restrict__ q0, __nv_bfloat16* __restrict__ q1,
                       __nv_bfloat16* __restrict__ q2, __nv_bfloat16* __restrict__ q3,
                       const float* __restrict__ sums, int n0, int n1, int n2, int n3) {
    int z = blockIdx.y;
    const float* w = z==0?w0 : z==1?w1 : z==2?w2 : w3;
    __nv_bfloat16* q = z==0?q0 : z==1?q1 : z==2?q2 : q3;
    int n = z==0?n0 : z==1?n1 : z==2?n2 : n3;
    float s = sums[z] / (float)n + 1e-8f;
    float inv = 1.0f / s;
    int n4 = n >> 2;
    for (int i = blockIdx.x*blockDim.x + threadIdx.x; i < n4; i += gridDim.x*blockDim.x) {
        float4 v = ((const float4*)w)[i];
        float t0 = fminf(1.f, fmaxf(-1.f, rintf(v.x * inv)));   // half-to-even
        float t1 = fminf(1.f, fmaxf(-1.f, rintf(v.y * inv)));
        float t2 = fminf(1.f, fmaxf(-1.f, rintf(v.z * inv)));
        float t3 = fminf(1.f, fmaxf(-1.f, rintf(v.w * inv)));
        __nv_bfloat162 p0 = __floats2bfloat162_rn(t0, t1);
        __nv_bfloat162 p1 = __floats2bfloat162_rn(t2, t3);
        uint2 o = { *(uint32_t*)&p0, *(uint32_t*)&p1 };
        ((uint2*)q)[i] = o;
    }
}

__global__ void split4(const float* __restrict__ w0, const float* __restrict__ w1,
                       const float* __restrict__ w2, const float* __restrict__ w3,
                       __nv_bfloat16* __restrict__ h0, __nv_bfloat16* __restrict__ h1,
                       __nv_bfloat16* __restrict__ h2, __nv_bfloat16* __restrict__ h3,
                       __nv_bfloat16* __restrict__ l0, __nv_bfloat16* __restrict__ l1,
                       __nv_bfloat16* __restrict__ l2, __nv_bfloat16* __restrict__ l3,
                       int n0, int n1, int n2, int n3) {
    int z = blockIdx.y;
    const float* w = z==0?w0 : z==1?w1 : z==2?w2 : w3;
    __nv_bfloat16* hh = z==0?h0 : z==1?h1 : z==2?h2 : h3;
    __nv_bfloat16* ll = z==0?l0 : z==1?l1 : z==2?l2 : l3;
    int n4 = (z==0?n0 : z==1?n1 : z==2?n2 : n3) >> 2;
    for (int i = blockIdx.x*blockDim.x + threadIdx.x; i < n4; i += gridDim.x*blockDim.x) {
        float4 v = ((const float4*)w)[i];
        uint32_t h01, l01, h23, l23;
        split2(v.x, v.y, h01, l01);
        split2(v.z, v.w, h23, l23);
        uint2 ho = {h01, h23}, lo = {l01, l23};
        ((uint2*)hh)[i] = ho;
        ((uint2*)ll)[i] = lo;
    }
}

// ---------------- layernorm -> split bf16 (register-resident) ----------------
__device__ __forceinline__ float blockReduceSum(float v) {
    __shared__ float sh[33];
    __syncthreads();
    int lane = threadIdx.x & 31, wid = threadIdx.x >> 5;
    #pragma unroll
    for (int o = 16; o; o >>= 1) v += __shfl_down_sync(0xffffffffu, v, o);
    if (!lane) sh[wid] = v;
    __syncthreads();
    if (threadIdx.x < 8) {
        float t = sh[threadIdx.x];
        #pragma unroll
        for (int o = 4; o; o >>= 1) t += __shfl_down_sync(0xffu, t, o);
        if (!threadIdx.x) sh[32] = t;
    }
    __syncthreads();
    return sh[32];
}

__global__ void __launch_bounds__(256) ln_kernel(const float* __restrict__ x,
                                                 __nv_bfloat16* __restrict__ yh,
                                                 __nv_bfloat16* __restrict__ yl,
                                                 const float* __restrict__ g,
                                                 const float* __restrict__ b,
                                                 int width) {
    int t = threadIdx.x;
    int n4 = width >> 2;
    const float4* xr = (const float4*)(x + (size_t)blockIdx.x * width);
    float4 v[3];
    float s = 0.f;
    #pragma unroll
    for (int c = 0; c < 3; c++) {
        int i = t + c*256;
        if (i < n4) {
            v[c] = xr[i];
            s += v[c].x + v[c].y + v[c].z + v[c].w;
        }
    }
    float m = blockReduceSum(s) / (float)width;
    float v2 = 0.f;
    #pragma unroll
    for (int c = 0; c < 3; c++) {
        int i = t + c*256;
        if (i < n4) {
            float dx = v[c].x - m, dy = v[c].y - m, dz = v[c].z - m, dw = v[c].w - m;
            v2 += dx*dx + dy*dy + dz*dz + dw*dw;
        }
    }
    float var = blockReduceSum(v2) / (float)width;
    float r = rsqrtf(var + 1e-5f);
    uint2* yhr = (uint2*)(yh + (size_t)blockIdx.x * width);
    uint2* ylr = (uint2*)(yl + (size_t)blockIdx.x * width);
    #pragma unroll
    for (int c = 0; c < 3; c++) {
        int i = t + c*256;
        if (i < n4) {
            float4 gg = ((const float4*)g)[i];
            float4 bb = ((const float4*)b)[i];
            float o0 = (v[c].x - m) * r * gg.x + bb.x;
            float o1 = (v[c].y - m) * r * gg.y + bb.y;
            float o2 = (v[c].z - m) * r * gg.z + bb.z;
            float o3 = (v[c].w - m) * r * gg.w + bb.w;
            uint32_t h01, l01, h23, l23;
            split2(o0, o1, h01, l01);
            split2(o2, o3, h23, l23);
            uint2 ho = {h01, h23}, lo = {l01, l23};
            yhr[i] = ho;
            ylr[i] = lo;
        }
    }
}

// ---------------- bf16 tensor-core GEMM (3-stage cp.async) -------------------
// C = s*(A @ W^T) + bias [+gelu] [+resid]
// EPI: 0 = fp32 out, 1 = fp32 out + GELU, 2 = split-bf16 out (QKV; Q pre-scaled)
#define GW 20            /* words per 32-elem K-slice row (16 + 4 pad) */
#define GT (128*GW)      /* words per array per stage */
#define GSMEM2 (3*3*GT*4)   /* 92160 B  */
#define GSMEM3 (3*4*GT*4)   /* 122880 B */

template<int CHAINS, int EPI>
__global__ void __launch_bounds__(256,2) gemm_bf16(
    const uint32_t* __restrict__ AHg, const uint32_t* __restrict__ ALg,
    const uint32_t* __restrict__ WHg, const uint32_t* __restrict__ WLg,
    const float* __restrict__ sumptr, float wcount,
    const float* __restrict__ bias, const float* __restrict__ resid,
    float* __restrict__ C, int M, int N, int K)
{
    extern __shared__ uint32_t smw[];
    const int PS = (CHAINS + 1) * GT;
    int t = threadIdx.x, lane = t & 31, wid = t >> 5;
    int wm = wid & 3, wn = wid >> 2;      // 4x2 warp grid: 32m x 64n per warp
    int bm = blockIdx.y * 128, bn = blockIdx.x * 128;
    int Kw = K >> 1;
    float acc[2][8][4] = {};

    int crow = t >> 2, cwg = (t & 3) << 2;

    auto do_copy = [&](int slot, int kw) {
        uint32_t* S = smw + slot*PS;
        #pragma unroll
        for (int it = 0; it < 2; it++) {
            int row = it*64 + crow;
            cp_async16(S +        row*GW + cwg, AHg + (size_t)(bm+row)*Kw + kw + cwg);
            cp_async16(S +   GT + row*GW + cwg, ALg + (size_t)(bm+row)*Kw + kw + cwg);
            cp_async16(S + 2*GT + row*GW + cwg, WHg + (size_t)(bn+row)*Kw + kw + cwg);
            if (CHAINS == 3)
                cp_async16(S + 3*GT + row*GW + cwg, WLg + (size_t)(bn+row)*Kw + kw + cwg);
        }
        asm volatile("cp.async.commit_group;\n");
    };

    int nsteps = K >> 5;
    do_copy(0, 0);
    do_copy(1, 16);

    int lsub = lane >> 3, lrow = lane & 7;
    int lmrow = (lsub & 1) * 8 + lrow;
    int lkoff = (lsub >> 1) * 4;
    int bl8 = lane & 7;
    int btile = lsub >> 1;
    int bkh = (lsub & 1) * 4;

    for (int i = 0; i < nsteps; i++) {
        if (i + 1 < nsteps) asm volatile("cp.async.wait_group 1;\n");
        else                asm volatile("cp.async.wait_group 0;\n");
        __syncthreads();
        if (i + 2 < nsteps) do_copy((i + 2) % 3, (i + 2) * 16);

        uint32_t* S = smw + (i % 3) * PS;
        const uint32_t* AHs = S;
        const uint32_t* ALs = S + GT;
        const uint32_t* WHs = S + 2*GT;
        const uint32_t* WLs = S + 3*GT;

        #pragma unroll
        for (int g = 0; g < 2; g++) {
            uint32_t bh[8][2], bl[8][2];
            #pragma unroll
            for (int p = 0; p < 4; p++) {
                int brow = wn*64 + p*16 + btile*8 + bl8;
                ldsm4(bh[2*p][0], bh[2*p][1], bh[2*p+1][0], bh[2*p+1][1],
                      WHs + brow*GW + g*8 + bkh);
                if (CHAINS == 3)
                    ldsm4(bl[2*p][0], bl[2*p][1], bl[2*p+1][0], bl[2*p+1][1],
                          WLs + brow*GW + g*8 + bkh);
            }
            uint32_t ah[2][4], al[2][4];
            #pragma unroll
            for (int ii = 0; ii < 2; ii++) {
                int mr = wm*32 + ii*16 + lmrow;
                int kc = g*8 + lkoff;
                ldsm4(ah[ii][0], ah[ii][1], ah[ii][2], ah[ii][3], AHs + mr*GW + kc);
                ldsm4(al[ii][0], al[ii][1], al[ii][2], al[ii][3], ALs + mr*GW + kc);
            }
            // hi chain first (16 independent accumulators), then lo chain
            #pragma unroll
            for (int ii = 0; ii < 2; ii++)
                #pragma unroll
                for (int j = 0; j < 8; j++)
                    mma16(acc[ii][j], ah[ii], bh[j]);
            #pragma unroll
            for (int ii = 0; ii < 2; ii++)
                #pragma unroll
                for (int j = 0; j < 8; j++)
                    mma16(acc[ii][j], al[ii], bh[j]);
            if (CHAINS == 3) {
                #pragma unroll
                for (int ii = 0; ii < 2; ii++)
                    #pragma unroll
                    for (int j = 0; j < 8; j++)
                        mma16(acc[ii][j], ah[ii], bl[j]);
            }
        }
    }

    float s = 1.0f;
    if (sumptr) s = sumptr[0] / wcount + 1e-8f;
    #pragma unroll
    for (int i = 0; i < 2; i++) {
        int r0 = bm + wm*32 + i*16 + (lane >> 2);
        #pragma unroll
        for (int j = 0; j < 8; j++) {
            int c0 = bn + wn*64 + j*8 + ((lane & 3) << 1);
            float v[4] = {acc[i][j][0]*s, acc[i][j][1]*s, acc[i][j][2]*s, acc[i][j][3]*s};
            if (bias) { v[0] += bias[c0]; v[1] += bias[c0+1]; v[2] += bias[c0]; v[3] += bias[c0+1]; }
            if (EPI == 1) {
                #pragma unroll
                for (int u = 0; u < 4; u++)
                    v[u] = v[u] * 0.5f * (1.0f + erff(v[u] * 0.70710678118654752f));
            }
            if (resid) {
                v[0] += resid[(size_t)r0*N + c0];     v[1] += resid[(size_t)r0*N + c0+1];
                v[2] += resid[(size_t)(r0+8)*N + c0]; v[3] += resid[(size_t)(r0+8)*N + c0+1];
            }
            if (EPI == 2) {
                // split-bf16 output, Q columns pre-scaled
                float mult = (c0 < INNER) ? SCALE : 1.0f;
                uint32_t* Ch = (uint32_t*)C;
                uint32_t* Cl = Ch + QPLANE;
                uint32_t h01, l01, h23, l23;
                split2(v[0]*mult, v[1]*mult, h01, l01);
                split2(v[2]*mult, v[3]*mult, h23, l23);
                int cw = c0 >> 1, Nw = N >> 1;
                Ch[(size_t)r0*Nw + cw]     = h01; Cl[(size_t)r0*Nw + cw]     = l01;
                Ch[(size_t)(r0+8)*Nw + cw] = h23; Cl[(size_t)(r0+8)*Nw + cw] = l23;
            } else {
                C[(size_t)r0*N + c0]       = v[0]; C[(size_t)r0*N + c0+1]     = v[1];
                C[(size_t)(r0+8)*N + c0]   = v[2]; C[(size_t)(r0+8)*N + c0+1] = v[3];
            }
        }
    }
}

// ---------------- tensor-core flash attention (pre-split bf16 input) ---------
#define AW 36    /* words per 64-dhead row (32 + 4 pad; 144B, 16B-aligned) */
#define AQW (128*AW)
#define AKW (64*AW)
#define AFSMEM ((2*AQW + 4*AKW)*4)   /* 73728 B */

__global__ void __launch_bounds__(256) attn_flash(const uint32_t* __restrict__ qh,
                                                  const uint32_t* __restrict__ ql,
                                                  float* __restrict__ O) {
    extern __shared__ uint32_t asw[];
    uint32_t* Qh = asw;
    uint32_t* Ql = asw + AQW;
    uint32_t* Kh = asw + 2*AQW;
    uint32_t* Kl = Kh + AKW;
    uint32_t* Vh = Kl + AKW;
    uint32_t* Vl = Vh + AKW;

    int t = threadIdx.x, lane = t & 31, wid = t >> 5;
    int bh = blockIdx.y;
    int b = bh / HEADS, hh = bh % HEADS;
    int m0 = blockIdx.x * 128;
    int hw = hh * (DHEAD/2);             // 32-word head offset

    // ---- Q load: pure copy of pre-split bf16 (128 rows x 32 words x2 planes)
    #pragma unroll
    for (int it = 0; it < 4; it++) {
        int idx = it*256 + t;            // 0..1023
        int row = idx >> 3, wg = (idx & 7) << 2;
        size_t src = (size_t)(b*SEQ + m0 + row) * QKVW + hw + wg;
        *(uint4*)(Qh + row*AW + wg) = *(const uint4*)(qh + src);
        *(uint4*)(Ql + row*AW + wg) = *(const uint4*)(ql + src);
    }
    __syncthreads();

    int lsub = lane >> 3, lrow = lane & 7;
    int mr = wid*16 + (lsub & 1)*8 + lrow;
    int lk = (lsub >> 1) * 4;
    uint32_t qfh[4][4], qfl[4][4];
    #pragma unroll
    for (int g = 0; g < 4; g++) {
        ldsm4(qfh[g][0], qfh[g][1], qfh[g][2], qfh[g][3], Qh + mr*AW + g*8 + lk);
        ldsm4(qfl[g][0], qfl[g][1], qfl[g][2], qfl[g][3], Ql + mr*AW + g*8 + lk);
    }

    float mi0 = -1e30f, mi1 = -1e30f, li0 = 0.f, li1 = 0.f;
    float acc[8][4] = {};

    for (int kv = 0; kv < SEQ; kv += 64) {
        __syncthreads();
        // ---- K/V tile copy (64 rows x 32 words x 4 planes)
        #pragma unroll
        for (int it = 0; it < 2; it++) {
            int idx = it*256 + t;        // 0..511
            int row = idx >> 3, wg = (idx & 7) << 2;
            size_t rb = (size_t)(b*SEQ + kv + row) * QKVW;
            int w = row*AW + wg;
            *(uint4*)(Kh + w) = *(const uint4*)(qh + rb + (INNER/2)   + hw + wg);
            *(uint4*)(Kl + w) = *(const uint4*)(ql + rb + (INNER/2)   + hw + wg);
            *(uint4*)(Vh + w) = *(const uint4*)(qh + rb + INNER       + hw + wg);
            *(uint4*)(Vl + w) = *(const uint4*)(ql + rb + INNER       + hw + wg);
        }
        __syncthreads();

        float s[8][4] = {};
        int koff = ((lane >> 3) & 1) * 4;
        #pragma unroll
        for (int g = 0; g < 4; g++) {
            #pragma unroll
            for (int j = 0; j < 8; j++) {
                const uint32_t* pk = Kh + (j*8 + (lane & 7))*AW + g*8 + koff;
                uint32_t bhv[2], blv[2];
                ldsm2(bhv[0], bhv[1], pk);
                ldsm2(blv[0], blv[1], Kl + (j*8 + (lane & 7))*AW + g*8 + koff);
                mma16(s[j], qfh[g], bhv);
                mma16(s[j], qfl[g], bhv);
                mma16(s[j], qfh[g], blv);
            }
        }

        float rm0 = -1e30f, rm1 = -1e30f;
        #pragma unroll
        for (int j = 0; j < 8; j++) {
            rm0 = fmaxf(rm0, fmaxf(s[j][0], s[j][1]));
            rm1 = fmaxf(rm1, fmaxf(s[j][2], s[j][3]));
        }
        rm0 = fmaxf(rm0, __shfl_xor_sync(0xffffffffu, rm0, 1));
        rm0 = fmaxf(rm0, __shfl_xor_sync(0xffffffffu, rm0, 2));
        rm1 = fmaxf(rm1, __shfl_xor_sync(0xffffffffu, rm1, 1));
        rm1 = fmaxf(rm1, __shfl_xor_sync(0xffffffffu, rm1, 2));
        float mn0 = fmaxf(mi0, rm0), mn1 = fmaxf(mi1, rm1);
        float f0 = __expf(mi0 - mn0), f1 = __expf(mi1 - mn1);
        mi0 = mn0; mi1 = mn1;
        float sum0 = 0.f, sum1 = 0.f;
        #pragma unroll
        for (int j = 0; j < 8; j++) {
            s[j][0] = __expf(s[j][0] - mn0); s[j][1] = __expf(s[j][1] - mn0);
            s[j][2] = __expf(s[j][2] - mn1); s[j][3] = __expf(s[j][3] - mn1);
            sum0 += s[j][0] + s[j][1];
            sum1 += s[j][2] + s[j][3];
        }
        sum0 += __shfl_xor_sync(0xffffffffu, sum0, 1);
        sum0 += __shfl_xor_sync(0xffffffffu, sum0, 2);
        sum1 += __shfl_xor_sync(0xffffffffu, sum1, 1);
        sum1 += __shfl_xor_sync(0xffffffffu, sum1, 2);
        li0 = li0*f0 + sum0; li1 = li1*f1 + sum1;
        #pragma unroll
        for (int j = 0; j < 8; j++) {
            acc[j][0] *= f0; acc[j][1] *= f0;
            acc[j][2] *= f1; acc[j][3] *= f1;
        }

        #pragma unroll
        for (int g = 0; g < 4; g++) {
            uint32_t aph[4], apl[4];
            split2(s[2*g][0],   s[2*g][1],   aph[0], apl[0]);
            split2(s[2*g][2],   s[2*g][3],   aph[1], apl[1]);
            split2(s[2*g+1][0], s[2*g+1][1], aph[2], apl[2]);
            split2(s[2*g+1][2], s[2*g+1][3], aph[3], apl[3]);
            #pragma unroll
            for (int j = 0; j < 8; j++) {
                const uint32_t* pv = Vh + (g*16 + (lane & 15))*AW + j*4;
                uint32_t bhv[2], blv[2];
                ldsm2t(bhv[0], bhv[1], pv);
                ldsm2t(blv[0], blv[1], Vl + (g*16 + (lane & 15))*AW + j*4);
                mma16(acc[j], aph, bhv);
                mma16(acc[j], apl, bhv);
                mma16(acc[j], aph, blv);
            }
        }
    }

    float inv0 = 1.0f / li0, inv1 = 1.0f / li1;
    int r = m0 + wid*16 + (lane >> 2);
    #pragma unroll
    for (int j = 0; j < 8; j++) {
        int col = hh*DHEAD + j*8 + ((lane & 3) << 1);
        float2 o0 = {acc[j][0]*inv0, acc[j][1]*inv0};
        float2 o1 = {acc[j][2]*inv1, acc[j][3]*inv1};
        *(float2*)(O + ((size_t)b*SEQ + r)*INNER + col)     = o0;
        *(float2*)(O + ((size_t)b*SEQ + r + 8)*INNER + col) = o1;
    }
}

// ---------------- host driver -----------------------------------------------
extern "C" void kernel_launch(void* const* d_in, const int* in_sizes, int n_in,
                              void* d_out, int out_size) {
    const float* x    = (const float*)d_in[0];
    const float* ln1g = (const float*)d_in[1];
    const float* ln1b = (const float*)d_in[2];
    const float* Wqkv = (const float*)d_in[3];
    const float* ln2g = (const float*)d_in[4];
    const float* ln2b = (const float*)d_in[5];
    const float* Wo   = (const float*)d_in[6];
    const float* bo   = (const float*)d_in[7];
    const float* f1g  = (const float*)d_in[8];
    const float* f1b  = (const float*)d_in[9];
    const float* W1   = (const float*)d_in[10];
    const float* b1   = (const float*)d_in[11];
    const float* f2g  = (const float*)d_in[12];
    const float* f2b  = (const float*)d_in[13];
    const float* W2   = (const float*)d_in[14];
    const float* b2   = (const float*)d_in[15];
    float* h = (float*)d_out;

    float *qkv, *ob, *mlp, *scal;
    __nv_bfloat16 *ah, *al, *whq, *wlq, *who, *wlo, *wh1, *wl1, *wh2, *wl2;
    cudaGetSymbolAddress((void**)&qkv, g_qkv);
    cudaGetSymbolAddress((void**)&ob,  g_obuf);
    cudaGetSymbolAddress((void**)&mlp, g_mlp);
    cudaGetSymbolAddress((void**)&ah,  g_ah);
    cudaGetSymbolAddress((void**)&al,  g_al);
    cudaGetSymbolAddress((void**)&whq, g_whq);
    cudaGetSymbolAddress((void**)&wlq, g_wlq);
    cudaGetSymbolAddress((void**)&who, g_who);
    cudaGetSymbolAddress((void**)&wlo, g_wlo);
    cudaGetSymbolAddress((void**)&wh1, g_wh1);
    cudaGetSymbolAddress((void**)&wl1, g_wl1);
    cudaGetSymbolAddress((void**)&wh2, g_wh2);
    cudaGetSymbolAddress((void**)&wl2, g_wl2);
    cudaGetSymbolAddress((void**)&scal, g_scal);

    cudaFuncSetAttribute(gemm_bf16<2,0>, cudaFuncAttributeMaxDynamicSharedMemorySize, GSMEM2);
    cudaFuncSetAttribute(gemm_bf16<2,1>, cudaFuncAttributeMaxDynamicSharedMemorySize, GSMEM2);
    cudaFuncSetAttribute(gemm_bf16<2,2>, cudaFuncAttributeMaxDynamicSharedMemorySize, GSMEM2);
    cudaFuncSetAttribute(gemm_bf16<3,0>, cudaFuncAttributeMaxDynamicSharedMemorySize, GSMEM3);
    cudaFuncSetAttribute(gemm_bf16<3,1>, cudaFuncAttributeMaxDynamicSharedMemorySize, GSMEM3);
    cudaFuncSetAttribute(gemm_bf16<3,2>, cudaFuncAttributeMaxDynamicSharedMemorySize, GSMEM3);
    cudaFuncSetAttribute(attn_flash,     cudaFuncAttributeMaxDynamicSharedMemorySize, AFSMEM);

    cudaMemcpyAsync(h, x, sizeof(float)*(size_t)ROWS*DIMM, cudaMemcpyDeviceToDevice);

    const int nA = NQKV*DIMM, nO = DIMM*INNER, n1 = MLPD*DIMM, n2 = DIMM*MLPD;

    for (int l = 0; l < DEPTH; l++) {
        bool tern = (l < DEPTH - 1);
        if (tern) {
            cudaMemsetAsync(scal, 0, 4*sizeof(float));
            abs_sum4<<<dim3(160,4),256>>>(
                Wqkv + (size_t)l*nA, Wo + (size_t)l*nO, W1 + (size_t)l*n1, W2 + (size_t)l*n2,
                nA, nO, n1, n2, scal);
            quant4<<<dim3(160,4),256>>>(
                Wqkv + (size_t)l*nA, Wo + (size_t)l*nO, W1 + (size_t)l*n1, W2 + (size_t)l*n2,
                whq, who, wh1, wh2, scal, nA, nO, n1, n2);
        } else {
            split4<<<dim3(160,4),256>>>(
                Wqkv + (size_t)l*nA, Wo + (size_t)l*nO, W1 + (size_t)l*n1, W2 + (size_t)l*n2,
                whq, who, wh1, wh2, wlq, wlo, wl1, wl2, nA, nO, n1, n2);
        }

        // attention block (QKV gemm emits pre-split, Q pre-scaled bf16)
        ln_kernel<<<ROWS,256>>>(h, ah, al, ln1g + l*DIMM, ln1b + l*DIMM, DIMM);
        if (tern)
            gemm_bf16<2,2><<<dim3(NQKV/128, ROWS/128),256,GSMEM2>>>(
                (uint32_t*)ah, (uint32_t*)al, (uint32_t*)whq, nullptr,
                scal+0, (float)nA, nullptr, nullptr, qkv, ROWS, NQKV, DIMM);
        else
            gemm_bf16<3,2><<<dim3(NQKV/128, ROWS/128),256,GSMEM3>>>(
                (uint32_t*)ah, (uint32_t*)al, (uint32_t*)whq, (uint32_t*)wlq,
                nullptr, 1.0f, nullptr, nullptr, qkv, ROWS, NQKV, DIMM);
        attn_flash<<<dim3(SEQ/128, BB*HEADS),256,AFSMEM>>>(
            (uint32_t*)qkv, (uint32_t*)qkv + QPLANE, ob);
        ln_kernel<<<ROWS,256>>>(ob, ah, al, ln2g + l*INNER, ln2b + l*INNER, INNER);
        if (tern)
            gemm_bf16<2,0><<<dim3(DIMM/128, ROWS/128),256,GSMEM2>>>(
                (uint32_t*)ah, (uint32_t*)al, (uint32_t*)who, nullptr,
                scal+1, (float)nO, bo + l*DIMM, h, h, ROWS, DIMM, INNER);
        else
            gemm_bf16<3,0><<<dim3(DIMM/128, ROWS/128),256,GSMEM3>>>(
                (uint32_t*)ah, (uint32_t*)al, (uint32_t*)who, (uint32_t*)wlo,
                nullptr, 1.0f, bo + l*DIMM, h, h, ROWS, DIMM, INNER);

        // MLP block (GELU fused into FF1 epilogue)
        ln_kernel<<<ROWS,256>>>(h, ah, al, f1g + l*DIMM, f1b + l*DIMM, DIMM);
        if (tern)
            gemm_bf16<2,1><<<dim3(MLPD/128, ROWS/128),256,GSMEM2>>>(
                (uint32_t*)ah, (uint32_t*)al, (uint32_t*)wh1, nullptr,
                scal+2, (float)n1, b1 + l*MLPD, nullptr, mlp, ROWS, MLPD, DIMM);
        else
            gemm_bf16<3,1><<<dim3(MLPD/128, ROWS/128),256,GSMEM3>>>(
                (uint32_t*)ah, (uint32_t*)al, (uint32_t*)wh1, (uint32_t*)wl1,
                nullptr, 1.0f, b1 + l*MLPD, nullptr, mlp, ROWS, MLPD, DIMM);
        ln_kernel<<<ROWS,256>>>(mlp, ah, al, f2g + l*MLPD, f2b + l*MLPD, MLPD);
        if (tern)
            gemm_bf16<2,0><<<dim3(DIMM/128, ROWS/128),256,GSMEM2>>>(
                (uint32_t*)ah, (uint32_t*)al, (uint32_t*)wh2, nullptr,
                scal+3, (float)n2, b2 + l*DIMM, h, h, ROWS, DIMM, MLPD);
        else
            gemm_bf16<3,0><<<dim3(DIMM/128, ROWS/128),256,GSMEM3>>>(
                (uint32_t*)ah, (uint32_t*)al, (uint32_t*)wh2, (uint32_t*)wl2,
                nullptr, 1.0f, b2 + l*DIMM, h, h, ROWS, DIMM, MLPD);
    }
}

// round 13
// speedup vs baseline: 4.0417x; 1.0840x over previous
#include <cuda_runtime.h>
#include <cuda_bf16.h>
#include <math.h>
#include <stdint.h>

#define DIMM  768
#define HEADS 12
#define DHEAD 64
#define INNER 768
#define MLPD  3072
#define BB    8
#define SEQ   1024
#define ROWS  (BB*SEQ)   /* 8192 */
#define DEPTH 6
#define SCALE 0.125f     /* 64^-0.5 */
#define NQKV  (3*INNER)
#define QKVW  (NQKV/2)   /* words per row in split-bf16 qkv plane: 1152 */
#define QPLANE ((size_t)ROWS*QKVW)   /* words per hi/lo plane */

// ---------------- scratch (device globals: no allocations allowed) ----------
__device__ __align__(16) float g_qkv[(size_t)ROWS*NQKV];   // 2 bf16 planes (hi, lo)
__device__ __align__(16) float g_obuf[ROWS*INNER];
__device__ __align__(16) float g_mlp[(size_t)ROWS*MLPD];
__device__ __align__(16) __nv_bfloat16 g_ah[(size_t)ROWS*MLPD];   // LN out hi
__device__ __align__(16) __nv_bfloat16 g_al[(size_t)ROWS*MLPD];   // LN out lo
__device__ __align__(16) __nv_bfloat16 g_whq[NQKV*DIMM];
__device__ __align__(16) __nv_bfloat16 g_wlq[NQKV*DIMM];
__device__ __align__(16) __nv_bfloat16 g_who[DIMM*INNER];
__device__ __align__(16) __nv_bfloat16 g_wlo[DIMM*INNER];
__device__ __align__(16) __nv_bfloat16 g_wh1[MLPD*DIMM];
__device__ __align__(16) __nv_bfloat16 g_wl1[MLPD*DIMM];
__device__ __align__(16) __nv_bfloat16 g_wh2[DIMM*MLPD];
__device__ __align__(16) __nv_bfloat16 g_wl2[DIMM*MLPD];
__device__ float g_scal[4];

// ---------------- asm helpers ------------------------------------------------
__device__ __forceinline__ void cp_async16(void* smem, const void* gmem) {
    uint32_t s = (uint32_t)__cvta_generic_to_shared(smem);
    asm volatile("cp.async.cg.shared.global [%0], [%1], 16;\n" :: "r"(s), "l"(gmem));
}
__device__ __forceinline__ void ldsm4(uint32_t& a0, uint32_t& a1, uint32_t& a2,
                                      uint32_t& a3, const uint32_t* p) {
    uint32_t s = (uint32_t)__cvta_generic_to_shared(p);
    asm volatile("ldmatrix.sync.aligned.m8n8.x4.shared.b16 {%0,%1,%2,%3}, [%4];\n"
                 : "=r"(a0), "=r"(a1), "=r"(a2), "=r"(a3) : "r"(s));
}
__device__ __forceinline__ void ldsm2(uint32_t& a0, uint32_t& a1, const uint32_t* p) {
    uint32_t s = (uint32_t)__cvta_generic_to_shared(p);
    asm volatile("ldmatrix.sync.aligned.m8n8.x2.shared.b16 {%0,%1}, [%2];\n"
                 : "=r"(a0), "=r"(a1) : "r"(s));
}
__device__ __forceinline__ void ldsm2t(uint32_t& a0, uint32_t& a1, const uint32_t* p) {
    uint32_t s = (uint32_t)__cvta_generic_to_shared(p);
    asm volatile("ldmatrix.sync.aligned.m8n8.x2.trans.shared.b16 {%0,%1}, [%2];\n"
                 : "=r"(a0), "=r"(a1) : "r"(s));
}
__device__ __forceinline__ void mma16(float c[4], const uint32_t a[4], const uint32_t b[2]) {
    asm volatile(
        "mma.sync.aligned.m16n8k16.row.col.f32.bf16.bf16.f32 "
        "{%0,%1,%2,%3}, {%4,%5,%6,%7}, {%8,%9}, {%0,%1,%2,%3};\n"
        : "+f"(c[0]), "+f"(c[1]), "+f"(c[2]), "+f"(c[3])
        : "r"(a[0]), "r"(a[1]), "r"(a[2]), "r"(a[3]), "r"(b[0]), "r"(b[1]));
}
__device__ __forceinline__ void split2(float a, float b, uint32_t& hi, uint32_t& lo) {
    __nv_bfloat162 h = __floats2bfloat162_rn(a, b);
    hi = *reinterpret_cast<uint32_t*>(&h);
    float la = a - __bfloat162float(h.x);
    float lb = b - __bfloat162float(h.y);
    __nv_bfloat162 l = __floats2bfloat162_rn(la, lb);
    lo = *reinterpret_cast<uint32_t*>(&l);
}

// ---------------- batched abs-sum / quant / split (float4) ------------------
__global__ void abs_sum4(const float* __restrict__ w0, const float* __restrict__ w1,
                         const float* __restrict__ w2, const float* __restrict__ w3,
                         int n0, int n1, int n2, int n3, float* out) {
    int z = blockIdx.y;
    const float* w = z==0?w0 : z==1?w1 : z==2?w2 : w3;
    int n4 = (z==0?n0 : z==1?n1 : z==2?n2 : n3) >> 2;
    float s = 0.f;
    for (int i = blockIdx.x*blockDim.x + threadIdx.x; i < n4; i += gridDim.x*blockDim.x) {
        float4 v = ((const float4*)w)[i];
        s += fabsf(v.x) + fabsf(v.y) + fabsf(v.z) + fabsf(v.w);
    }
    #pragma unroll
    for (int o = 16; o; o >>= 1) s += __shfl_down_sync(0xffffffffu, s, o);
    __shared__ float sh[8];
    if ((threadIdx.x & 31) == 0) sh[threadIdx.x >> 5] = s;
    __syncthreads();
    if (threadIdx.x < 8) {
        float v = sh[threadIdx.x];
        #pragma unroll
        for (int o = 4; o; o >>= 1) v += __shfl_down_sync(0xffu, v, o);
        if (threadIdx.x == 0) atomicAdd(out + z, v);
    }
}

__global__ void quant4(const float* __restrict__ w0, const float* __restrict__ w1,
                       const float* __restrict__ w2, const float* __restrict__ w3,
                       __nv_bfloat16* __restrict__ q0, __nv_bfloat16* __restrict__ q1,
                       __nv_bfloat16* __restrict__ q2, __nv_bfloat16* __restrict__ q3,
                       const float* __restrict__ sums, int n0, int n1, int n2, int n3) {
    int z = blockIdx.y;
    const float* w = z==0?w0 : z==1?w1 : z==2?w2 : w3;
    __nv_bfloat16* q = z==0?q0 : z==1?q1 : z==2?q2 : q3;
    int n = z==0?n0 : z==1?n1 : z==2?n2 : n3;
    float s = sums[z] / (float)n + 1e-8f;
    float inv = 1.0f / s;
    int n4 = n >> 2;
    for (int i = blockIdx.x*blockDim.x + threadIdx.x; i < n4; i += gridDim.x*blockDim.x) {
        float4 v = ((const float4*)w)[i];
        float t0 = fminf(1.f, fmaxf(-1.f, rintf(v.x * inv)));   // half-to-even
        float t1 = fminf(1.f, fmaxf(-1.f, rintf(v.y * inv)));
        float t2 = fminf(1.f, fmaxf(-1.f, rintf(v.z * inv)));
        float t3 = fminf(1.f, fmaxf(-1.f, rintf(v.w * inv)));
        __nv_bfloat162 p0 = __floats2bfloat162_rn(t0, t1);
        __nv_bfloat162 p1 = __floats2bfloat162_rn(t2, t3);
        uint2 o = { *(uint32_t*)&p0, *(uint32_t*)&p1 };
        ((uint2*)q)[i] = o;
    }
}

__global__ void split4(const float* __restrict__ w0, const float* __restrict__ w1,
                       const float* __restrict__ w2, const float* __restrict__ w3,
                       __nv_bfloat16* __restrict__ h0, __nv_bfloat16* __restrict__ h1,
                       __nv_bfloat16* __restrict__ h2, __nv_bfloat16* __restrict__ h3,
                       __nv_bfloat16* __restrict__ l0, __nv_bfloat16* __restrict__ l1,
                       __nv_bfloat16* __restrict__ l2, __nv_bfloat16* __restrict__ l3,
                       int n0, int n1, int n2, int n3) {
    int z = blockIdx.y;
    const float* w = z==0?w0 : z==1?w1 : z==2?w2 : w3;
    __nv_bfloat16* hh = z==0?h0 : z==1?h1 : z==2?h2 : h3;
    __nv_bfloat16* ll = z==0?l0 : z==1?l1 : z==2?l2 : l3;
    int n4 = (z==0?n0 : z==1?n1 : z==2?n2 : n3) >> 2;
    for (int i = blockIdx.x*blockDim.x + threadIdx.x; i < n4; i += gridDim.x*blockDim.x) {
        float4 v = ((const float4*)w)[i];
        uint32_t h01, l01, h23, l23;
        split2(v.x, v.y, h01, l01);
        split2(v.z, v.w, h23, l23);
        uint2 ho = {h01, h23}, lo = {l01, l23};
        ((uint2*)hh)[i] = ho;
        ((uint2*)ll)[i] = lo;
    }
}

// ---------------- layernorm -> split bf16 (register-resident) ----------------
__device__ __forceinline__ float blockReduceSum(float v) {
    __shared__ float sh[33];
    __syncthreads();
    int lane = threadIdx.x & 31, wid = threadIdx.x >> 5;
    #pragma unroll
    for (int o = 16; o; o >>= 1) v += __shfl_down_sync(0xffffffffu, v, o);
    if (!lane) sh[wid] = v;
    __syncthreads();
    if (threadIdx.x < 8) {
        float t = sh[threadIdx.x];
        #pragma unroll
        for (int o = 4; o; o >>= 1) t += __shfl_down_sync(0xffu, t, o);
        if (!threadIdx.x) sh[32] = t;
    }
    __syncthreads();
    return sh[32];
}

__global__ void __launch_bounds__(256) ln_kernel(const float* __restrict__ x,
                                                 __nv_bfloat16* __restrict__ yh,
                                                 __nv_bfloat16* __restrict__ yl,
                                                 const float* __restrict__ g,
                                                 const float* __restrict__ b,
                                                 int width) {
    int t = threadIdx.x;
    int n4 = width >> 2;
    const float4* xr = (const float4*)(x + (size_t)blockIdx.x * width);
    float4 v[3];
    float s = 0.f;
    #pragma unroll
    for (int c = 0; c < 3; c++) {
        int i = t + c*256;
        if (i < n4) {
            v[c] = xr[i];
            s += v[c].x + v[c].y + v[c].z + v[c].w;
        }
    }
    float m = blockReduceSum(s) / (float)width;
    float v2 = 0.f;
    #pragma unroll
    for (int c = 0; c < 3; c++) {
        int i = t + c*256;
        if (i < n4) {
            float dx = v[c].x - m, dy = v[c].y - m, dz = v[c].z - m, dw = v[c].w - m;
            v2 += dx*dx + dy*dy + dz*dz + dw*dw;
        }
    }
    float var = blockReduceSum(v2) / (float)width;
    float r = rsqrtf(var + 1e-5f);
    uint2* yhr = (uint2*)(yh + (size_t)blockIdx.x * width);
    uint2* ylr = (uint2*)(yl + (size_t)blockIdx.x * width);
    #pragma unroll
    for (int c = 0; c < 3; c++) {
        int i = t + c*256;
        if (i < n4) {
            float4 gg = ((const float4*)g)[i];
            float4 bb = ((const float4*)b)[i];
            float o0 = (v[c].x - m) * r * gg.x + bb.x;
            float o1 = (v[c].y - m) * r * gg.y + bb.y;
            float o2 = (v[c].z - m) * r * gg.z + bb.z;
            float o3 = (v[c].w - m) * r * gg.w + bb.w;
            uint32_t h01, l01, h23, l23;
            split2(o0, o1, h01, l01);
            split2(o2, o3, h23, l23);
            uint2 ho = {h01, h23}, lo = {l01, l23};
            yhr[i] = ho;
            ylr[i] = lo;
        }
    }
}

// ---------------- bf16 tensor-core GEMM (BK=64, 2-stage, 1 sync/step) --------
// C = s*(A @ W^T) + bias [+gelu] [+resid]
// EPI: 0 = fp32 out, 1 = fp32 out + GELU, 2 = split-bf16 out (QKV; Q pre-scaled)
#define GW 36            /* words per 64-elem K-slice row (32 + 4 pad) */
#define GT (128*GW)      /* words per array per stage: 4608 */
#define GSMEM2 (2*3*GT*4)   /* 110592 B */
#define GSMEM3 (2*4*GT*4)   /* 147456 B (1 CTA/SM; layer-5 only) */

template<int CHAINS, int EPI>
__global__ void __launch_bounds__(256,2) gemm_bf16(
    const uint32_t* __restrict__ AHg, const uint32_t* __restrict__ ALg,
    const uint32_t* __restrict__ WHg, const uint32_t* __restrict__ WLg,
    const float* __restrict__ sumptr, float wcount,
    const float* __restrict__ bias, const float* __restrict__ resid,
    float* __restrict__ C, int M, int N, int K)
{
    extern __shared__ uint32_t smw[];
    const int PS = (CHAINS + 1) * GT;
    int t = threadIdx.x, lane = t & 31, wid = t >> 5;
    int wm = wid & 3, wn = wid >> 2;      // 4x2 warp grid: 32m x 64n per warp
    int bm = blockIdx.y * 128, bn = blockIdx.x * 128;
    int Kw = K >> 1;
    float acc[2][8][4] = {};

    int crow = t >> 3, cwg = (t & 7) << 2;    // 32 rows per pass, 32 words/row

    auto do_copy = [&](int slot, int kw) {
        uint32_t* S = smw + slot*PS;
        #pragma unroll
        for (int it = 0; it < 4; it++) {
            int row = it*32 + crow;
            cp_async16(S +        row*GW + cwg, AHg + (size_t)(bm+row)*Kw + kw + cwg);
            cp_async16(S +   GT + row*GW + cwg, ALg + (size_t)(bm+row)*Kw + kw + cwg);
            cp_async16(S + 2*GT + row*GW + cwg, WHg + (size_t)(bn+row)*Kw + kw + cwg);
            if (CHAINS == 3)
                cp_async16(S + 3*GT + row*GW + cwg, WLg + (size_t)(bn+row)*Kw + kw + cwg);
        }
        asm volatile("cp.async.commit_group;\n");
    };

    int nsteps = K >> 6;           // BK = 64
    do_copy(0, 0);

    int lsub = lane >> 3, lrow = lane & 7;
    int lmrow = (lsub & 1) * 8 + lrow;
    int lkoff = (lsub >> 1) * 4;
    int bl8 = lane & 7;
    int btile = lsub >> 1;
    int bkh = (lsub & 1) * 4;

    for (int i = 0; i < nsteps; i++) {
        asm volatile("cp.async.wait_group 0;\n");
        __syncthreads();
        if (i + 1 < nsteps) do_copy((i + 1) & 1, (i + 1) * 32);

        uint32_t* S = smw + (i & 1) * PS;
        const uint32_t* AHs = S;
        const uint32_t* ALs = S + GT;
        const uint32_t* WHs = S + 2*GT;
        const uint32_t* WLs = S + 3*GT;

        #pragma unroll
        for (int g = 0; g < 4; g++) {          // four k16 groups in BK=64
            uint32_t bh[8][2], bl[8][2];
            #pragma unroll
            for (int p = 0; p < 4; p++) {
                int brow = wn*64 + p*16 + btile*8 + bl8;
                ldsm4(bh[2*p][0], bh[2*p][1], bh[2*p+1][0], bh[2*p+1][1],
                      WHs + brow*GW + g*8 + bkh);
                if (CHAINS == 3)
                    ldsm4(bl[2*p][0], bl[2*p][1], bl[2*p+1][0], bl[2*p+1][1],
                          WLs + brow*GW + g*8 + bkh);
            }
            uint32_t ah[2][4], al[2][4];
            #pragma unroll
            for (int ii = 0; ii < 2; ii++) {
                int mr = wm*32 + ii*16 + lmrow;
                int kc = g*8 + lkoff;
                ldsm4(ah[ii][0], ah[ii][1], ah[ii][2], ah[ii][3], AHs + mr*GW + kc);
                ldsm4(al[ii][0], al[ii][1], al[ii][2], al[ii][3], ALs + mr*GW + kc);
            }
            // hi chain first (16 independent accumulators), then lo chain
            #pragma unroll
            for (int ii = 0; ii < 2; ii++)
                #pragma unroll
                for (int j = 0; j < 8; j++)
                    mma16(acc[ii][j], ah[ii], bh[j]);
            #pragma unroll
            for (int ii = 0; ii < 2; ii++)
                #pragma unroll
                for (int j = 0; j < 8; j++)
                    mma16(acc[ii][j], al[ii], bh[j]);
            if (CHAINS == 3) {
                #pragma unroll
                for (int ii = 0; ii < 2; ii++)
                    #pragma unroll
                    for (int j = 0; j < 8; j++)
                        mma16(acc[ii][j], ah[ii], bl[j]);
            }
        }
    }

    float s = 1.0f;
    if (sumptr) s = sumptr[0] / wcount + 1e-8f;
    #pragma unroll
    for (int i = 0; i < 2; i++) {
        int r0 = bm + wm*32 + i*16 + (lane >> 2);
        #pragma unroll
        for (int j = 0; j < 8; j++) {
            int c0 = bn + wn*64 + j*8 + ((lane & 3) << 1);
            float v[4] = {acc[i][j][0]*s, acc[i][j][1]*s, acc[i][j][2]*s, acc[i][j][3]*s};
            if (bias) { v[0] += bias[c0]; v[1] += bias[c0+1]; v[2] += bias[c0]; v[3] += bias[c0+1]; }
            if (EPI == 1) {
                #pragma unroll
                for (int u = 0; u < 4; u++)
                    v[u] = v[u] * 0.5f * (1.0f + erff(v[u] * 0.70710678118654752f));
            }
            if (resid) {
                float2 r1 = *(const float2*)(resid + (size_t)r0*N + c0);
                float2 r2 = *(const float2*)(resid + (size_t)(r0+8)*N + c0);
                v[0] += r1.x; v[1] += r1.y; v[2] += r2.x; v[3] += r2.y;
            }
            if (EPI == 2) {
                float mult = (c0 < INNER) ? SCALE : 1.0f;
                uint32_t* Ch = (uint32_t*)C;
                uint32_t* Cl = Ch + QPLANE;
                uint32_t h01, l01, h23, l23;
                split2(v[0]*mult, v[1]*mult, h01, l01);
                split2(v[2]*mult, v[3]*mult, h23, l23);
                int cw = c0 >> 1, Nw = N >> 1;
                Ch[(size_t)r0*Nw + cw]     = h01; Cl[(size_t)r0*Nw + cw]     = l01;
                Ch[(size_t)(r0+8)*Nw + cw] = h23; Cl[(size_t)(r0+8)*Nw + cw] = l23;
            } else {
                *(float2*)(C + (size_t)r0*N + c0)     = make_float2(v[0], v[1]);
                *(float2*)(C + (size_t)(r0+8)*N + c0) = make_float2(v[2], v[3]);
            }
        }
    }
}

// ---------------- tensor-core flash attention (pre-split bf16 input) ---------
#define AW 36    /* words per 64-dhead row (32 + 4 pad; 144B, 16B-aligned) */
#define AQW (128*AW)
#define AKW (64*AW)
#define AFSMEM ((2*AQW + 4*AKW)*4)   /* 73728 B */

__global__ void __launch_bounds__(256) attn_flash(const uint32_t* __restrict__ qh,
                                                  const uint32_t* __restrict__ ql,
                                                  float* __restrict__ O) {
    extern __shared__ uint32_t asw[];
    uint32_t* Qh = asw;
    uint32_t* Ql = asw + AQW;
    uint32_t* Kh = asw + 2*AQW;
    uint32_t* Kl = Kh + AKW;
    uint32_t* Vh = Kl + AKW;
    uint32_t* Vl = Vh + AKW;

    int t = threadIdx.x, lane = t & 31, wid = t >> 5;
    int bh = blockIdx.y;
    int b = bh / HEADS, hh = bh % HEADS;
    int m0 = blockIdx.x * 128;
    int hw = hh * (DHEAD/2);             // 32-word head offset

    #pragma unroll
    for (int it = 0; it < 4; it++) {
        int idx = it*256 + t;
        int row = idx >> 3, wg = (idx & 7) << 2;
        size_t src = (size_t)(b*SEQ + m0 + row) * QKVW + hw + wg;
        *(uint4*)(Qh + row*AW + wg) = *(const uint4*)(qh + src);
        *(uint4*)(Ql + row*AW + wg) = *(const uint4*)(ql + src);
    }
    __syncthreads();

    int lsub = lane >> 3, lrow = lane & 7;
    int mr = wid*16 + (lsub & 1)*8 + lrow;
    int lk = (lsub >> 1) * 4;
    uint32_t qfh[4][4], qfl[4][4];
    #pragma unroll
    for (int g = 0; g < 4; g++) {
        ldsm4(qfh[g][0], qfh[g][1], qfh[g][2], qfh[g][3], Qh + mr*AW + g*8 + lk);
        ldsm4(qfl[g][0], qfl[g][1], qfl[g][2], qfl[g][3], Ql + mr*AW + g*8 + lk);
    }

    float mi0 = -1e30f, mi1 = -1e30f, li0 = 0.f, li1 = 0.f;
    float acc[8][4] = {};

    for (int kv = 0; kv < SEQ; kv += 64) {
        __syncthreads();
        #pragma unroll
        for (int it = 0; it < 2; it++) {
            int idx = it*256 + t;
            int row = idx >> 3, wg = (idx & 7) << 2;
            size_t rb = (size_t)(b*SEQ + kv + row) * QKVW;
            int w = row*AW + wg;
            *(uint4*)(Kh + w) = *(const uint4*)(qh + rb + (INNER/2)   + hw + wg);
            *(uint4*)(Kl + w) = *(const uint4*)(ql + rb + (INNER/2)   + hw + wg);
            *(uint4*)(Vh + w) = *(const uint4*)(qh + rb + INNER       + hw + wg);
            *(uint4*)(Vl + w) = *(const uint4*)(ql + rb + INNER       + hw + wg);
        }
        __syncthreads();

        float s[8][4] = {};
        int koff = ((lane >> 3) & 1) * 4;
        #pragma unroll
        for (int g = 0; g < 4; g++) {
            #pragma unroll
            for (int j = 0; j < 8; j++) {
                const uint32_t* pk = Kh + (j*8 + (lane & 7))*AW + g*8 + koff;
                uint32_t bhv[2], blv[2];
                ldsm2(bhv[0], bhv[1], pk);
                ldsm2(blv[0], blv[1], Kl + (j*8 + (lane & 7))*AW + g*8 + koff);
                mma16(s[j], qfh[g], bhv);
                mma16(s[j], qfl[g], bhv);
                mma16(s[j], qfh[g], blv);
            }
        }

        float rm0 = -1e30f, rm1 = -1e30f;
        #pragma unroll
        for (int j = 0; j < 8; j++) {
            rm0 = fmaxf(rm0, fmaxf(s[j][0], s[j][1]));
            rm1 = fmaxf(rm1, fmaxf(s[j][2], s[j][3]));
        }
        rm0 = fmaxf(rm0, __shfl_xor_sync(0xffffffffu, rm0, 1));
        rm0 = fmaxf(rm0, __shfl_xor_sync(0xffffffffu, rm0, 2));
        rm1 = fmaxf(rm1, __shfl_xor_sync(0xffffffffu, rm1, 1));
        rm1 = fmaxf(rm1, __shfl_xor_sync(0xffffffffu, rm1, 2));
        float mn0 = fmaxf(mi0, rm0), mn1 = fmaxf(mi1, rm1);
        float f0 = __expf(mi0 - mn0), f1 = __expf(mi1 - mn1);
        mi0 = mn0; mi1 = mn1;
        float sum0 = 0.f, sum1 = 0.f;
        #pragma unroll
        for (int j = 0; j < 8; j++) {
            s[j][0] = __expf(s[j][0] - mn0); s[j][1] = __expf(s[j][1] - mn0);
            s[j][2] = __expf(s[j][2] - mn1); s[j][3] = __expf(s[j][3] - mn1);
            sum0 += s[j][0] + s[j][1];
            sum1 += s[j][2] + s[j][3];
        }
        sum0 += __shfl_xor_sync(0xffffffffu, sum0, 1);
        sum0 += __shfl_xor_sync(0xffffffffu, sum0, 2);
        sum1 += __shfl_xor_sync(0xffffffffu, sum1, 1);
        sum1 += __shfl_xor_sync(0xffffffffu, sum1, 2);
        li0 = li0*f0 + sum0; li1 = li1*f1 + sum1;
        #pragma unroll
        for (int j = 0; j < 8; j++) {
            acc[j][0] *= f0; acc[j][1] *= f0;
            acc[j][2] *= f1; acc[j][3] *= f1;
        }

        #pragma unroll
        for (int g = 0; g < 4; g++) {
            uint32_t aph[4], apl[4];
            split2(s[2*g][0],   s[2*g][1],   aph[0], apl[0]);
            split2(s[2*g][2],   s[2*g][3],   aph[1], apl[1]);
            split2(s[2*g+1][0], s[2*g+1][1], aph[2], apl[2]);
            split2(s[2*g+1][2], s[2*g+1][3], aph[3], apl[3]);
            #pragma unroll
            for (int j = 0; j < 8; j++) {
                const uint32_t* pv = Vh + (g*16 + (lane & 15))*AW + j*4;
                uint32_t bhv[2], blv[2];
                ldsm2t(bhv[0], bhv[1], pv);
                ldsm2t(blv[0], blv[1], Vl + (g*16 + (lane & 15))*AW + j*4);
                mma16(acc[j], aph, bhv);
                mma16(acc[j], apl, bhv);
                mma16(acc[j], aph, blv);
            }
        }
    }

    float inv0 = 1.0f / li0, inv1 = 1.0f / li1;
    int r = m0 + wid*16 + (lane >> 2);
    #pragma unroll
    for (int j = 0; j < 8; j++) {
        int col = hh*DHEAD + j*8 + ((lane & 3) << 1);
        float2 o0 = {acc[j][0]*inv0, acc[j][1]*inv0};
        float2 o1 = {acc[j][2]*inv1, acc[j][3]*inv1};
        *(float2*)(O + ((size_t)b*SEQ + r)*INNER + col)     = o0;
        *(float2*)(O + ((size_t)b*SEQ + r + 8)*INNER + col) = o1;
    }
}

// ---------------- host driver -----------------------------------------------
extern "C" void kernel_launch(void* const* d_in, const int* in_sizes, int n_in,
                              void* d_out, int out_size) {
    const float* x    = (const float*)d_in[0];
    const float* ln1g = (const float*)d_in[1];
    const float* ln1b = (const float*)d_in[2];
    const float* Wqkv = (const float*)d_in[3];
    const float* ln2g = (const float*)d_in[4];
    const float* ln2b = (const float*)d_in[5];
    const float* Wo   = (const float*)d_in[6];
    const float* bo   = (const float*)d_in[7];
    const float* f1g  = (const float*)d_in[8];
    const float* f1b  = (const float*)d_in[9];
    const float* W1   = (const float*)d_in[10];
    const float* b1   = (const float*)d_in[11];
    const float* f2g  = (const float*)d_in[12];
    const float* f2b  = (const float*)d_in[13];
    const float* W2   = (const float*)d_in[14];
    const float* b2   = (const float*)d_in[15];
    float* h = (float*)d_out;

    float *qkv, *ob, *mlp, *scal;
    __nv_bfloat16 *ah, *al, *whq, *wlq, *who, *wlo, *wh1, *wl1, *wh2, *wl2;
    cudaGetSymbolAddress((void**)&qkv, g_qkv);
    cudaGetSymbolAddress((void**)&ob,  g_obuf);
    cudaGetSymbolAddress((void**)&mlp, g_mlp);
    cudaGetSymbolAddress((void**)&ah,  g_ah);
    cudaGetSymbolAddress((void**)&al,  g_al);
    cudaGetSymbolAddress((void**)&whq, g_whq);
    cudaGetSymbolAddress((void**)&wlq, g_wlq);
    cudaGetSymbolAddress((void**)&who, g_who);
    cudaGetSymbolAddress((void**)&wlo, g_wlo);
    cudaGetSymbolAddress((void**)&wh1, g_wh1);
    cudaGetSymbolAddress((void**)&wl1, g_wl1);
    cudaGetSymbolAddress((void**)&wh2, g_wh2);
    cudaGetSymbolAddress((void**)&wl2, g_wl2);
    cudaGetSymbolAddress((void**)&scal, g_scal);

    cudaFuncSetAttribute(gemm_bf16<2,0>, cudaFuncAttributeMaxDynamicSharedMemorySize, GSMEM2);
    cudaFuncSetAttribute(gemm_bf16<2,1>, cudaFuncAttributeMaxDynamicSharedMemorySize, GSMEM2);
    cudaFuncSetAttribute(gemm_bf16<2,2>, cudaFuncAttributeMaxDynamicSharedMemorySize, GSMEM2);
    cudaFuncSetAttribute(gemm_bf16<3,0>, cudaFuncAttributeMaxDynamicSharedMemorySize, GSMEM3);
    cudaFuncSetAttribute(gemm_bf16<3,1>, cudaFuncAttributeMaxDynamicSharedMemorySize, GSMEM3);
    cudaFuncSetAttribute(gemm_bf16<3,2>, cudaFuncAttributeMaxDynamicSharedMemorySize, GSMEM3);
    cudaFuncSetAttribute(attn_flash,     cudaFuncAttributeMaxDynamicSharedMemorySize, AFSMEM);

    cudaMemcpyAsync(h, x, sizeof(float)*(size_t)ROWS*DIMM, cudaMemcpyDeviceToDevice);

    const int nA = NQKV*DIMM, nO = DIMM*INNER, n1 = MLPD*DIMM, n2 = DIMM*MLPD;

    for (int l = 0; l < DEPTH; l++) {
        bool tern = (l < DEPTH - 1);
        if (tern) {
            cudaMemsetAsync(scal, 0, 4*sizeof(float));
            abs_sum4<<<dim3(160,4),256>>>(
                Wqkv + (size_t)l*nA, Wo + (size_t)l*nO, W1 + (size_t)l*n1, W2 + (size_t)l*n2,
                nA, nO, n1, n2, scal);
            quant4<<<dim3(160,4),256>>>(
                Wqkv + (size_t)l*nA, Wo + (size_t)l*nO, W1 + (size_t)l*n1, W2 + (size_t)l*n2,
                whq, who, wh1, wh2, scal, nA, nO, n1, n2);
        } else {
            split4<<<dim3(160,4),256>>>(
                Wqkv + (size_t)l*nA, Wo + (size_t)l*nO, W1 + (size_t)l*n1, W2 + (size_t)l*n2,
                whq, who, wh1, wh2, wlq, wlo, wl1, wl2, nA, nO, n1, n2);
        }

        // attention block (QKV gemm emits pre-split, Q pre-scaled bf16)
        ln_kernel<<<ROWS,256>>>(h, ah, al, ln1g + l*DIMM, ln1b + l*DIMM, DIMM);
        if (tern)
            gemm_bf16<2,2><<<dim3(NQKV/128, ROWS/128),256,GSMEM2>>>(
                (uint32_t*)ah, (uint32_t*)al, (uint32_t*)whq, nullptr,
                scal+0, (float)nA, nullptr, nullptr, qkv, ROWS, NQKV, DIMM);
        else
            gemm_bf16<3,2><<<dim3(NQKV/128, ROWS/128),256,GSMEM3>>>(
                (uint32_t*)ah, (uint32_t*)al, (uint32_t*)whq, (uint32_t*)wlq,
                nullptr, 1.0f, nullptr, nullptr, qkv, ROWS, NQKV, DIMM);
        attn_flash<<<dim3(SEQ/128, BB*HEADS),256,AFSMEM>>>(
            (uint32_t*)qkv, (uint32_t*)qkv + QPLANE, ob);
        ln_kernel<<<ROWS,256>>>(ob, ah, al, ln2g + l*INNER, ln2b + l*INNER, INNER);
        if (tern)
            gemm_bf16<2,0><<<dim3(DIMM/128, ROWS/128),256,GSMEM2>>>(
                (uint32_t*)ah, (uint32_t*)al, (uint32_t*)who, nullptr,
                scal+1, (float)nO, bo + l*DIMM, h, h, ROWS, DIMM, INNER);
        else
            gemm_bf16<3,0><<<dim3(DIMM/128, ROWS/128),256,GSMEM3>>>(
                (uint32_t*)ah, (uint32_t*)al, (uint32_t*)who, (uint32_t*)wlo,
                nullptr, 1.0f, bo + l*DIMM, h, h, ROWS, DIMM, INNER);

        // MLP block (GELU fused into FF1 epilogue)
        ln_kernel<<<ROWS,256>>>(h, ah, al, f1g + l*DIMM, f1b + l*DIMM, DIMM);
        if (tern)
            gemm_bf16<2,1><<<dim3(MLPD/128, ROWS/128),256,GSMEM2>>>(
                (uint32_t*)ah, (uint32_t*)al, (uint32_t*)wh1, nullptr,
                scal+2, (float)n1, b1 + l*MLPD, nullptr, mlp, ROWS, MLPD, DIMM);
        else
            gemm_bf16<3,1><<<dim3(MLPD/128, ROWS/128),256,GSMEM3>>>(
                (uint32_t*)ah, (uint32_t*)al, (uint32_t*)wh1, (uint32_t*)wl1,
                nullptr, 1.0f, b1 + l*MLPD, nullptr, mlp, ROWS, MLPD, DIMM);
        ln_kernel<<<ROWS,256>>>(mlp, ah, al, f2g + l*MLPD, f2b + l*MLPD, MLPD);
        if (tern)
            gemm_bf16<2,0><<<dim3(DIMM/128, ROWS/128),256,GSMEM2>>>(
                (uint32_t*)ah, (uint32_t*)al, (uint32_t*)wh2, nullptr,
                scal+3, (float)n2, b2 + l*DIMM, h, h, ROWS, DIMM, MLPD);
        else
            gemm_bf16<3,0><<<dim3(DIMM/128, ROWS/128),256,GSMEM3>>>(
                (uint32_t*)ah, (uint32_t*)al, (uint32_t*)wh2, (uint32_t*)wl2,
                nullptr, 1.0f, b2 + l*DIMM, h, h, ROWS, DIMM, MLPD);
    }
}

// round 14
// speedup vs baseline: 4.3658x; 1.0802x over previous
#include <cuda_runtime.h>
#include <cuda_bf16.h>
#include <math.h>
#include <stdint.h>

#define DIMM  768
#define HEADS 12
#define DHEAD 64
#define INNER 768
#define MLPD  3072
#define BB    8
#define SEQ   1024
#define ROWS  (BB*SEQ)   /* 8192 */
#define DEPTH 6
#define SCALE 0.125f     /* 64^-0.5 */
#define NQKV  (3*INNER)
#define QKVW  (NQKV/2)   /* words per row in split-bf16 qkv plane: 1152 */
#define QPLANE ((size_t)ROWS*QKVW)   /* words per hi/lo plane */

// ---------------- scratch (device globals: no allocations allowed) ----------
__device__ __align__(16) float g_qkv[(size_t)ROWS*NQKV];   // 2 bf16 planes (hi, lo)
__device__ __align__(16) float g_obuf[ROWS*INNER];
__device__ __align__(16) float g_mlp[(size_t)ROWS*MLPD];
__device__ __align__(16) __nv_bfloat16 g_ah[(size_t)ROWS*MLPD];   // LN out hi
__device__ __align__(16) __nv_bfloat16 g_al[(size_t)ROWS*MLPD];   // LN out lo
__device__ __align__(16) __nv_bfloat16 g_whq[NQKV*DIMM];
__device__ __align__(16) __nv_bfloat16 g_wlq[NQKV*DIMM];
__device__ __align__(16) __nv_bfloat16 g_who[DIMM*INNER];
__device__ __align__(16) __nv_bfloat16 g_wlo[DIMM*INNER];
__device__ __align__(16) __nv_bfloat16 g_wh1[MLPD*DIMM];
__device__ __align__(16) __nv_bfloat16 g_wl1[MLPD*DIMM];
__device__ __align__(16) __nv_bfloat16 g_wh2[DIMM*MLPD];
__device__ __align__(16) __nv_bfloat16 g_wl2[DIMM*MLPD];
__device__ float g_scal[4];

// ---------------- asm helpers ------------------------------------------------
__device__ __forceinline__ void cp_async16(void* smem, const void* gmem) {
    uint32_t s = (uint32_t)__cvta_generic_to_shared(smem);
    asm volatile("cp.async.cg.shared.global [%0], [%1], 16;\n" :: "r"(s), "l"(gmem));
}
__device__ __forceinline__ void ldsm4(uint32_t& a0, uint32_t& a1, uint32_t& a2,
                                      uint32_t& a3, const uint32_t* p) {
    uint32_t s = (uint32_t)__cvta_generic_to_shared(p);
    asm volatile("ldmatrix.sync.aligned.m8n8.x4.shared.b16 {%0,%1,%2,%3}, [%4];\n"
                 : "=r"(a0), "=r"(a1), "=r"(a2), "=r"(a3) : "r"(s));
}
__device__ __forceinline__ void ldsm2(uint32_t& a0, uint32_t& a1, const uint32_t* p) {
    uint32_t s = (uint32_t)__cvta_generic_to_shared(p);
    asm volatile("ldmatrix.sync.aligned.m8n8.x2.shared.b16 {%0,%1}, [%2];\n"
                 : "=r"(a0), "=r"(a1) : "r"(s));
}
__device__ __forceinline__ void ldsm2t(uint32_t& a0, uint32_t& a1, const uint32_t* p) {
    uint32_t s = (uint32_t)__cvta_generic_to_shared(p);
    asm volatile("ldmatrix.sync.aligned.m8n8.x2.trans.shared.b16 {%0,%1}, [%2];\n"
                 : "=r"(a0), "=r"(a1) : "r"(s));
}
__device__ __forceinline__ void mma16(float c[4], const uint32_t a[4], const uint32_t b[2]) {
    asm volatile(
        "mma.sync.aligned.m16n8k16.row.col.f32.bf16.bf16.f32 "
        "{%0,%1,%2,%3}, {%4,%5,%6,%7}, {%8,%9}, {%0,%1,%2,%3};\n"
        : "+f"(c[0]), "+f"(c[1]), "+f"(c[2]), "+f"(c[3])
        : "r"(a[0]), "r"(a[1]), "r"(a[2]), "r"(a[3]), "r"(b[0]), "r"(b[1]));
}
__device__ __forceinline__ void split2(float a, float b, uint32_t& hi, uint32_t& lo) {
    __nv_bfloat162 h = __floats2bfloat162_rn(a, b);
    hi = *reinterpret_cast<uint32_t*>(&h);
    float la = a - __bfloat162float(h.x);
    float lb = b - __bfloat162float(h.y);
    __nv_bfloat162 l = __floats2bfloat162_rn(la, lb);
    lo = *reinterpret_cast<uint32_t*>(&l);
}

// ---------------- batched abs-sum / quant / split (float4) ------------------
__global__ void abs_sum4(const float* __restrict__ w0, const float* __restrict__ w1,
                         const float* __restrict__ w2, const float* __restrict__ w3,
                         int n0, int n1, int n2, int n3, float* out) {
    int z = blockIdx.y;
    const float* w = z==0?w0 : z==1?w1 : z==2?w2 : w3;
    int n4 = (z==0?n0 : z==1?n1 : z==2?n2 : n3) >> 2;
    float s = 0.f;
    for (int i = blockIdx.x*blockDim.x + threadIdx.x; i < n4; i += gridDim.x*blockDim.x) {
        float4 v = ((const float4*)w)[i];
        s += fabsf(v.x) + fabsf(v.y) + fabsf(v.z) + fabsf(v.w);
    }
    #pragma unroll
    for (int o = 16; o; o >>= 1) s += __shfl_down_sync(0xffffffffu, s, o);
    __shared__ float sh[8];
    if ((threadIdx.x & 31) == 0) sh[threadIdx.x >> 5] = s;
    __syncthreads();
    if (threadIdx.x < 8) {
        float v = sh[threadIdx.x];
        #pragma unroll
        for (int o = 4; o; o >>= 1) v += __shfl_down_sync(0xffu, v, o);
        if (threadIdx.x == 0) atomicAdd(out + z, v);
    }
}

__global__ void quant4(const float* __restrict__ w0, const float* __restrict__ w1,
                       const float* __restrict__ w2, const float* __restrict__ w3,
                       __nv_bfloat16* __restrict__ q0, __nv_bfloat16* __restrict__ q1,
                       __nv_bfloat16* __restrict__ q2, __nv_bfloat16* __restrict__ q3,
                       const float* __restrict__ sums, int n0, int n1, int n2, int n3) {
    int z = blockIdx.y;
    const float* w = z==0?w0 : z==1?w1 : z==2?w2 : w3;
    __nv_bfloat16* q = z==0?q0 : z==1?q1 : z==2?q2 : q3;
    int n = z==0?n0 : z==1?n1 : z==2?n2 : n3;
    float s = sums[z] / (float)n + 1e-8f;
    float inv = 1.0f / s;
    int n4 = n >> 2;
    for (int i = blockIdx.x*blockDim.x + threadIdx.x; i < n4; i += gridDim.x*blockDim.x) {
        float4 v = ((const float4*)w)[i];
        float t0 = fminf(1.f, fmaxf(-1.f, rintf(v.x * inv)));   // half-to-even
        float t1 = fminf(1.f, fmaxf(-1.f, rintf(v.y * inv)));
        float t2 = fminf(1.f, fmaxf(-1.f, rintf(v.z * inv)));
        float t3 = fminf(1.f, fmaxf(-1.f, rintf(v.w * inv)));
        __nv_bfloat162 p0 = __floats2bfloat162_rn(t0, t1);
        __nv_bfloat162 p1 = __floats2bfloat162_rn(t2, t3);
        uint2 o = { *(uint32_t*)&p0, *(uint32_t*)&p1 };
        ((uint2*)q)[i] = o;
    }
}

__global__ void split4(const float* __restrict__ w0, const float* __restrict__ w1,
                       const float* __restrict__ w2, const float* __restrict__ w3,
                       __nv_bfloat16* __restrict__ h0, __nv_bfloat16* __restrict__ h1,
                       __nv_bfloat16* __restrict__ h2, __nv_bfloat16* __restrict__ h3,
                       __nv_bfloat16* __restrict__ l0, __nv_bfloat16* __restrict__ l1,
                       __nv_bfloat16* __restrict__ l2, __nv_bfloat16* __restrict__ l3,
                       int n0, int n1, int n2, int n3) {
    int z = blockIdx.y;
    const float* w = z==0?w0 : z==1?w1 : z==2?w2 : w3;
    __nv_bfloat16* hh = z==0?h0 : z==1?h1 : z==2?h2 : h3;
    __nv_bfloat16* ll = z==0?l0 : z==1?l1 : z==2?l2 : l3;
    int n4 = (z==0?n0 : z==1?n1 : z==2?n2 : n3) >> 2;
    for (int i = blockIdx.x*blockDim.x + threadIdx.x; i < n4; i += gridDim.x*blockDim.x) {
        float4 v = ((const float4*)w)[i];
        uint32_t h01, l01, h23, l23;
        split2(v.x, v.y, h01, l01);
        split2(v.z, v.w, h23, l23);
        uint2 ho = {h01, h23}, lo = {l01, l23};
        ((uint2*)hh)[i] = ho;
        ((uint2*)ll)[i] = lo;
    }
}

// ---------------- layernorm -> split bf16 (register-resident) ----------------
__device__ __forceinline__ float blockReduceSum(float v) {
    __shared__ float sh[33];
    __syncthreads();
    int lane = threadIdx.x & 31, wid = threadIdx.x >> 5;
    #pragma unroll
    for (int o = 16; o; o >>= 1) v += __shfl_down_sync(0xffffffffu, v, o);
    if (!lane) sh[wid] = v;
    __syncthreads();
    if (threadIdx.x < 8) {
        float t = sh[threadIdx.x];
        #pragma unroll
        for (int o = 4; o; o >>= 1) t += __shfl_down_sync(0xffu, t, o);
        if (!threadIdx.x) sh[32] = t;
    }
    __syncthreads();
    return sh[32];
}

__global__ void __launch_bounds__(256) ln_kernel(const float* __restrict__ x,
                                                 __nv_bfloat16* __restrict__ yh,
                                                 __nv_bfloat16* __restrict__ yl,
                                                 const float* __restrict__ g,
                                                 const float* __restrict__ b,
                                                 int width) {
    int t = threadIdx.x;
    int n4 = width >> 2;
    const float4* xr = (const float4*)(x + (size_t)blockIdx.x * width);
    float4 v[3];
    float s = 0.f;
    #pragma unroll
    for (int c = 0; c < 3; c++) {
        int i = t + c*256;
        if (i < n4) {
            v[c] = xr[i];
            s += v[c].x + v[c].y + v[c].z + v[c].w;
        }
    }
    float m = blockReduceSum(s) / (float)width;
    float v2 = 0.f;
    #pragma unroll
    for (int c = 0; c < 3; c++) {
        int i = t + c*256;
        if (i < n4) {
            float dx = v[c].x - m, dy = v[c].y - m, dz = v[c].z - m, dw = v[c].w - m;
            v2 += dx*dx + dy*dy + dz*dz + dw*dw;
        }
    }
    float var = blockReduceSum(v2) / (float)width;
    float r = rsqrtf(var + 1e-5f);
    uint2* yhr = (uint2*)(yh + (size_t)blockIdx.x * width);
    uint2* ylr = (uint2*)(yl + (size_t)blockIdx.x * width);
    #pragma unroll
    for (int c = 0; c < 3; c++) {
        int i = t + c*256;
        if (i < n4) {
            float4 gg = ((const float4*)g)[i];
            float4 bb = ((const float4*)b)[i];
            float o0 = (v[c].x - m) * r * gg.x + bb.x;
            float o1 = (v[c].y - m) * r * gg.y + bb.y;
            float o2 = (v[c].z - m) * r * gg.z + bb.z;
            float o3 = (v[c].w - m) * r * gg.w + bb.w;
            uint32_t h01, l01, h23, l23;
            split2(o0, o1, h01, l01);
            split2(o2, o3, h23, l23);
            uint2 ho = {h01, h23}, lo = {l01, l23};
            yhr[i] = ho;
            ylr[i] = lo;
        }
    }
}

// ---------------- bf16 tensor-core GEMM (2-stage, 1 sync/step) ---------------
// C = s*(A @ W^T) + bias [+gelu] [+resid]
// EPI: 0 = fp32 out, 1 = fp32 out + GELU, 2 = split-bf16 out (QKV; Q pre-scaled)
// BK: 64 for 2-chain (3 arrays, 110.6KB, 2 CTA/SM); 32 for 3-chain (4 arrays,
//     81.9KB, 2 CTA/SM — restores layer-5 occupancy).
template<int CHAINS> struct GCfg {
    static const int BK  = (CHAINS == 2) ? 64 : 32;
    static const int WPR = BK / 2;          // words per row chunk
    static const int GW  = WPR + 4;         // padded row stride (words)
    static const int GT  = 128 * GW;        // words per array per stage
    static const int SM  = 2 * (CHAINS + 1) * GT * 4;   // smem bytes
};
#define GSMEM2 (GCfg<2>::SM)   /* 110592 */
#define GSMEM3 (GCfg<3>::SM)   /* 81920  */

template<int CHAINS, int EPI>
__global__ void __launch_bounds__(256,2) gemm_bf16(
    const uint32_t* __restrict__ AHg, const uint32_t* __restrict__ ALg,
    const uint32_t* __restrict__ WHg, const uint32_t* __restrict__ WLg,
    const float* __restrict__ sumptr, float wcount,
    const float* __restrict__ bias, const float* __restrict__ resid,
    float* __restrict__ C, int M, int N, int K)
{
    extern __shared__ uint32_t smw[];
    const int BK  = GCfg<CHAINS>::BK;
    const int WPR = GCfg<CHAINS>::WPR;
    const int GW  = GCfg<CHAINS>::GW;
    const int GT  = GCfg<CHAINS>::GT;
    const int PS  = (CHAINS + 1) * GT;
    const int NG  = BK / 16;                // k16 groups per step
    const int TPR = WPR / 4;                // copy threads per row
    const int RPP = 256 / TPR;              // rows per copy pass
    int t = threadIdx.x, lane = t & 31, wid = t >> 5;
    int wm = wid & 3, wn = wid >> 2;        // 4x2 warp grid: 32m x 64n per warp
    int bm = blockIdx.y * 128, bn = blockIdx.x * 128;
    int Kw = K >> 1;
    float acc[2][8][4] = {};

    int crow = t / TPR, cwg = (t % TPR) << 2;

    auto do_copy = [&](int slot, int kw) {
        uint32_t* S = smw + slot*PS;
        #pragma unroll
        for (int it = 0; it < 128/RPP; it++) {
            int row = it*RPP + crow;
            cp_async16(S +        row*GW + cwg, AHg + (size_t)(bm+row)*Kw + kw + cwg);
            cp_async16(S +   GT + row*GW + cwg, ALg + (size_t)(bm+row)*Kw + kw + cwg);
            cp_async16(S + 2*GT + row*GW + cwg, WHg + (size_t)(bn+row)*Kw + kw + cwg);
            if (CHAINS == 3)
                cp_async16(S + 3*GT + row*GW + cwg, WLg + (size_t)(bn+row)*Kw + kw + cwg);
        }
        asm volatile("cp.async.commit_group;\n");
    };

    int nsteps = K / BK;
    do_copy(0, 0);

    int lsub = lane >> 3, lrow = lane & 7;
    int lmrow = (lsub & 1) * 8 + lrow;
    int lkoff = (lsub >> 1) * 4;
    int bl8 = lane & 7;
    int btile = lsub >> 1;
    int bkh = (lsub & 1) * 4;

    for (int i = 0; i < nsteps; i++) {
        asm volatile("cp.async.wait_group 0;\n");
        __syncthreads();
        if (i + 1 < nsteps) do_copy((i + 1) & 1, (i + 1) * WPR);

        uint32_t* S = smw + (i & 1) * PS;
        const uint32_t* AHs = S;
        const uint32_t* ALs = S + GT;
        const uint32_t* WHs = S + 2*GT;
        const uint32_t* WLs = S + 3*GT;

        #pragma unroll
        for (int g = 0; g < NG; g++) {
            uint32_t bh[8][2], bl[8][2];
            #pragma unroll
            for (int p = 0; p < 4; p++) {
                int brow = wn*64 + p*16 + btile*8 + bl8;
                ldsm4(bh[2*p][0], bh[2*p][1], bh[2*p+1][0], bh[2*p+1][1],
                      WHs + brow*GW + g*8 + bkh);
                if (CHAINS == 3)
                    ldsm4(bl[2*p][0], bl[2*p][1], bl[2*p+1][0], bl[2*p+1][1],
                          WLs + brow*GW + g*8 + bkh);
            }
            uint32_t ah[2][4], al[2][4];
            #pragma unroll
            for (int ii = 0; ii < 2; ii++) {
                int mr = wm*32 + ii*16 + lmrow;
                int kc = g*8 + lkoff;
                ldsm4(ah[ii][0], ah[ii][1], ah[ii][2], ah[ii][3], AHs + mr*GW + kc);
                ldsm4(al[ii][0], al[ii][1], al[ii][2], al[ii][3], ALs + mr*GW + kc);
            }
            // hi chain first (16 independent accumulators), then lo chain
            #pragma unroll
            for (int ii = 0; ii < 2; ii++)
                #pragma unroll
                for (int j = 0; j < 8; j++)
                    mma16(acc[ii][j], ah[ii], bh[j]);
            #pragma unroll
            for (int ii = 0; ii < 2; ii++)
                #pragma unroll
                for (int j = 0; j < 8; j++)
                    mma16(acc[ii][j], al[ii], bh[j]);
            if (CHAINS == 3) {
                #pragma unroll
                for (int ii = 0; ii < 2; ii++)
                    #pragma unroll
                    for (int j = 0; j < 8; j++)
                        mma16(acc[ii][j], ah[ii], bl[j]);
            }
        }
    }

    float s = 1.0f;
    if (sumptr) s = sumptr[0] / wcount + 1e-8f;
    #pragma unroll
    for (int i = 0; i < 2; i++) {
        int r0 = bm + wm*32 + i*16 + (lane >> 2);
        #pragma unroll
        for (int j = 0; j < 8; j++) {
            int c0 = bn + wn*64 + j*8 + ((lane & 3) << 1);
            float v[4] = {acc[i][j][0]*s, acc[i][j][1]*s, acc[i][j][2]*s, acc[i][j][3]*s};
            if (bias) { v[0] += bias[c0]; v[1] += bias[c0+1]; v[2] += bias[c0]; v[3] += bias[c0+1]; }
            if (EPI == 1) {
                #pragma unroll
                for (int u = 0; u < 4; u++)
                    v[u] = v[u] * 0.5f * (1.0f + erff(v[u] * 0.70710678118654752f));
            }
            if (resid) {
                float2 r1 = *(const float2*)(resid + (size_t)r0*N + c0);
                float2 r2 = *(const float2*)(resid + (size_t)(r0+8)*N + c0);
                v[0] += r1.x; v[1] += r1.y; v[2] += r2.x; v[3] += r2.y;
            }
            if (EPI == 2) {
                float mult = (c0 < INNER) ? SCALE : 1.0f;
                uint32_t* Ch = (uint32_t*)C;
                uint32_t* Cl = Ch + QPLANE;
                uint32_t h01, l01, h23, l23;
                split2(v[0]*mult, v[1]*mult, h01, l01);
                split2(v[2]*mult, v[3]*mult, h23, l23);
                int cw = c0 >> 1, Nw = N >> 1;
                Ch[(size_t)r0*Nw + cw]     = h01; Cl[(size_t)r0*Nw + cw]     = l01;
                Ch[(size_t)(r0+8)*Nw + cw] = h23; Cl[(size_t)(r0+8)*Nw + cw] = l23;
            } else {
                *(float2*)(C + (size_t)r0*N + c0)     = make_float2(v[0], v[1]);
                *(float2*)(C + (size_t)(r0+8)*N + c0) = make_float2(v[2], v[3]);
            }
        }
    }
}

// ---------------- tensor-core flash attention (pre-split bf16 input) ---------
#define AW 36    /* words per 64-dhead row (32 + 4 pad; 144B, 16B-aligned) */
#define AQW (128*AW)
#define AKW (64*AW)
#define AFSMEM ((2*AQW + 4*AKW)*4)   /* 73728 B */

__global__ void __launch_bounds__(256,2) attn_flash(const uint32_t* __restrict__ qh,
                                                    const uint32_t* __restrict__ ql,
                                                    float* __restrict__ O) {
    extern __shared__ uint32_t asw[];
    uint32_t* Qh = asw;
    uint32_t* Ql = asw + AQW;
    uint32_t* Kh = asw + 2*AQW;
    uint32_t* Kl = Kh + AKW;
    uint32_t* Vh = Kl + AKW;
    uint32_t* Vl = Vh + AKW;

    int t = threadIdx.x, lane = t & 31, wid = t >> 5;
    int bh = blockIdx.y;
    int b = bh / HEADS, hh = bh % HEADS;
    int m0 = blockIdx.x * 128;
    int hw = hh * (DHEAD/2);             // 32-word head offset

    #pragma unroll
    for (int it = 0; it < 4; it++) {
        int idx = it*256 + t;
        int row = idx >> 3, wg = (idx & 7) << 2;
        size_t src = (size_t)(b*SEQ + m0 + row) * QKVW + hw + wg;
        *(uint4*)(Qh + row*AW + wg) = *(const uint4*)(qh + src);
        *(uint4*)(Ql + row*AW + wg) = *(const uint4*)(ql + src);
    }
    __syncthreads();

    int lsub = lane >> 3, lrow = lane & 7;
    int mr = wid*16 + (lsub & 1)*8 + lrow;
    int lk = (lsub >> 1) * 4;
    uint32_t qfh[4][4], qfl[4][4];
    #pragma unroll
    for (int g = 0; g < 4; g++) {
        ldsm4(qfh[g][0], qfh[g][1], qfh[g][2], qfh[g][3], Qh + mr*AW + g*8 + lk);
        ldsm4(qfl[g][0], qfl[g][1], qfl[g][2], qfl[g][3], Ql + mr*AW + g*8 + lk);
    }

    float mi0 = -1e30f, mi1 = -1e30f, li0 = 0.f, li1 = 0.f;
    float acc[8][4] = {};

    for (int kv = 0; kv < SEQ; kv += 64) {
        __syncthreads();
        #pragma unroll
        for (int it = 0; it < 2; it++) {
            int idx = it*256 + t;
            int row = idx >> 3, wg = (idx & 7) << 2;
            size_t rb = (size_t)(b*SEQ + kv + row) * QKVW;
            int w = row*AW + wg;
            *(uint4*)(Kh + w) = *(const uint4*)(qh + rb + (INNER/2)   + hw + wg);
            *(uint4*)(Kl + w) = *(const uint4*)(ql + rb + (INNER/2)   + hw + wg);
            *(uint4*)(Vh + w) = *(const uint4*)(qh + rb + INNER       + hw + wg);
            *(uint4*)(Vl + w) = *(const uint4*)(ql + rb + INNER       + hw + wg);
        }
        __syncthreads();

        float s[8][4] = {};
        int koff = ((lane >> 3) & 1) * 4;
        #pragma unroll
        for (int g = 0; g < 4; g++) {
            #pragma unroll
            for (int j = 0; j < 8; j++) {
                const uint32_t* pk = Kh + (j*8 + (lane & 7))*AW + g*8 + koff;
                uint32_t bhv[2], blv[2];
                ldsm2(bhv[0], bhv[1], pk);
                ldsm2(blv[0], blv[1], Kl + (j*8 + (lane & 7))*AW + g*8 + koff);
                mma16(s[j], qfh[g], bhv);
                mma16(s[j], qfl[g], bhv);
                mma16(s[j], qfh[g], blv);
            }
        }

        float rm0 = -1e30f, rm1 = -1e30f;
        #pragma unroll
        for (int j = 0; j < 8; j++) {
            rm0 = fmaxf(rm0, fmaxf(s[j][0], s[j][1]));
            rm1 = fmaxf(rm1, fmaxf(s[j][2], s[j][3]));
        }
        rm0 = fmaxf(rm0, __shfl_xor_sync(0xffffffffu, rm0, 1));
        rm0 = fmaxf(rm0, __shfl_xor_sync(0xffffffffu, rm0, 2));
        rm1 = fmaxf(rm1, __shfl_xor_sync(0xffffffffu, rm1, 1));
        rm1 = fmaxf(rm1, __shfl_xor_sync(0xffffffffu, rm1, 2));
        float mn0 = fmaxf(mi0, rm0), mn1 = fmaxf(mi1, rm1);
        float f0 = __expf(mi0 - mn0), f1 = __expf(mi1 - mn1);
        mi0 = mn0; mi1 = mn1;
        float sum0 = 0.f, sum1 = 0.f;
        #pragma unroll
        for (int j = 0; j < 8; j++) {
            s[j][0] = __expf(s[j][0] - mn0); s[j][1] = __expf(s[j][1] - mn0);
            s[j][2] = __expf(s[j][2] - mn1); s[j][3] = __expf(s[j][3] - mn1);
            sum0 += s[j][0] + s[j][1];
            sum1 += s[j][2] + s[j][3];
        }
        sum0 += __shfl_xor_sync(0xffffffffu, sum0, 1);
        sum0 += __shfl_xor_sync(0xffffffffu, sum0, 2);
        sum1 += __shfl_xor_sync(0xffffffffu, sum1, 1);
        sum1 += __shfl_xor_sync(0xffffffffu, sum1, 2);
        li0 = li0*f0 + sum0; li1 = li1*f1 + sum1;
        #pragma unroll
        for (int j = 0; j < 8; j++) {
            acc[j][0] *= f0; acc[j][1] *= f0;
            acc[j][2] *= f1; acc[j][3] *= f1;
        }

        #pragma unroll
        for (int g = 0; g < 4; g++) {
            uint32_t aph[4], apl[4];
            split2(s[2*g][0],   s[2*g][1],   aph[0], apl[0]);
            split2(s[2*g][2],   s[2*g][3],   aph[1], apl[1]);
            split2(s[2*g+1][0], s[2*g+1][1], aph[2], apl[2]);
            split2(s[2*g+1][2], s[2*g+1][3], aph[3], apl[3]);
            #pragma unroll
            for (int j = 0; j < 8; j++) {
                const uint32_t* pv = Vh + (g*16 + (lane & 15))*AW + j*4;
                uint32_t bhv[2], blv[2];
                ldsm2t(bhv[0], bhv[1], pv);
                ldsm2t(blv[0], blv[1], Vl + (g*16 + (lane & 15))*AW + j*4);
                mma16(acc[j], aph, bhv);
                mma16(acc[j], apl, bhv);
                mma16(acc[j], aph, blv);
            }
        }
    }

    float inv0 = 1.0f / li0, inv1 = 1.0f / li1;
    int r = m0 + wid*16 + (lane >> 2);
    #pragma unroll
    for (int j = 0; j < 8; j++) {
        int col = hh*DHEAD + j*8 + ((lane & 3) << 1);
        float2 o0 = {acc[j][0]*inv0, acc[j][1]*inv0};
        float2 o1 = {acc[j][2]*inv1, acc[j][3]*inv1};
        *(float2*)(O + ((size_t)b*SEQ + r)*INNER + col)     = o0;
        *(float2*)(O + ((size_t)b*SEQ + r + 8)*INNER + col) = o1;
    }
}

// ---------------- host driver -----------------------------------------------
extern "C" void kernel_launch(void* const* d_in, const int* in_sizes, int n_in,
                              void* d_out, int out_size) {
    const float* x    = (const float*)d_in[0];
    const float* ln1g = (const float*)d_in[1];
    const float* ln1b = (const float*)d_in[2];
    const float* Wqkv = (const float*)d_in[3];
    const float* ln2g = (const float*)d_in[4];
    const float* ln2b = (const float*)d_in[5];
    const float* Wo   = (const float*)d_in[6];
    const float* bo   = (const float*)d_in[7];
    const float* f1g  = (const float*)d_in[8];
    const float* f1b  = (const float*)d_in[9];
    const float* W1   = (const float*)d_in[10];
    const float* b1   = (const float*)d_in[11];
    const float* f2g  = (const float*)d_in[12];
    const float* f2b  = (const float*)d_in[13];
    const float* W2   = (const float*)d_in[14];
    const float* b2   = (const float*)d_in[15];
    float* h = (float*)d_out;

    float *qkv, *ob, *mlp, *scal;
    __nv_bfloat16 *ah, *al, *whq, *wlq, *who, *wlo, *wh1, *wl1, *wh2, *wl2;
    cudaGetSymbolAddress((void**)&qkv, g_qkv);
    cudaGetSymbolAddress((void**)&ob,  g_obuf);
    cudaGetSymbolAddress((void**)&mlp, g_mlp);
    cudaGetSymbolAddress((void**)&ah,  g_ah);
    cudaGetSymbolAddress((void**)&al,  g_al);
    cudaGetSymbolAddress((void**)&whq, g_whq);
    cudaGetSymbolAddress((void**)&wlq, g_wlq);
    cudaGetSymbolAddress((void**)&who, g_who);
    cudaGetSymbolAddress((void**)&wlo, g_wlo);
    cudaGetSymbolAddress((void**)&wh1, g_wh1);
    cudaGetSymbolAddress((void**)&wl1, g_wl1);
    cudaGetSymbolAddress((void**)&wh2, g_wh2);
    cudaGetSymbolAddress((void**)&wl2, g_wl2);
    cudaGetSymbolAddress((void**)&scal, g_scal);

    cudaFuncSetAttribute(gemm_bf16<2,0>, cudaFuncAttributeMaxDynamicSharedMemorySize, GSMEM2);
    cudaFuncSetAttribute(gemm_bf16<2,1>, cudaFuncAttributeMaxDynamicSharedMemorySize, GSMEM2);
    cudaFuncSetAttribute(gemm_bf16<2,2>, cudaFuncAttributeMaxDynamicSharedMemorySize, GSMEM2);
    cudaFuncSetAttribute(gemm_bf16<3,0>, cudaFuncAttributeMaxDynamicSharedMemorySize, GSMEM3);
    cudaFuncSetAttribute(gemm_bf16<3,1>, cudaFuncAttributeMaxDynamicSharedMemorySize, GSMEM3);
    cudaFuncSetAttribute(gemm_bf16<3,2>, cudaFuncAttributeMaxDynamicSharedMemorySize, GSMEM3);
    cudaFuncSetAttribute(attn_flash,     cudaFuncAttributeMaxDynamicSharedMemorySize, AFSMEM);

    cudaMemcpyAsync(h, x, sizeof(float)*(size_t)ROWS*DIMM, cudaMemcpyDeviceToDevice);

    const int nA = NQKV*DIMM, nO = DIMM*INNER, n1 = MLPD*DIMM, n2 = DIMM*MLPD;

    for (int l = 0; l < DEPTH; l++) {
        bool tern = (l < DEPTH - 1);
        if (tern) {
            cudaMemsetAsync(scal, 0, 4*sizeof(float));
            abs_sum4<<<dim3(160,4),256>>>(
                Wqkv + (size_t)l*nA, Wo + (size_t)l*nO, W1 + (size_t)l*n1, W2 + (size_t)l*n2,
                nA, nO, n1, n2, scal);
            quant4<<<dim3(160,4),256>>>(
                Wqkv + (size_t)l*nA, Wo + (size_t)l*nO, W1 + (size_t)l*n1, W2 + (size_t)l*n2,
                whq, who, wh1, wh2, scal, nA, nO, n1, n2);
        } else {
            split4<<<dim3(160,4),256>>>(
                Wqkv + (size_t)l*nA, Wo + (size_t)l*nO, W1 + (size_t)l*n1, W2 + (size_t)l*n2,
                whq, who, wh1, wh2, wlq, wlo, wl1, wl2, nA, nO, n1, n2);
        }

        // attention block (QKV gemm emits pre-split, Q pre-scaled bf16)
        ln_kernel<<<ROWS,256>>>(h, ah, al, ln1g + l*DIMM, ln1b + l*DIMM, DIMM);
        if (tern)
            gemm_bf16<2,2><<<dim3(NQKV/128, ROWS/128),256,GSMEM2>>>(
                (uint32_t*)ah, (uint32_t*)al, (uint32_t*)whq, nullptr,
                scal+0, (float)nA, nullptr, nullptr, qkv, ROWS, NQKV, DIMM);
        else
            gemm_bf16<3,2><<<dim3(NQKV/128, ROWS/128),256,GSMEM3>>>(
                (uint32_t*)ah, (uint32_t*)al, (uint32_t*)whq, (uint32_t*)wlq,
                nullptr, 1.0f, nullptr, nullptr, qkv, ROWS, NQKV, DIMM);
        attn_flash<<<dim3(SEQ/128, BB*HEADS),256,AFSMEM>>>(
            (uint32_t*)qkv, (uint32_t*)qkv + QPLANE, ob);
        ln_kernel<<<ROWS,256>>>(ob, ah, al, ln2g + l*INNER, ln2b + l*INNER, INNER);
        if (tern)
            gemm_bf16<2,0><<<dim3(DIMM/128, ROWS/128),256,GSMEM2>>>(
                (uint32_t*)ah, (uint32_t*)al, (uint32_t*)who, nullptr,
                scal+1, (float)nO, bo + l*DIMM, h, h, ROWS, DIMM, INNER);
        else
            gemm_bf16<3,0><<<dim3(DIMM/128, ROWS/128),256,GSMEM3>>>(
                (uint32_t*)ah, (uint32_t*)al, (uint32_t*)who, (uint32_t*)wlo,
                nullptr, 1.0f, bo + l*DIMM, h, h, ROWS, DIMM, INNER);

        // MLP block (GELU fused into FF1 epilogue)
        ln_kernel<<<ROWS,256>>>(h, ah, al, f1g + l*DIMM, f1b + l*DIMM, DIMM);
        if (tern)
            gemm_bf16<2,1><<<dim3(MLPD/128, ROWS/128),256,GSMEM2>>>(
                (uint32_t*)ah, (uint32_t*)al, (uint32_t*)wh1, nullptr,
                scal+2, (float)n1, b1 + l*MLPD, nullptr, mlp, ROWS, MLPD, DIMM);
        else
            gemm_bf16<3,1><<<dim3(MLPD/128, ROWS/128),256,GSMEM3>>>(
                (uint32_t*)ah, (uint32_t*)al, (uint32_t*)wh1, (uint32_t*)wl1,
                nullptr, 1.0f, b1 + l*MLPD, nullptr, mlp, ROWS, MLPD, DIMM);
        ln_kernel<<<ROWS,256>>>(mlp, ah, al, f2g + l*MLPD, f2b + l*MLPD, MLPD);
        if (tern)
            gemm_bf16<2,0><<<dim3(DIMM/128, ROWS/128),256,GSMEM2>>>(
                (uint32_t*)ah, (uint32_t*)al, (uint32_t*)wh2, nullptr,
                scal+3, (float)n2, b2 + l*DIMM, h, h, ROWS, DIMM, MLPD);
        else
            gemm_bf16<3,0><<<dim3(DIMM/128, ROWS/128),256,GSMEM3>>>(
                (uint32_t*)ah, (uint32_t*)al, (uint32_t*)wh2, (uint32_t*)wl2,
                nullptr, 1.0f, b2 + l*DIMM, h, h, ROWS, DIMM, MLPD);
    }
}